// round 2
// baseline (speedup 1.0000x reference)
#include <cuda_runtime.h>
#include <math.h>

#define BB 2048
#define LL 200
#define DD 128
#define H0N 80
#define H1N 40
#define NT 512

// shared memory layout (floats)
#define OFF_HIST   0                       // [200][129]  = 25800
#define OFF_A0     (OFF_HIST + 200*129)    // [128][80]   = 10240  (aliased as h1S [200][41]=8200 later)
#define OFF_H0     (OFF_A0 + 128*80)       // [200][81]   = 16200
#define OFF_W1     (OFF_H0 + 200*81)       // [80][40]    = 3200
#define OFF_TGT    (OFF_W1 + 3200)         // 128
#define OFF_C0     (OFF_TGT + 128)         // 80
#define OFF_B1     (OFF_C0 + 80)           // 40
#define OFF_W2     (OFF_B1 + 40)           // 40
#define OFF_ATTN   (OFF_W2 + 40)           // 200
#define OFF_RED    (OFF_ATTN + 200)        // 64
#define OFF_PART   (OFF_RED + 64)          // [4][128] = 512
#define SMEM_FLOATS (OFF_PART + 512)

__global__ __launch_bounds__(NT, 1)
void din_kernel(const float* __restrict__ hist,
                const float* __restrict__ tgt,
                const int*   __restrict__ mask,
                const float* __restrict__ W0,
                const float* __restrict__ b0,
                const float* __restrict__ W1,
                const float* __restrict__ b1,
                const float* __restrict__ W2,
                const float* __restrict__ b2,
                float* __restrict__ out)
{
    extern __shared__ float sm[];
    float* histS = sm + OFF_HIST;
    float* A0s   = sm + OFF_A0;
    float* h1S   = sm + OFF_A0;     // alias: A0 dead after layer-0 GEMM
    float* h0S   = sm + OFF_H0;
    float* W1s   = sm + OFF_W1;
    float* tgtS  = sm + OFF_TGT;
    float* c0s   = sm + OFF_C0;
    float* b1s   = sm + OFF_B1;
    float* w2s   = sm + OFF_W2;
    float* attnS = sm + OFF_ATTN;
    float* redS  = sm + OFF_RED;
    float* partS = sm + OFF_PART;

    const int b   = blockIdx.x;
    const int tid = threadIdx.x;

    // ---- target vector ----
    if (tid < DD) tgtS[tid] = tgt[(size_t)b * DD + tid];
    __syncthreads();

    // ---- stage hist[b] into smem (padded rows of 129) ----
    {
        const float4* hb = (const float4*)(hist + (size_t)b * LL * DD);
        for (int idx = tid; idx < LL * DD / 4; idx += NT) {   // 6400 float4
            float4 v = hb[idx];
            int l  = idx >> 5;
            int d4 = (idx & 31) << 2;
            float* r = &histS[l * 129 + d4];
            r[0] = v.x; r[1] = v.y; r[2] = v.z; r[3] = v.w;
        }
    }

    // ---- per-batch effective layer-0 weights:
    //  A0[d][h] = W0_hist + W0_diff + tgt[d]*W0_prod
    for (int idx = tid; idx < DD * H0N; idx += NT) {
        int d = idx / H0N;
        int h = idx - d * H0N;
        A0s[idx] = W0[d * H0N + h]
                 + W0[(2 * DD + d) * H0N + h]
                 + tgtS[d] * W0[(3 * DD + d) * H0N + h];
    }
    //  c0[h] = b0[h] + sum_d tgt[d]*(W0_tgt - W0_diff)
    if (tid < H0N) {
        float s0 = 0.f, s1 = 0.f;
        #pragma unroll 4
        for (int d = 0; d < DD; d += 2) {
            s0 = fmaf(tgtS[d],     W0[(DD + d) * H0N + tid]     - W0[(2 * DD + d) * H0N + tid],     s0);
            s1 = fmaf(tgtS[d + 1], W0[(DD + d + 1) * H0N + tid] - W0[(2 * DD + d + 1) * H0N + tid], s1);
        }
        c0s[tid] = b0[tid] + s0 + s1;
    }
    for (int idx = tid; idx < H0N * H1N; idx += NT) W1s[idx] = W1[idx];
    if (tid < H1N) { b1s[tid] = b1[tid]; w2s[tid] = W2[tid]; }
    __syncthreads();

    // ---- layer 0 GEMM: h0[200][80] = relu(hist @ A0 + c0) ----
    // 500 threads; 4(l) x 8(h) register tile each
    if (tid < 500) {
        const int lt = tid / 10;
        const int ht = tid - lt * 10;
        const int l0 = lt * 4;
        const int h0 = ht * 8;
        float acc[4][8];
        #pragma unroll
        for (int i = 0; i < 4; ++i)
            #pragma unroll
            for (int j = 0; j < 8; ++j) acc[i][j] = 0.f;

        #pragma unroll 2
        for (int d = 0; d < DD; ++d) {
            float a[4];
            #pragma unroll
            for (int i = 0; i < 4; ++i) a[i] = histS[(l0 + i) * 129 + d];
            const float4* wr = (const float4*)&A0s[d * H0N + h0];
            float4 w0v = wr[0];
            float4 w1v = wr[1];
            float w[8] = {w0v.x, w0v.y, w0v.z, w0v.w, w1v.x, w1v.y, w1v.z, w1v.w};
            #pragma unroll
            for (int i = 0; i < 4; ++i)
                #pragma unroll
                for (int j = 0; j < 8; ++j)
                    acc[i][j] = fmaf(a[i], w[j], acc[i][j]);
        }
        #pragma unroll
        for (int i = 0; i < 4; ++i)
            #pragma unroll
            for (int j = 0; j < 8; ++j) {
                float v = acc[i][j] + c0s[h0 + j];
                h0S[(l0 + i) * 81 + h0 + j] = v > 0.f ? v : 0.f;
            }
    }
    __syncthreads();

    // ---- layer 1 GEMM: h1[200][40] = relu(h0 @ W1 + b1) ----
    // 500 threads; 4(l) x 4(j) register tile each; h1 aliased over A0
    if (tid < 500) {
        const int lt = tid / 10;
        const int jt = tid - lt * 10;
        const int l0 = lt * 4;
        const int j0 = jt * 4;
        float acc[4][4];
        #pragma unroll
        for (int i = 0; i < 4; ++i)
            #pragma unroll
            for (int j = 0; j < 4; ++j) acc[i][j] = 0.f;

        #pragma unroll 4
        for (int k = 0; k < H0N; ++k) {
            float a[4];
            #pragma unroll
            for (int i = 0; i < 4; ++i) a[i] = h0S[(l0 + i) * 81 + k];
            float4 wv = *(const float4*)&W1s[k * H1N + j0];
            float w[4] = {wv.x, wv.y, wv.z, wv.w};
            #pragma unroll
            for (int i = 0; i < 4; ++i)
                #pragma unroll
                for (int j = 0; j < 4; ++j)
                    acc[i][j] = fmaf(a[i], w[j], acc[i][j]);
        }
        #pragma unroll
        for (int i = 0; i < 4; ++i)
            #pragma unroll
            for (int j = 0; j < 4; ++j) {
                float v = acc[i][j] + b1s[j0 + j];
                h1S[(l0 + i) * 41 + j0 + j] = v > 0.f ? v : 0.f;
            }
    }
    __syncthreads();

    // ---- layer 2 + mask ----
    float logit = -3.402823466e38f;
    if (tid < LL) {
        float s0 = b2[0], s1 = 0.f;
        #pragma unroll
        for (int j = 0; j < H1N; j += 2) {
            s0 = fmaf(h1S[tid * 41 + j],     w2s[j],     s0);
            s1 = fmaf(h1S[tid * 41 + j + 1], w2s[j + 1], s1);
        }
        float score = s0 + s1;
        float m = (float)mask[(size_t)b * LL + tid];
        logit = score + (1.0f - m) * (-1e9f);
    }

    // ---- masked softmax over L (16 warps) ----
    {
        float v = logit;
        #pragma unroll
        for (int o = 16; o; o >>= 1) v = fmaxf(v, __shfl_xor_sync(0xffffffffu, v, o));
        if ((tid & 31) == 0) redS[tid >> 5] = v;
    }
    __syncthreads();
    if (tid < 32) {
        float m = (tid < 16) ? redS[tid] : -3.402823466e38f;
        #pragma unroll
        for (int o = 8; o; o >>= 1) m = fmaxf(m, __shfl_xor_sync(0xffffffffu, m, o));
        if (tid == 0) redS[32] = m;
    }
    __syncthreads();
    const float M = redS[32];
    float e = (tid < LL) ? expf(logit - M) : 0.f;
    {
        float s = e;
        #pragma unroll
        for (int o = 16; o; o >>= 1) s += __shfl_xor_sync(0xffffffffu, s, o);
        if ((tid & 31) == 0) redS[tid >> 5] = s;
    }
    __syncthreads();
    if (tid < 32) {
        float s = (tid < 16) ? redS[tid] : 0.f;
        #pragma unroll
        for (int o = 8; o; o >>= 1) s += __shfl_xor_sync(0xffffffffu, s, o);
        if (tid == 0) redS[33] = s;
    }
    __syncthreads();
    const float S = redS[33];
    if (tid < LL) {
        float a = e / S;
        attnS[tid] = a;
        out[(size_t)BB * DD + (size_t)b * LL + tid] = a;
    }
    __syncthreads();

    // ---- user_interest[b][d] = sum_l attn[l] * hist[b][l][d] ----
    // 512 threads: 4 l-chunks of 50 x 128 d, then reduce
    {
        const int d = tid & 127;
        const int g = tid >> 7;          // 0..3
        const int lb = g * 50;
        float s = 0.f;
        #pragma unroll 2
        for (int l = lb; l < lb + 50; ++l)
            s = fmaf(attnS[l], histS[l * 129 + d], s);
        partS[g * 128 + d] = s;
    }
    __syncthreads();
    if (tid < DD) {
        out[(size_t)b * DD + tid] =
            partS[tid] + partS[128 + tid] + partS[256 + tid] + partS[384 + tid];
    }
}

extern "C" void kernel_launch(void* const* d_in, const int* in_sizes, int n_in,
                              void* d_out, int out_size)
{
    const float* hist = (const float*)d_in[0];
    const float* tgt  = (const float*)d_in[1];
    const int*   mask = (const int*)  d_in[2];
    const float* W0   = (const float*)d_in[3];
    const float* b0   = (const float*)d_in[4];
    const float* W1   = (const float*)d_in[5];
    const float* b1   = (const float*)d_in[6];
    const float* W2   = (const float*)d_in[7];
    const float* b2   = (const float*)d_in[8];
    float* out = (float*)d_out;

    static int smem_set = 0;
    const int smem_bytes = SMEM_FLOATS * (int)sizeof(float);
    if (!smem_set) {
        cudaFuncSetAttribute(din_kernel,
                             cudaFuncAttributeMaxDynamicSharedMemorySize,
                             smem_bytes);
        smem_set = 1;
    }
    din_kernel<<<BB, NT, smem_bytes>>>(hist, tgt, mask, W0, b0, W1, b1, W2, b2, out);
}

// round 4
// speedup vs baseline: 1.5521x; 1.5521x over previous
#include <cuda_runtime.h>
#include <cuda_bf16.h>
#include <cstdint>
#include <math.h>

#define BB 2048
#define LL 200
#define DD 128
#define H0N 80
#define H1N 40
#define NT 256

// word strides (chosen for conflict-free ldmatrix: bank = 4r+c / 12r+c distinct)
#define S_HIST 68
#define S_H0   44
#define S_W1   44

// ---- smem byte offsets ----
#define HIST_HI 0
#define HIST_LO 56576            // 208*68*4
#define H0_HI   113152
#define H0_LO   149760           // +208*44*4
#define A0T_HI  113152           // alias over h0 region (dead after GEMM0)
#define A0T_LO  134912           // +80*68*4
#define W1T_HI  186368
#define W1T_LO  193408           // +40*44*4
#define MISC    200448
#define OFF_TGT  (MISC + 0)      // 128 f
#define OFF_C0   (MISC + 512)    // 80 f
#define OFF_B1   (MISC + 1024)   // 40 f
#define OFF_W2   (MISC + 1280)   // 40 f
#define OFF_SC   (MISC + 1536)   // 208 f
#define OFF_ATTN (MISC + 2560)   // 200 f
#define OFF_RED  (MISC + 3584)   // 32 f
#define OFF_PART (MISC + 3712)   // 256 f
#define SMEM_BYTES (MISC + 4736) // 205,184 B

#define LDSM4(r0, r1, r2, r3, addr) asm volatile( \
    "ldmatrix.sync.aligned.m8n8.x4.shared.b16 {%0,%1,%2,%3}, [%4];" \
    : "=r"(r0), "=r"(r1), "=r"(r2), "=r"(r3) : "r"(addr))

#define MMA16816(c, a, bfr) asm volatile( \
    "mma.sync.aligned.m16n8k16.row.col.f32.bf16.bf16.f32 " \
    "{%0,%1,%2,%3}, {%4,%5,%6,%7}, {%8,%9}, {%0,%1,%2,%3};" \
    : "+f"((c)[0]), "+f"((c)[1]), "+f"((c)[2]), "+f"((c)[3]) \
    : "r"((a)[0]), "r"((a)[1]), "r"((a)[2]), "r"((a)[3]), \
      "r"((bfr)[0]), "r"((bfr)[1]))

__device__ __forceinline__ uint32_t smem_u32(const void* p) {
    uint32_t a;
    asm("{ .reg .u64 t; cvta.to.shared.u64 t, %1; cvt.u32.u64 %0, t; }" : "=r"(a) : "l"(p));
    return a;
}

// split fp32 pair -> packed bf16x2 hi word + lo word
__device__ __forceinline__ void split2(float a, float b, uint32_t& hiw, uint32_t& low) {
    __nv_bfloat16 ah = __float2bfloat16(a);
    __nv_bfloat16 bh = __float2bfloat16(b);
    __nv_bfloat16 al = __float2bfloat16(a - __bfloat162float(ah));
    __nv_bfloat16 bl = __float2bfloat16(b - __bfloat162float(bh));
    hiw = (uint32_t)__bfloat16_as_ushort(ah) | ((uint32_t)__bfloat16_as_ushort(bh) << 16);
    low = (uint32_t)__bfloat16_as_ushort(al) | ((uint32_t)__bfloat16_as_ushort(bl) << 16);
}

__global__ __launch_bounds__(NT, 1)
void din_kernel(const float* __restrict__ hist,
                const float* __restrict__ tgt,
                const int*   __restrict__ mask,
                const float* __restrict__ W0,
                const float* __restrict__ b0,
                const float* __restrict__ W1,
                const float* __restrict__ b1,
                const float* __restrict__ W2,
                const float* __restrict__ b2,
                float* __restrict__ out)
{
    extern __shared__ char smc[];
    float* tgtS   = (float*)(smc + OFF_TGT);
    float* c0s    = (float*)(smc + OFF_C0);
    float* b1s    = (float*)(smc + OFF_B1);
    float* w2s    = (float*)(smc + OFF_W2);
    float* scoreS = (float*)(smc + OFF_SC);
    float* attnS  = (float*)(smc + OFF_ATTN);
    float* redS   = (float*)(smc + OFF_RED);
    float* partS  = (float*)(smc + OFF_PART);

    const int b    = blockIdx.x;
    const int tid  = threadIdx.x;
    const int wid  = tid >> 5;
    const int lane = tid & 31;
    const uint32_t smem_base = smem_u32(smc);

    if (tid < DD) tgtS[tid] = tgt[(size_t)b * DD + tid];
    __syncthreads();

    // ---- stage hist -> bf16 hi/lo [208][S_HIST words], rows 200..207 zeroed ----
    {
        const float4* hb = (const float4*)(hist + (size_t)b * LL * DD);
        for (int idx = tid; idx < LL * 32; idx += NT) {
            int r  = idx >> 5;
            int c4 = (idx & 31) << 2;
            float4 v = hb[idx];
            uint32_t hw0, lw0, hw1, lw1;
            split2(v.x, v.y, hw0, lw0);
            split2(v.z, v.w, hw1, lw1);
            uint32_t wo = (uint32_t)(r * S_HIST + (c4 >> 1)) * 4u;
            *(uint32_t*)(smc + HIST_HI + wo)     = hw0;
            *(uint32_t*)(smc + HIST_LO + wo)     = lw0;
            *(uint32_t*)(smc + HIST_HI + wo + 4) = hw1;
            *(uint32_t*)(smc + HIST_LO + wo + 4) = lw1;
        }
        for (int idx = tid; idx < 8 * S_HIST; idx += NT) {
            uint32_t wo = (uint32_t)((200 + idx / S_HIST) * S_HIST + (idx % S_HIST)) * 4u;
            *(uint32_t*)(smc + HIST_HI + wo) = 0u;
            *(uint32_t*)(smc + HIST_LO + wo) = 0u;
        }
    }

    // ---- A0t[n][k] = W0_hist + W0_diff + tgt[k]*W0_prod  (bf16 hi/lo, [80][64w]) ----
    for (int w = tid; w < H0N * 64; w += NT) {
        int n  = w % H0N;
        int kp = w / H0N;
        int d  = kp * 2;
        float v0 = W0[d * H0N + n] + W0[(2 * DD + d) * H0N + n] + tgtS[d] * W0[(3 * DD + d) * H0N + n];
        float v1 = W0[(d + 1) * H0N + n] + W0[(2 * DD + d + 1) * H0N + n] + tgtS[d + 1] * W0[(3 * DD + d + 1) * H0N + n];
        uint32_t hw, lw;
        split2(v0, v1, hw, lw);
        uint32_t wo = (uint32_t)(n * S_HIST + kp) * 4u;
        *(uint32_t*)(smc + A0T_HI + wo) = hw;
        *(uint32_t*)(smc + A0T_LO + wo) = lw;
    }
    // ---- c0[h] = b0[h] + sum_d tgt[d]*(W0_tgt - W0_diff) ----
    if (tid < H0N) {
        float s0 = 0.f, s1 = 0.f;
        #pragma unroll 4
        for (int d = 0; d < DD; d += 2) {
            s0 = fmaf(tgtS[d],     W0[(DD + d) * H0N + tid]     - W0[(2 * DD + d) * H0N + tid],     s0);
            s1 = fmaf(tgtS[d + 1], W0[(DD + d + 1) * H0N + tid] - W0[(2 * DD + d + 1) * H0N + tid], s1);
        }
        c0s[tid] = b0[tid] + s0 + s1;
    }
    // ---- W1t[n][k] (bf16 hi/lo, [40][40w]) ----
    for (int w = tid; w < H1N * 40; w += NT) {
        int n  = w % H1N;
        int kp = w / H1N;
        int k  = kp * 2;
        uint32_t hw, lw;
        split2(W1[k * H1N + n], W1[(k + 1) * H1N + n], hw, lw);
        uint32_t wo = (uint32_t)(n * S_W1 + kp) * 4u;
        *(uint32_t*)(smc + W1T_HI + wo) = hw;
        *(uint32_t*)(smc + W1T_LO + wo) = lw;
    }
    if (tid < H1N) { b1s[tid] = b1[tid]; w2s[tid] = W2[tid]; }
    __syncthreads();

    // ldmatrix lane geometry
    const int rA = lane & 15;                          // row within 16-row tile
    const int kA = (lane & 16) ? 4 : 0;                // k-word offset (A)
    const int rB = (lane & 7) | ((lane & 16) >> 1);    // row within B n-pair
    const int kB = (lane & 8) ? 4 : 0;

    const int mb0 = wid * 16;
    const int mb1 = (wid + 8) * 16;
    const int ntl = (wid < 5) ? 2 : 1;

    // =========== GEMM0: h0[200][80] = relu(hist @ A0t^T + c0), split-bf16 x3 ===========
    {
        float C0[2][10][4];
        #pragma unroll
        for (int t = 0; t < 2; ++t)
            #pragma unroll
            for (int n = 0; n < 10; ++n)
                #pragma unroll
                for (int j = 0; j < 4; ++j) C0[t][n][j] = 0.f;

        #pragma unroll 1
        for (int term = 0; term < 3; ++term) {
            const uint32_t abase = smem_base + ((term == 2) ? HIST_LO : HIST_HI);
            const uint32_t bbase = smem_base + ((term == 1) ? A0T_LO : A0T_HI);
            const uint32_t aAdr0 = abase + (uint32_t)((mb0 + rA) * S_HIST + kA) * 4u;
            const uint32_t aAdr1 = abase + (uint32_t)((mb1 + rA) * S_HIST + kA) * 4u;
            const uint32_t bAdr  = bbase + (uint32_t)(rB * S_HIST + kB) * 4u;
            #pragma unroll 1
            for (int ks = 0; ks < 8; ++ks) {
                uint32_t bf[10][2];
                #pragma unroll
                for (int p = 0; p < 5; ++p)
                    LDSM4(bf[2 * p][0], bf[2 * p][1], bf[2 * p + 1][0], bf[2 * p + 1][1],
                          bAdr + (uint32_t)(p * 16 * S_HIST + ks * 8) * 4u);
                uint32_t a[4];
                LDSM4(a[0], a[1], a[2], a[3], aAdr0 + (uint32_t)(ks * 8) * 4u);
                #pragma unroll
                for (int n = 0; n < 10; ++n) MMA16816(C0[0][n], a, bf[n]);
                if (ntl == 2) {
                    LDSM4(a[0], a[1], a[2], a[3], aAdr1 + (uint32_t)(ks * 8) * 4u);
                    #pragma unroll
                    for (int n = 0; n < 10; ++n) MMA16816(C0[1][n], a, bf[n]);
                }
            }
        }
        __syncthreads();   // all A0t reads done before h0 overwrites the region

        #pragma unroll 1
        for (int t = 0; t < ntl; ++t) {
            const int mb = (t == 0) ? mb0 : mb1;
            const int row = mb + (lane >> 2);
            #pragma unroll
            for (int nt = 0; nt < 10; ++nt) {
                const int col = nt * 8 + (lane & 3) * 2;
                uint32_t hw, lw;
                float v0 = fmaxf(C0[t][nt][0] + c0s[col],     0.f);
                float v1 = fmaxf(C0[t][nt][1] + c0s[col + 1], 0.f);
                split2(v0, v1, hw, lw);
                uint32_t wo = (uint32_t)(row * S_H0 + nt * 4 + (lane & 3)) * 4u;
                *(uint32_t*)(smc + H0_HI + wo) = hw;
                *(uint32_t*)(smc + H0_LO + wo) = lw;
                v0 = fmaxf(C0[t][nt][2] + c0s[col],     0.f);
                v1 = fmaxf(C0[t][nt][3] + c0s[col + 1], 0.f);
                split2(v0, v1, hw, lw);
                wo = (uint32_t)((row + 8) * S_H0 + nt * 4 + (lane & 3)) * 4u;
                *(uint32_t*)(smc + H0_HI + wo) = hw;
                *(uint32_t*)(smc + H0_LO + wo) = lw;
            }
        }
    }
    __syncthreads();

    // =========== GEMM1 + layer2: scores[l], split-bf16 x3, K=80 ===========
    {
        float C1[2][5][4];
        #pragma unroll
        for (int t = 0; t < 2; ++t)
            #pragma unroll
            for (int n = 0; n < 5; ++n)
                #pragma unroll
                for (int j = 0; j < 4; ++j) C1[t][n][j] = 0.f;

        #pragma unroll 1
        for (int term = 0; term < 3; ++term) {
            const uint32_t abase = smem_base + ((term == 2) ? H0_LO : H0_HI);
            const uint32_t bbase = smem_base + ((term == 1) ? W1T_LO : W1T_HI);
            const uint32_t aAdr0 = abase + (uint32_t)((mb0 + rA) * S_H0 + kA) * 4u;
            const uint32_t aAdr1 = abase + (uint32_t)((mb1 + rA) * S_H0 + kA) * 4u;
            const uint32_t bAdr  = bbase + (uint32_t)(rB * S_W1 + kB) * 4u;
            #pragma unroll 1
            for (int ks = 0; ks < 5; ++ks) {
                uint32_t bf[6][2];
                #pragma unroll
                for (int p = 0; p < 3; ++p)    // tile pair (4,5): 5 is garbage, unused
                    LDSM4(bf[2 * p][0], bf[2 * p][1], bf[2 * p + 1][0], bf[2 * p + 1][1],
                          bAdr + (uint32_t)(p * 16 * S_W1 + ks * 8) * 4u);
                uint32_t a[4];
                LDSM4(a[0], a[1], a[2], a[3], aAdr0 + (uint32_t)(ks * 8) * 4u);
                #pragma unroll
                for (int n = 0; n < 5; ++n) MMA16816(C1[0][n], a, bf[n]);
                if (ntl == 2) {
                    LDSM4(a[0], a[1], a[2], a[3], aAdr1 + (uint32_t)(ks * 8) * 4u);
                    #pragma unroll
                    for (int n = 0; n < 5; ++n) MMA16816(C1[1][n], a, bf[n]);
                }
            }
        }

        const float b2v = b2[0];
        #pragma unroll 1
        for (int t = 0; t < ntl; ++t) {
            float p0 = 0.f, p1 = 0.f;
            #pragma unroll
            for (int nt = 0; nt < 5; ++nt) {
                const int col = nt * 8 + (lane & 3) * 2;
                p0 += fmaxf(C1[t][nt][0] + b1s[col],     0.f) * w2s[col]
                    + fmaxf(C1[t][nt][1] + b1s[col + 1], 0.f) * w2s[col + 1];
                p1 += fmaxf(C1[t][nt][2] + b1s[col],     0.f) * w2s[col]
                    + fmaxf(C1[t][nt][3] + b1s[col + 1], 0.f) * w2s[col + 1];
            }
            p0 += __shfl_xor_sync(0xffffffffu, p0, 1);
            p0 += __shfl_xor_sync(0xffffffffu, p0, 2);
            p1 += __shfl_xor_sync(0xffffffffu, p1, 1);
            p1 += __shfl_xor_sync(0xffffffffu, p1, 2);
            if ((lane & 3) == 0) {
                const int mb = (t == 0) ? mb0 : mb1;
                const int row = mb + (lane >> 2);
                scoreS[row]     = p0 + b2v;
                scoreS[row + 8] = p1 + b2v;
            }
        }
    }
    __syncthreads();

    // ---- masked softmax over L ----
    float logit = -3.402823466e38f;
    if (tid < LL) {
        float m = (float)mask[(size_t)b * LL + tid];
        logit = scoreS[tid] + (1.0f - m) * (-1e9f);
    }
    {
        float v = logit;
        #pragma unroll
        for (int o = 16; o; o >>= 1) v = fmaxf(v, __shfl_xor_sync(0xffffffffu, v, o));
        if (lane == 0) redS[wid] = v;
    }
    __syncthreads();
    if (tid < 32) {
        float m = (tid < 8) ? redS[tid] : -3.402823466e38f;
        #pragma unroll
        for (int o = 4; o; o >>= 1) m = fmaxf(m, __shfl_xor_sync(0xffffffffu, m, o));
        if (tid == 0) redS[16] = m;
    }
    __syncthreads();
    const float M = redS[16];
    float e = (tid < LL) ? expf(logit - M) : 0.f;
    {
        float s = e;
        #pragma unroll
        for (int o = 16; o; o >>= 1) s += __shfl_xor_sync(0xffffffffu, s, o);
        if (lane == 0) redS[wid] = s;
    }
    __syncthreads();
    if (tid < 32) {
        float s = (tid < 8) ? redS[tid] : 0.f;
        #pragma unroll
        for (int o = 4; o; o >>= 1) s += __shfl_xor_sync(0xffffffffu, s, o);
        if (tid == 0) redS[17] = s;
    }
    __syncthreads();
    const float S = redS[17];
    if (tid < LL) {
        float a = e / S;
        attnS[tid] = a;
        out[(size_t)BB * DD + (size_t)b * LL + tid] = a;
    }
    __syncthreads();

    // ---- user_interest[b][d] = sum_l attn[l]*hist[l][d]  (smem hi+lo reconstruct) ----
    {
        const int d = tid & 127;
        const int g = tid >> 7;
        const __nv_bfloat16* hh = (const __nv_bfloat16*)(smc + HIST_HI);
        const __nv_bfloat16* hl = (const __nv_bfloat16*)(smc + HIST_LO);
        float s = 0.f;
        #pragma unroll 2
        for (int l = g * 100; l < g * 100 + 100; ++l) {
            float hv = __bfloat162float(hh[l * (2 * S_HIST) + d]) +
                       __bfloat162float(hl[l * (2 * S_HIST) + d]);
            s = fmaf(attnS[l], hv, s);
        }
        partS[g * 128 + d] = s;
    }
    __syncthreads();
    if (tid < DD)
        out[(size_t)b * DD + tid] = partS[tid] + partS[128 + tid];
}

extern "C" void kernel_launch(void* const* d_in, const int* in_sizes, int n_in,
                              void* d_out, int out_size)
{
    const float* hist = (const float*)d_in[0];
    const float* tgt  = (const float*)d_in[1];
    const int*   mask = (const int*)  d_in[2];
    const float* W0   = (const float*)d_in[3];
    const float* b0   = (const float*)d_in[4];
    const float* W1   = (const float*)d_in[5];
    const float* b1   = (const float*)d_in[6];
    const float* W2   = (const float*)d_in[7];
    const float* b2   = (const float*)d_in[8];
    float* out = (float*)d_out;

    static int smem_set = 0;
    if (!smem_set) {
        cudaFuncSetAttribute(din_kernel,
                             cudaFuncAttributeMaxDynamicSharedMemorySize,
                             SMEM_BYTES);
        smem_set = 1;
    }
    din_kernel<<<BB, NT, SMEM_BYTES>>>(hist, tgt, mask, W0, b0, W1, b1, W2, b2, out);
}

// round 5
// speedup vs baseline: 1.6856x; 1.0860x over previous
#include <cuda_runtime.h>
#include <cuda_bf16.h>
#include <cstdint>
#include <math.h>

#define BB 2048
#define LL 200
#define DD 128
#define H0N 80
#define H1N 40
#define NT 416            // 13 warps: one 16-row m-tile each

// word strides (conflict-free ldmatrix: bank = 4r mod 32 / 12r mod 32 distinct)
#define S_HIST 68
#define S_H0   44
#define S_W1   44

// ---- smem byte offsets ----
#define HIST_HI 0
#define HIST_LO 56576            // 208*68*4
#define H0_HI   113152
#define H0_LO   149760           // +208*44*4
#define A0T_HI  113152           // alias over h0 region (dead after GEMM0 mainloop)
#define A0T_LO  134912           // +80*68*4
#define W1T_HI  186368
#define W1T_LO  193408           // +40*44*4
#define MISC    200448
#define OFF_TGT  (MISC + 0)      // 128 f
#define OFF_C0   (MISC + 512)    // 80 f
#define OFF_B1   (MISC + 1024)   // 40 f
#define OFF_W2   (MISC + 1280)   // 40 f
#define OFF_SC   (MISC + 1536)   // 208 f
#define OFF_ATTN (MISC + 2560)   // 200 f
#define OFF_RED  (MISC + 3584)   // 32 f
#define OFF_PART (MISC + 3712)   // 256 f
#define SMEM_BYTES (MISC + 4736) // 205,184 B

#define LDSM4(r0, r1, r2, r3, addr) asm volatile( \
    "ldmatrix.sync.aligned.m8n8.x4.shared.b16 {%0,%1,%2,%3}, [%4];" \
    : "=r"(r0), "=r"(r1), "=r"(r2), "=r"(r3) : "r"(addr))

#define MMA16816(c, a, bfr) asm volatile( \
    "mma.sync.aligned.m16n8k16.row.col.f32.bf16.bf16.f32 " \
    "{%0,%1,%2,%3}, {%4,%5,%6,%7}, {%8,%9}, {%0,%1,%2,%3};" \
    : "+f"((c)[0]), "+f"((c)[1]), "+f"((c)[2]), "+f"((c)[3]) \
    : "r"((a)[0]), "r"((a)[1]), "r"((a)[2]), "r"((a)[3]), \
      "r"((bfr)[0]), "r"((bfr)[1]))

__device__ __forceinline__ uint32_t smem_u32(const void* p) {
    uint32_t a;
    asm("{ .reg .u64 t; cvta.to.shared.u64 t, %1; cvt.u32.u64 %0, t; }" : "=r"(a) : "l"(p));
    return a;
}

// split fp32 pair -> packed bf16x2 hi word + lo word
__device__ __forceinline__ void split2(float a, float b, uint32_t& hiw, uint32_t& low) {
    __nv_bfloat16 ah = __float2bfloat16(a);
    __nv_bfloat16 bh = __float2bfloat16(b);
    __nv_bfloat16 al = __float2bfloat16(a - __bfloat162float(ah));
    __nv_bfloat16 bl = __float2bfloat16(b - __bfloat162float(bh));
    hiw = (uint32_t)__bfloat16_as_ushort(ah) | ((uint32_t)__bfloat16_as_ushort(bh) << 16);
    low = (uint32_t)__bfloat16_as_ushort(al) | ((uint32_t)__bfloat16_as_ushort(bl) << 16);
}

__global__ __launch_bounds__(NT, 1)
void din_kernel(const float* __restrict__ hist,
                const float* __restrict__ tgt,
                const int*   __restrict__ mask,
                const float* __restrict__ W0,
                const float* __restrict__ b0,
                const float* __restrict__ W1,
                const float* __restrict__ b1,
                const float* __restrict__ W2,
                const float* __restrict__ b2,
                float* __restrict__ out)
{
    extern __shared__ char smc[];
    float* tgtS   = (float*)(smc + OFF_TGT);
    float* c0s    = (float*)(smc + OFF_C0);
    float* b1s    = (float*)(smc + OFF_B1);
    float* w2s    = (float*)(smc + OFF_W2);
    float* scoreS = (float*)(smc + OFF_SC);
    float* attnS  = (float*)(smc + OFF_ATTN);
    float* redS   = (float*)(smc + OFF_RED);
    float* partS  = (float*)(smc + OFF_PART);

    const int b    = blockIdx.x;
    const int tid  = threadIdx.x;
    const int wid  = tid >> 5;
    const int lane = tid & 31;
    const uint32_t smem_base = smem_u32(smc);

    if (tid < DD) tgtS[tid] = tgt[(size_t)b * DD + tid];
    __syncthreads();

    // ---- stage hist -> bf16 hi/lo [208][S_HIST words], rows 200..207 zeroed ----
    {
        const float4* hb = (const float4*)(hist + (size_t)b * LL * DD);
        for (int idx = tid; idx < LL * 32; idx += NT) {
            int r  = idx >> 5;
            int c4 = (idx & 31) << 2;
            float4 v = hb[idx];
            uint32_t hw0, lw0, hw1, lw1;
            split2(v.x, v.y, hw0, lw0);
            split2(v.z, v.w, hw1, lw1);
            uint32_t wo = (uint32_t)(r * S_HIST + (c4 >> 1)) * 4u;
            *(uint32_t*)(smc + HIST_HI + wo)     = hw0;
            *(uint32_t*)(smc + HIST_LO + wo)     = lw0;
            *(uint32_t*)(smc + HIST_HI + wo + 4) = hw1;
            *(uint32_t*)(smc + HIST_LO + wo + 4) = lw1;
        }
        for (int idx = tid; idx < 8 * S_HIST; idx += NT) {
            uint32_t wo = (uint32_t)((200 + idx / S_HIST) * S_HIST + (idx % S_HIST)) * 4u;
            *(uint32_t*)(smc + HIST_HI + wo) = 0u;
            *(uint32_t*)(smc + HIST_LO + wo) = 0u;
        }
    }

    // ---- A0t[n][k] = W0_hist + W0_diff + tgt[k]*W0_prod  (bf16 hi/lo) ----
    for (int w = tid; w < H0N * 64; w += NT) {
        int n  = w % H0N;
        int kp = w / H0N;
        int d  = kp * 2;
        float v0 = W0[d * H0N + n] + W0[(2 * DD + d) * H0N + n] + tgtS[d] * W0[(3 * DD + d) * H0N + n];
        float v1 = W0[(d + 1) * H0N + n] + W0[(2 * DD + d + 1) * H0N + n] + tgtS[d + 1] * W0[(3 * DD + d + 1) * H0N + n];
        uint32_t hw, lw;
        split2(v0, v1, hw, lw);
        uint32_t wo = (uint32_t)(n * S_HIST + kp) * 4u;
        *(uint32_t*)(smc + A0T_HI + wo) = hw;
        *(uint32_t*)(smc + A0T_LO + wo) = lw;
    }
    // ---- c0[h] = b0[h] + sum_d tgt[d]*(W0_tgt - W0_diff) ----
    if (tid < H0N) {
        float s0 = 0.f, s1 = 0.f;
        #pragma unroll 4
        for (int d = 0; d < DD; d += 2) {
            s0 = fmaf(tgtS[d],     W0[(DD + d) * H0N + tid]     - W0[(2 * DD + d) * H0N + tid],     s0);
            s1 = fmaf(tgtS[d + 1], W0[(DD + d + 1) * H0N + tid] - W0[(2 * DD + d + 1) * H0N + tid], s1);
        }
        c0s[tid] = b0[tid] + s0 + s1;
    }
    // ---- W1t[n][k] (bf16 hi/lo) ----
    for (int w = tid; w < H1N * 40; w += NT) {
        int n  = w % H1N;
        int kp = w / H1N;
        int k  = kp * 2;
        uint32_t hw, lw;
        split2(W1[k * H1N + n], W1[(k + 1) * H1N + n], hw, lw);
        uint32_t wo = (uint32_t)(n * S_W1 + kp) * 4u;
        *(uint32_t*)(smc + W1T_HI + wo) = hw;
        *(uint32_t*)(smc + W1T_LO + wo) = lw;
    }
    if (tid < H1N) { b1s[tid] = b1[tid]; w2s[tid] = W2[tid]; }
    __syncthreads();

    // ldmatrix lane geometry
    const int rA = lane & 15;
    const int kA = (lane & 16) ? 4 : 0;
    const int rB = (lane & 7) | ((lane & 16) >> 1);
    const int kB = (lane & 8) ? 4 : 0;
    const int mb = wid * 16;            // one 16-row m-tile per warp (13 warps)

    // =========== GEMM0: h0[208][80] = relu(hist @ A0t^T + c0), split-bf16 x3 ===========
    {
        float C0[10][4];
        #pragma unroll
        for (int n = 0; n < 10; ++n)
            #pragma unroll
            for (int j = 0; j < 4; ++j) C0[n][j] = 0.f;

        #pragma unroll 1
        for (int term = 0; term < 3; ++term) {
            const uint32_t abase = smem_base + ((term == 2) ? HIST_LO : HIST_HI);
            const uint32_t bbase = smem_base + ((term == 1) ? A0T_LO : A0T_HI);
            const uint32_t aAdr  = abase + (uint32_t)((mb + rA) * S_HIST + kA) * 4u;
            const uint32_t bAdr  = bbase + (uint32_t)(rB * S_HIST + kB) * 4u;
            #pragma unroll 1
            for (int ks = 0; ks < 8; ++ks) {
                uint32_t bf[10][2];
                #pragma unroll
                for (int p = 0; p < 5; ++p)
                    LDSM4(bf[2 * p][0], bf[2 * p][1], bf[2 * p + 1][0], bf[2 * p + 1][1],
                          bAdr + (uint32_t)(p * 16 * S_HIST + ks * 8) * 4u);
                uint32_t a[4];
                LDSM4(a[0], a[1], a[2], a[3], aAdr + (uint32_t)(ks * 8) * 4u);
                #pragma unroll
                for (int n = 0; n < 10; ++n) MMA16816(C0[n], a, bf[n]);
            }
        }
        __syncthreads();   // all A0t reads done before h0 overwrites the region

        const int row = mb + (lane >> 2);
        #pragma unroll
        for (int nt = 0; nt < 10; ++nt) {
            const int col = nt * 8 + (lane & 3) * 2;
            uint32_t hw, lw;
            float v0 = fmaxf(C0[nt][0] + c0s[col],     0.f);
            float v1 = fmaxf(C0[nt][1] + c0s[col + 1], 0.f);
            split2(v0, v1, hw, lw);
            uint32_t wo = (uint32_t)(row * S_H0 + nt * 4 + (lane & 3)) * 4u;
            *(uint32_t*)(smc + H0_HI + wo) = hw;
            *(uint32_t*)(smc + H0_LO + wo) = lw;
            v0 = fmaxf(C0[nt][2] + c0s[col],     0.f);
            v1 = fmaxf(C0[nt][3] + c0s[col + 1], 0.f);
            split2(v0, v1, hw, lw);
            wo = (uint32_t)((row + 8) * S_H0 + nt * 4 + (lane & 3)) * 4u;
            *(uint32_t*)(smc + H0_HI + wo) = hw;
            *(uint32_t*)(smc + H0_LO + wo) = lw;
        }
    }
    __syncthreads();

    // =========== GEMM1 + layer2: scores[l], split-bf16 x3, K=80 ===========
    {
        float C1[5][4];
        #pragma unroll
        for (int n = 0; n < 5; ++n)
            #pragma unroll
            for (int j = 0; j < 4; ++j) C1[n][j] = 0.f;

        #pragma unroll 1
        for (int term = 0; term < 3; ++term) {
            const uint32_t abase = smem_base + ((term == 2) ? H0_LO : H0_HI);
            const uint32_t bbase = smem_base + ((term == 1) ? W1T_LO : W1T_HI);
            const uint32_t aAdr  = abase + (uint32_t)((mb + rA) * S_H0 + kA) * 4u;
            const uint32_t bAdr  = bbase + (uint32_t)(rB * S_W1 + kB) * 4u;
            #pragma unroll 1
            for (int ks = 0; ks < 5; ++ks) {
                uint32_t bf[6][2];
                #pragma unroll
                for (int p = 0; p < 3; ++p)    // tile 5 is padding, unused
                    LDSM4(bf[2 * p][0], bf[2 * p][1], bf[2 * p + 1][0], bf[2 * p + 1][1],
                          bAdr + (uint32_t)(p * 16 * S_W1 + ks * 8) * 4u);
                uint32_t a[4];
                LDSM4(a[0], a[1], a[2], a[3], aAdr + (uint32_t)(ks * 8) * 4u);
                #pragma unroll
                for (int n = 0; n < 5; ++n) MMA16816(C1[n], a, bf[n]);
            }
        }

        const float b2v = b2[0];
        float p0 = 0.f, p1 = 0.f;
        #pragma unroll
        for (int nt = 0; nt < 5; ++nt) {
            const int col = nt * 8 + (lane & 3) * 2;
            p0 += fmaxf(C1[nt][0] + b1s[col],     0.f) * w2s[col]
                + fmaxf(C1[nt][1] + b1s[col + 1], 0.f) * w2s[col + 1];
            p1 += fmaxf(C1[nt][2] + b1s[col],     0.f) * w2s[col]
                + fmaxf(C1[nt][3] + b1s[col + 1], 0.f) * w2s[col + 1];
        }
        p0 += __shfl_xor_sync(0xffffffffu, p0, 1);
        p0 += __shfl_xor_sync(0xffffffffu, p0, 2);
        p1 += __shfl_xor_sync(0xffffffffu, p1, 1);
        p1 += __shfl_xor_sync(0xffffffffu, p1, 2);
        if ((lane & 3) == 0) {
            const int row = mb + (lane >> 2);
            scoreS[row]     = p0 + b2v;
            scoreS[row + 8] = p1 + b2v;
        }
    }
    __syncthreads();

    // ---- masked softmax over L (13 warps) ----
    float logit = -3.402823466e38f;
    if (tid < LL) {
        float m = (float)mask[(size_t)b * LL + tid];
        logit = scoreS[tid] + (1.0f - m) * (-1e9f);
    }
    {
        float v = logit;
        #pragma unroll
        for (int o = 16; o; o >>= 1) v = fmaxf(v, __shfl_xor_sync(0xffffffffu, v, o));
        if (lane == 0) redS[wid] = v;
    }
    __syncthreads();
    if (tid < 32) {
        float m = (tid < 13) ? redS[tid] : -3.402823466e38f;
        #pragma unroll
        for (int o = 8; o; o >>= 1) m = fmaxf(m, __shfl_xor_sync(0xffffffffu, m, o));
        if (tid == 0) redS[16] = m;
    }
    __syncthreads();
    const float M = redS[16];
    float e = (tid < LL) ? expf(logit - M) : 0.f;
    {
        float s = e;
        #pragma unroll
        for (int o = 16; o; o >>= 1) s += __shfl_xor_sync(0xffffffffu, s, o);
        if (lane == 0) redS[wid] = s;
    }
    __syncthreads();
    if (tid < 32) {
        float s = (tid < 13) ? redS[tid] : 0.f;
        #pragma unroll
        for (int o = 8; o; o >>= 1) s += __shfl_xor_sync(0xffffffffu, s, o);
        if (tid == 0) redS[17] = s;
    }
    __syncthreads();
    const float S = redS[17];
    if (tid < LL) {
        float a = e / S;
        attnS[tid] = a;
        out[(size_t)BB * DD + (size_t)b * LL + tid] = a;
    }
    __syncthreads();

    // ---- user_interest[b][d] = sum_l attn[l]*hist[l][d]  (smem hi+lo reconstruct) ----
    if (tid < 256) {
        const int d = tid & 127;
        const int g = tid >> 7;
        const __nv_bfloat16* hh = (const __nv_bfloat16*)(smc + HIST_HI);
        const __nv_bfloat16* hl = (const __nv_bfloat16*)(smc + HIST_LO);
        float s = 0.f;
        #pragma unroll 2
        for (int l = g * 100; l < g * 100 + 100; ++l) {
            float hv = __bfloat162float(hh[l * (2 * S_HIST) + d]) +
                       __bfloat162float(hl[l * (2 * S_HIST) + d]);
            s = fmaf(attnS[l], hv, s);
        }
        partS[g * 128 + d] = s;
    }
    __syncthreads();
    if (tid < DD)
        out[(size_t)b * DD + tid] = partS[tid] + partS[128 + tid];
}

extern "C" void kernel_launch(void* const* d_in, const int* in_sizes, int n_in,
                              void* d_out, int out_size)
{
    const float* hist = (const float*)d_in[0];
    const float* tgt  = (const float*)d_in[1];
    const int*   mask = (const int*)  d_in[2];
    const float* W0   = (const float*)d_in[3];
    const float* b0   = (const float*)d_in[4];
    const float* W1   = (const float*)d_in[5];
    const float* b1   = (const float*)d_in[6];
    const float* W2   = (const float*)d_in[7];
    const float* b2   = (const float*)d_in[8];
    float* out = (float*)d_out;

    static int smem_set = 0;
    if (!smem_set) {
        cudaFuncSetAttribute(din_kernel,
                             cudaFuncAttributeMaxDynamicSharedMemorySize,
                             SMEM_BYTES);
        smem_set = 1;
    }
    din_kernel<<<BB, NT, SMEM_BYTES>>>(hist, tgt, mask, W0, b0, W1, b1, W2, b2, out);
}

// round 6
// speedup vs baseline: 1.8953x; 1.1244x over previous
#include <cuda_runtime.h>
#include <cuda_bf16.h>
#include <cstdint>
#include <math.h>

#define BB 2048
#define LL 200
#define DD 128
#define H0N 80
#define H1N 40
#define NT 224            // 7 warps; 2 CTAs/SM
#define ROWS 112          // L-rows per chunk (2 chunks)

// word strides (conflict-free ldmatrix; identical to R5)
#define S_HIST 68
#define S_H0   44
#define S_W1   44

// ---- smem byte offsets ----
// Region X (chunk-lived): hist hi/lo -> h0 hi/lo + W1T
#define HIST_HI 0
#define HIST_LO (ROWS*S_HIST*4)          // 30464
#define H0_HI   0                         // alias (hist dead after GEMM0 mainloop)
#define H0_LO   (ROWS*S_H0*4)             // 19712
#define W1T_HI  (2*ROWS*S_H0*4)           // 39424
#define W1T_LO  (W1T_HI + H1N*S_W1*4)     // 46464   (ends 53504 < 60928)
// Region Y (batch-lived): A0t
#define A0T_HI  (2*ROWS*S_HIST*4)         // 60928
#define A0T_LO  (A0T_HI + H0N*S_HIST*4)   // 82688   (ends 104448)
#define MISC    104448
#define OFF_TGT  (MISC + 0)       // 128 f
#define OFF_C0   (MISC + 512)     // 80 f
#define OFF_B1   (MISC + 896)     // 40 f
#define OFF_W2   (MISC + 1088)    // 40 f
#define OFF_SC   (MISC + 1280)    // 224 f
#define OFF_ATTN (MISC + 2176)    // 224 f (200 used)
#define OFF_RED  (MISC + 3072)    // 32 f
#define OFF_PART (MISC + 3200)    // 512 f
#define SMEM_BYTES (MISC + 5248)  // 109,696 B -> 2 CTAs/SM

#define LDSM4(r0, r1, r2, r3, addr) asm volatile( \
    "ldmatrix.sync.aligned.m8n8.x4.shared.b16 {%0,%1,%2,%3}, [%4];" \
    : "=r"(r0), "=r"(r1), "=r"(r2), "=r"(r3) : "r"(addr))

#define MMA16816(c, a, bfr) asm volatile( \
    "mma.sync.aligned.m16n8k16.row.col.f32.bf16.bf16.f32 " \
    "{%0,%1,%2,%3}, {%4,%5,%6,%7}, {%8,%9}, {%0,%1,%2,%3};" \
    : "+f"((c)[0]), "+f"((c)[1]), "+f"((c)[2]), "+f"((c)[3]) \
    : "r"((a)[0]), "r"((a)[1]), "r"((a)[2]), "r"((a)[3]), \
      "r"((bfr)[0]), "r"((bfr)[1]))

__device__ __forceinline__ uint32_t smem_u32(const void* p) {
    uint32_t a;
    asm("{ .reg .u64 t; cvta.to.shared.u64 t, %1; cvt.u32.u64 %0, t; }" : "=r"(a) : "l"(p));
    return a;
}

__device__ __forceinline__ void split2(float a, float b, uint32_t& hiw, uint32_t& low) {
    __nv_bfloat16 ah = __float2bfloat16(a);
    __nv_bfloat16 bh = __float2bfloat16(b);
    __nv_bfloat16 al = __float2bfloat16(a - __bfloat162float(ah));
    __nv_bfloat16 bl = __float2bfloat16(b - __bfloat162float(bh));
    hiw = (uint32_t)__bfloat16_as_ushort(ah) | ((uint32_t)__bfloat16_as_ushort(bh) << 16);
    low = (uint32_t)__bfloat16_as_ushort(al) | ((uint32_t)__bfloat16_as_ushort(bl) << 16);
}

// stage one 112-row chunk of hist as bf16 hi/lo (rows past L zeroed)
__device__ __forceinline__ void stage_chunk(char* smc, const float4* hb, int c, int tid) {
    for (int idx = tid; idx < ROWS * 32; idx += NT) {
        int r = idx >> 5;
        int q = idx & 31;
        int gl = c * ROWS + r;
        float4 v = make_float4(0.f, 0.f, 0.f, 0.f);
        if (gl < LL) v = hb[gl * 32 + q];
        uint32_t hw0, lw0, hw1, lw1;
        split2(v.x, v.y, hw0, lw0);
        split2(v.z, v.w, hw1, lw1);
        uint32_t wo = (uint32_t)(r * S_HIST + q * 2) * 4u;
        *(uint32_t*)(smc + HIST_HI + wo)     = hw0;
        *(uint32_t*)(smc + HIST_LO + wo)     = lw0;
        *(uint32_t*)(smc + HIST_HI + wo + 4) = hw1;
        *(uint32_t*)(smc + HIST_LO + wo + 4) = lw1;
    }
}

__global__ __launch_bounds__(NT, 2)
void din_kernel(const float* __restrict__ hist,
                const float* __restrict__ tgt,
                const int*   __restrict__ mask,
                const float* __restrict__ W0,
                const float* __restrict__ b0,
                const float* __restrict__ W1,
                const float* __restrict__ b1,
                const float* __restrict__ W2,
                const float* __restrict__ b2,
                float* __restrict__ out)
{
    extern __shared__ char smc[];
    float* tgtS   = (float*)(smc + OFF_TGT);
    float* c0s    = (float*)(smc + OFF_C0);
    float* b1s    = (float*)(smc + OFF_B1);
    float* w2s    = (float*)(smc + OFF_W2);
    float* scoreS = (float*)(smc + OFF_SC);
    float* attnS  = (float*)(smc + OFF_ATTN);
    float* redS   = (float*)(smc + OFF_RED);
    float* partS  = (float*)(smc + OFF_PART);

    const int b    = blockIdx.x;
    const int tid  = threadIdx.x;
    const int wid  = tid >> 5;
    const int lane = tid & 31;
    const uint32_t smem_base = smem_u32(smc);
    const float4* hb = (const float4*)(hist + (size_t)b * LL * DD);

    if (tid < DD) tgtS[tid] = tgt[(size_t)b * DD + tid];
    __syncthreads();

    // ---- prologue: A0t build + c0 + small vectors + chunk0 staging ----
    for (int w = tid; w < H0N * 64; w += NT) {
        int n  = w % H0N;
        int kp = w / H0N;
        int d  = kp * 2;
        float v0 = W0[d * H0N + n] + W0[(2 * DD + d) * H0N + n] + tgtS[d] * W0[(3 * DD + d) * H0N + n];
        float v1 = W0[(d + 1) * H0N + n] + W0[(2 * DD + d + 1) * H0N + n] + tgtS[d + 1] * W0[(3 * DD + d + 1) * H0N + n];
        uint32_t hw, lw;
        split2(v0, v1, hw, lw);
        uint32_t wo = (uint32_t)(n * S_HIST + kp) * 4u;
        *(uint32_t*)(smc + A0T_HI + wo) = hw;
        *(uint32_t*)(smc + A0T_LO + wo) = lw;
    }
    if (tid < H0N) {
        float s0 = 0.f, s1 = 0.f;
        #pragma unroll 4
        for (int d = 0; d < DD; d += 2) {
            s0 = fmaf(tgtS[d],     W0[(DD + d) * H0N + tid]     - W0[(2 * DD + d) * H0N + tid],     s0);
            s1 = fmaf(tgtS[d + 1], W0[(DD + d + 1) * H0N + tid] - W0[(2 * DD + d + 1) * H0N + tid], s1);
        }
        c0s[tid] = b0[tid] + s0 + s1;
    }
    if (tid < H1N) { b1s[tid] = b1[tid]; w2s[tid] = W2[tid]; }
    stage_chunk(smc, hb, 0, tid);
    __syncthreads();

    // ldmatrix lane geometry (identical to R5)
    const int rA = lane & 15;
    const int kA = (lane & 16) ? 4 : 0;
    const int rB = (lane & 7) | ((lane & 16) >> 1);
    const int kB = (lane & 8) ? 4 : 0;
    const int mb = wid * 16;                   // one m-tile per warp (7 warps)

    #pragma unroll 1
    for (int c = 0; c < 2; ++c) {
        // ===== GEMM0: h0 = relu(hist @ A0t^T + c0), split-bf16 x3 =====
        {
            float C0[10][4];
            #pragma unroll
            for (int n = 0; n < 10; ++n)
                #pragma unroll
                for (int j = 0; j < 4; ++j) C0[n][j] = 0.f;

            #pragma unroll 1
            for (int term = 0; term < 3; ++term) {
                const uint32_t abase = smem_base + ((term == 2) ? HIST_LO : HIST_HI);
                const uint32_t bbase = smem_base + ((term == 1) ? A0T_LO : A0T_HI);
                const uint32_t aAdr  = abase + (uint32_t)((mb + rA) * S_HIST + kA) * 4u;
                const uint32_t bAdr  = bbase + (uint32_t)(rB * S_HIST + kB) * 4u;
                #pragma unroll 1
                for (int ks = 0; ks < 8; ++ks) {
                    uint32_t bf[10][2];
                    #pragma unroll
                    for (int p = 0; p < 5; ++p)
                        LDSM4(bf[2 * p][0], bf[2 * p][1], bf[2 * p + 1][0], bf[2 * p + 1][1],
                              bAdr + (uint32_t)(p * 16 * S_HIST + ks * 8) * 4u);
                    uint32_t a[4];
                    LDSM4(a[0], a[1], a[2], a[3], aAdr + (uint32_t)(ks * 8) * 4u);
                    #pragma unroll
                    for (int n = 0; n < 10; ++n) MMA16816(C0[n], a, bf[n]);
                }
            }
            __syncthreads();   // hist reads done; X region can be overwritten

            // epilogue: bias+relu+split -> H0 (alias X); also rebuild W1T (X tail)
            const int row = mb + (lane >> 2);
            #pragma unroll
            for (int nt = 0; nt < 10; ++nt) {
                const int col = nt * 8 + (lane & 3) * 2;
                uint32_t hw, lw;
                float v0 = fmaxf(C0[nt][0] + c0s[col],     0.f);
                float v1 = fmaxf(C0[nt][1] + c0s[col + 1], 0.f);
                split2(v0, v1, hw, lw);
                uint32_t wo = (uint32_t)(row * S_H0 + nt * 4 + (lane & 3)) * 4u;
                *(uint32_t*)(smc + H0_HI + wo) = hw;
                *(uint32_t*)(smc + H0_LO + wo) = lw;
                v0 = fmaxf(C0[nt][2] + c0s[col],     0.f);
                v1 = fmaxf(C0[nt][3] + c0s[col + 1], 0.f);
                split2(v0, v1, hw, lw);
                wo = (uint32_t)((row + 8) * S_H0 + nt * 4 + (lane & 3)) * 4u;
                *(uint32_t*)(smc + H0_HI + wo) = hw;
                *(uint32_t*)(smc + H0_LO + wo) = lw;
            }
            for (int w = tid; w < H1N * 40; w += NT) {
                int n  = w % H1N;
                int kp = w / H1N;
                int k  = kp * 2;
                uint32_t hw, lw;
                split2(W1[k * H1N + n], W1[(k + 1) * H1N + n], hw, lw);
                uint32_t wo = (uint32_t)(n * S_W1 + kp) * 4u;
                *(uint32_t*)(smc + W1T_HI + wo) = hw;
                *(uint32_t*)(smc + W1T_LO + wo) = lw;
            }
        }
        __syncthreads();

        // ===== GEMM1 + layer2: scores, split-bf16 x3, K=80 =====
        {
            float C1[5][4];
            #pragma unroll
            for (int n = 0; n < 5; ++n)
                #pragma unroll
                for (int j = 0; j < 4; ++j) C1[n][j] = 0.f;

            #pragma unroll 1
            for (int term = 0; term < 3; ++term) {
                const uint32_t abase = smem_base + ((term == 2) ? H0_LO : H0_HI);
                const uint32_t bbase = smem_base + ((term == 1) ? W1T_LO : W1T_HI);
                const uint32_t aAdr  = abase + (uint32_t)((mb + rA) * S_H0 + kA) * 4u;
                const uint32_t bAdr  = bbase + (uint32_t)(rB * S_W1 + kB) * 4u;
                #pragma unroll 1
                for (int ks = 0; ks < 5; ++ks) {
                    uint32_t bf[6][2];
                    #pragma unroll
                    for (int p = 0; p < 3; ++p)    // tile 5 garbage, unused
                        LDSM4(bf[2 * p][0], bf[2 * p][1], bf[2 * p + 1][0], bf[2 * p + 1][1],
                              bAdr + (uint32_t)(p * 16 * S_W1 + ks * 8) * 4u);
                    uint32_t a[4];
                    LDSM4(a[0], a[1], a[2], a[3], aAdr + (uint32_t)(ks * 8) * 4u);
                    #pragma unroll
                    for (int n = 0; n < 5; ++n) MMA16816(C1[n], a, bf[n]);
                }
            }

            const float b2v = b2[0];
            float p0 = 0.f, p1 = 0.f;
            #pragma unroll
            for (int nt = 0; nt < 5; ++nt) {
                const int col = nt * 8 + (lane & 3) * 2;
                p0 += fmaxf(C1[nt][0] + b1s[col],     0.f) * w2s[col]
                    + fmaxf(C1[nt][1] + b1s[col + 1], 0.f) * w2s[col + 1];
                p1 += fmaxf(C1[nt][2] + b1s[col],     0.f) * w2s[col]
                    + fmaxf(C1[nt][3] + b1s[col + 1], 0.f) * w2s[col + 1];
            }
            p0 += __shfl_xor_sync(0xffffffffu, p0, 1);
            p0 += __shfl_xor_sync(0xffffffffu, p0, 2);
            p1 += __shfl_xor_sync(0xffffffffu, p1, 1);
            p1 += __shfl_xor_sync(0xffffffffu, p1, 2);
            if ((lane & 3) == 0) {
                const int row = mb + (lane >> 2);
                scoreS[c * ROWS + row]     = p0 + b2v;
                scoreS[c * ROWS + row + 8] = p1 + b2v;
            }
        }

        if (c == 0) {
            __syncthreads();              // GEMM1 reads of X done
            stage_chunk(smc, hb, 1, tid); // overwrite X with chunk1 hist
            __syncthreads();
        }
    }
    __syncthreads();

    // ---- masked softmax over L (7 warps) ----
    float logit = -3.402823466e38f;
    if (tid < LL) {
        float m = (float)mask[(size_t)b * LL + tid];
        logit = scoreS[tid] + (1.0f - m) * (-1e9f);
    }
    {
        float v = logit;
        #pragma unroll
        for (int o = 16; o; o >>= 1) v = fmaxf(v, __shfl_xor_sync(0xffffffffu, v, o));
        if (lane == 0) redS[wid] = v;
    }
    __syncthreads();
    if (tid < 32) {
        float m = (tid < 7) ? redS[tid] : -3.402823466e38f;
        #pragma unroll
        for (int o = 4; o; o >>= 1) m = fmaxf(m, __shfl_xor_sync(0xffffffffu, m, o));
        if (tid == 0) redS[16] = m;
    }
    __syncthreads();
    const float M = redS[16];
    float e = (tid < LL) ? expf(logit - M) : 0.f;
    {
        float s = e;
        #pragma unroll
        for (int o = 16; o; o >>= 1) s += __shfl_xor_sync(0xffffffffu, s, o);
        if (lane == 0) redS[wid] = s;
    }
    __syncthreads();
    if (tid < 32) {
        float s = (tid < 7) ? redS[tid] : 0.f;
        #pragma unroll
        for (int o = 4; o; o >>= 1) s += __shfl_xor_sync(0xffffffffu, s, o);
        if (tid == 0) redS[17] = s;
    }
    __syncthreads();
    const float S = redS[17];
    if (tid < LL) {
        float a = e / S;
        attnS[tid] = a;
        out[(size_t)BB * DD + (size_t)b * LL + tid] = a;
    }
    __syncthreads();

    // ---- user_interest[b][d] = sum_l attn[l]*hist[l][d]  (gmem fp32, L2-hot) ----
    {
        const float* hbf = hist + (size_t)b * LL * DD;
        for (int i = tid; i < 512; i += NT) {
            const int d = i & 127;
            const int g = i >> 7;           // 0..3, 50 l's each
            float s = 0.f;
            #pragma unroll 2
            for (int l = g * 50; l < g * 50 + 50; ++l)
                s = fmaf(attnS[l], hbf[l * DD + d], s);
            partS[g * 128 + d] = s;
        }
    }
    __syncthreads();
    if (tid < DD)
        out[(size_t)b * DD + tid] = partS[tid] + partS[128 + tid] + partS[256 + tid] + partS[384 + tid];
}

extern "C" void kernel_launch(void* const* d_in, const int* in_sizes, int n_in,
                              void* d_out, int out_size)
{
    const float* hist = (const float*)d_in[0];
    const float* tgt  = (const float*)d_in[1];
    const int*   mask = (const int*)  d_in[2];
    const float* W0   = (const float*)d_in[3];
    const float* b0   = (const float*)d_in[4];
    const float* W1   = (const float*)d_in[5];
    const float* b1   = (const float*)d_in[6];
    const float* W2   = (const float*)d_in[7];
    const float* b2   = (const float*)d_in[8];
    float* out = (float*)d_out;

    static int smem_set = 0;
    if (!smem_set) {
        cudaFuncSetAttribute(din_kernel,
                             cudaFuncAttributeMaxDynamicSharedMemorySize,
                             SMEM_BYTES);
        smem_set = 1;
    }
    din_kernel<<<BB, NT, SMEM_BYTES>>>(hist, tgt, mask, W0, b0, W1, b1, W2, b2, out);
}

// round 7
// speedup vs baseline: 1.9748x; 1.0419x over previous
#include <cuda_runtime.h>
#include <cuda_bf16.h>
#include <cstdint>
#include <math.h>

#define BB 2048
#define LL 200
#define DD 128
#define H0N 80
#define H1N 40
#define NT 224            // 7 warps; 2 CTAs/SM
#define ROWS 112          // L-rows per chunk (2 chunks)

// word strides (conflict-free ldmatrix)
#define S_HIST 68
#define S_H0   44
#define S_W1   44

// ---- smem byte offsets ----
#define HIST_HI 0
#define HIST_LO (ROWS*S_HIST*4)          // 30464
#define H0_HI   0                         // alias (hist dead after GEMM0 mainloop)
#define H0_LO   (ROWS*S_H0*4)             // 19712
#define W1T_HI  (2*ROWS*S_H0*4)           // 39424
#define W1T_LO  (W1T_HI + H1N*S_W1*4)     // 46464
#define A0T_HI  (2*ROWS*S_HIST*4)         // 60928
#define A0T_LO  (A0T_HI + H0N*S_HIST*4)   // 82688
#define MISC    104448
#define OFF_TGT  (MISC + 0)
#define OFF_C0   (MISC + 512)
#define OFF_B1   (MISC + 896)
#define OFF_W2   (MISC + 1088)
#define OFF_SC   (MISC + 1280)
#define OFF_ATTN (MISC + 2176)
#define OFF_RED  (MISC + 3072)
#define OFF_PART (MISC + 3200)
#define SMEM_BYTES (MISC + 5248)          // 109,696 B -> 2 CTAs/SM

#define LDSM4(r0, r1, r2, r3, addr) asm volatile( \
    "ldmatrix.sync.aligned.m8n8.x4.shared.b16 {%0,%1,%2,%3}, [%4];" \
    : "=r"(r0), "=r"(r1), "=r"(r2), "=r"(r3) : "r"(addr))

#define MMA16816(c, a, bfr) asm volatile( \
    "mma.sync.aligned.m16n8k16.row.col.f32.bf16.bf16.f32 " \
    "{%0,%1,%2,%3}, {%4,%5,%6,%7}, {%8,%9}, {%0,%1,%2,%3};" \
    : "+f"((c)[0]), "+f"((c)[1]), "+f"((c)[2]), "+f"((c)[3]) \
    : "r"((a)[0]), "r"((a)[1]), "r"((a)[2]), "r"((a)[3]), \
      "r"((bfr)[0]), "r"((bfr)[1]))

__device__ __forceinline__ uint32_t smem_u32(const void* p) {
    uint32_t a;
    asm("{ .reg .u64 t; cvta.to.shared.u64 t, %1; cvt.u32.u64 %0, t; }" : "=r"(a) : "l"(p));
    return a;
}

__device__ __forceinline__ void split2(float a, float b, uint32_t& hiw, uint32_t& low) {
    __nv_bfloat16 ah = __float2bfloat16(a);
    __nv_bfloat16 bh = __float2bfloat16(b);
    __nv_bfloat16 al = __float2bfloat16(a - __bfloat162float(ah));
    __nv_bfloat16 bl = __float2bfloat16(b - __bfloat162float(bh));
    hiw = (uint32_t)__bfloat16_as_ushort(ah) | ((uint32_t)__bfloat16_as_ushort(bh) << 16);
    low = (uint32_t)__bfloat16_as_ushort(al) | ((uint32_t)__bfloat16_as_ushort(bl) << 16);
}

// stage one 112-row chunk of hist as bf16 hi/lo (rows past L zeroed)
__device__ __forceinline__ void stage_chunk(char* smc, const float4* hb, int c, int tid) {
    for (int idx = tid; idx < ROWS * 32; idx += NT) {
        int r = idx >> 5;
        int q = idx & 31;
        int gl = c * ROWS + r;
        float4 v = make_float4(0.f, 0.f, 0.f, 0.f);
        if (gl < LL) v = hb[gl * 32 + q];
        uint32_t hw0, lw0, hw1, lw1;
        split2(v.x, v.y, hw0, lw0);
        split2(v.z, v.w, hw1, lw1);
        uint32_t wo = (uint32_t)(r * S_HIST + q * 2) * 4u;
        *(uint32_t*)(smc + HIST_HI + wo)     = hw0;
        *(uint32_t*)(smc + HIST_LO + wo)     = lw0;
        *(uint32_t*)(smc + HIST_HI + wo + 4) = hw1;
        *(uint32_t*)(smc + HIST_LO + wo + 4) = lw1;
    }
}

__global__ __launch_bounds__(NT, 2)
void din_kernel(const float* __restrict__ hist,
                const float* __restrict__ tgt,
                const int*   __restrict__ mask,
                const float* __restrict__ W0,
                const float* __restrict__ b0,
                const float* __restrict__ W1,
                const float* __restrict__ b1,
                const float* __restrict__ W2,
                const float* __restrict__ b2,
                float* __restrict__ out)
{
    extern __shared__ char smc[];
    float* tgtS   = (float*)(smc + OFF_TGT);
    float* c0s    = (float*)(smc + OFF_C0);
    float* b1s    = (float*)(smc + OFF_B1);
    float* w2s    = (float*)(smc + OFF_W2);
    float* scoreS = (float*)(smc + OFF_SC);
    float* attnS  = (float*)(smc + OFF_ATTN);
    float* redS   = (float*)(smc + OFF_RED);
    float* partS  = (float*)(smc + OFF_PART);

    const int b    = blockIdx.x;
    const int tid  = threadIdx.x;
    const int wid  = tid >> 5;
    const int lane = tid & 31;
    const uint32_t smem_base = smem_u32(smc);
    const float4* hb = (const float4*)(hist + (size_t)b * LL * DD);

    if (tid < DD) tgtS[tid] = tgt[(size_t)b * DD + tid];
    __syncthreads();

    // ---- prologue: A0t build + c0 + small vectors + chunk0 staging ----
    for (int w = tid; w < H0N * 64; w += NT) {
        int n  = w % H0N;
        int kp = w / H0N;
        int d  = kp * 2;
        float v0 = W0[d * H0N + n] + W0[(2 * DD + d) * H0N + n] + tgtS[d] * W0[(3 * DD + d) * H0N + n];
        float v1 = W0[(d + 1) * H0N + n] + W0[(2 * DD + d + 1) * H0N + n] + tgtS[d + 1] * W0[(3 * DD + d + 1) * H0N + n];
        uint32_t hw, lw;
        split2(v0, v1, hw, lw);
        uint32_t wo = (uint32_t)(n * S_HIST + kp) * 4u;
        *(uint32_t*)(smc + A0T_HI + wo) = hw;
        *(uint32_t*)(smc + A0T_LO + wo) = lw;
    }
    if (tid < H0N) {
        float s0 = 0.f, s1 = 0.f;
        #pragma unroll 4
        for (int d = 0; d < DD; d += 2) {
            s0 = fmaf(tgtS[d],     W0[(DD + d) * H0N + tid]     - W0[(2 * DD + d) * H0N + tid],     s0);
            s1 = fmaf(tgtS[d + 1], W0[(DD + d + 1) * H0N + tid] - W0[(2 * DD + d + 1) * H0N + tid], s1);
        }
        c0s[tid] = b0[tid] + s0 + s1;
    }
    if (tid < H1N) { b1s[tid] = b1[tid]; w2s[tid] = W2[tid]; }
    stage_chunk(smc, hb, 0, tid);
    __syncthreads();

    // ldmatrix lane geometry
    const int rA = lane & 15;
    const int kA = (lane & 16) ? 4 : 0;
    const int rB = (lane & 7) | ((lane & 16) >> 1);
    const int kB = (lane & 8) ? 4 : 0;
    const int mb = wid * 16;                   // one m-tile per warp (7 warps)

    #pragma unroll 1
    for (int c = 0; c < 2; ++c) {
        // ===== GEMM0: h0 = relu(hist @ A0t^T + c0), fused split-bf16 (3 terms / k-step) =====
        {
            float C0[10][4];
            #pragma unroll
            for (int n = 0; n < 10; ++n)
                #pragma unroll
                for (int j = 0; j < 4; ++j) C0[n][j] = 0.f;

            const uint32_t aHiAdr = smem_base + HIST_HI + (uint32_t)((mb + rA) * S_HIST + kA) * 4u;
            const uint32_t aLoAdr = smem_base + HIST_LO + (uint32_t)((mb + rA) * S_HIST + kA) * 4u;
            const uint32_t bHiAdr = smem_base + A0T_HI + (uint32_t)(rB * S_HIST + kB) * 4u;
            const uint32_t bLoAdr = smem_base + A0T_LO + (uint32_t)(rB * S_HIST + kB) * 4u;

            #pragma unroll 2
            for (int ks = 0; ks < 8; ++ks) {
                const uint32_t ko = (uint32_t)(ks * 8) * 4u;
                uint32_t bHi[10][2], bLo[10][2], aHi[4], aLo[4];
                #pragma unroll
                for (int p = 0; p < 5; ++p) {
                    const uint32_t po = (uint32_t)(p * 16 * S_HIST) * 4u + ko;
                    LDSM4(bHi[2*p][0], bHi[2*p][1], bHi[2*p+1][0], bHi[2*p+1][1], bHiAdr + po);
                    LDSM4(bLo[2*p][0], bLo[2*p][1], bLo[2*p+1][0], bLo[2*p+1][1], bLoAdr + po);
                }
                LDSM4(aHi[0], aHi[1], aHi[2], aHi[3], aHiAdr + ko);
                LDSM4(aLo[0], aLo[1], aLo[2], aLo[3], aLoAdr + ko);
                #pragma unroll
                for (int n = 0; n < 10; ++n) MMA16816(C0[n], aHi, bHi[n]);
                #pragma unroll
                for (int n = 0; n < 10; ++n) MMA16816(C0[n], aHi, bLo[n]);
                #pragma unroll
                for (int n = 0; n < 10; ++n) MMA16816(C0[n], aLo, bHi[n]);
            }
            __syncthreads();   // hist reads done; X region can be overwritten

            // epilogue: bias+relu+split -> H0 (alias X); rebuild W1T (X tail)
            const int row = mb + (lane >> 2);
            #pragma unroll
            for (int nt = 0; nt < 10; ++nt) {
                const int col = nt * 8 + (lane & 3) * 2;
                uint32_t hw, lw;
                float v0 = fmaxf(C0[nt][0] + c0s[col],     0.f);
                float v1 = fmaxf(C0[nt][1] + c0s[col + 1], 0.f);
                split2(v0, v1, hw, lw);
                uint32_t wo = (uint32_t)(row * S_H0 + nt * 4 + (lane & 3)) * 4u;
                *(uint32_t*)(smc + H0_HI + wo) = hw;
                *(uint32_t*)(smc + H0_LO + wo) = lw;
                v0 = fmaxf(C0[nt][2] + c0s[col],     0.f);
                v1 = fmaxf(C0[nt][3] + c0s[col + 1], 0.f);
                split2(v0, v1, hw, lw);
                wo = (uint32_t)((row + 8) * S_H0 + nt * 4 + (lane & 3)) * 4u;
                *(uint32_t*)(smc + H0_HI + wo) = hw;
                *(uint32_t*)(smc + H0_LO + wo) = lw;
            }
            for (int w = tid; w < H1N * 40; w += NT) {
                int n  = w % H1N;
                int kp = w / H1N;
                int k  = kp * 2;
                uint32_t hw, lw;
                split2(W1[k * H1N + n], W1[(k + 1) * H1N + n], hw, lw);
                uint32_t wo = (uint32_t)(n * S_W1 + kp) * 4u;
                *(uint32_t*)(smc + W1T_HI + wo) = hw;
                *(uint32_t*)(smc + W1T_LO + wo) = lw;
            }
        }
        __syncthreads();

        // ===== GEMM1 + layer2: scores, fused split-bf16, K=80 =====
        {
            float C1[5][4];
            #pragma unroll
            for (int n = 0; n < 5; ++n)
                #pragma unroll
                for (int j = 0; j < 4; ++j) C1[n][j] = 0.f;

            const uint32_t aHiAdr = smem_base + H0_HI + (uint32_t)((mb + rA) * S_H0 + kA) * 4u;
            const uint32_t aLoAdr = smem_base + H0_LO + (uint32_t)((mb + rA) * S_H0 + kA) * 4u;
            const uint32_t bHiAdr = smem_base + W1T_HI + (uint32_t)(rB * S_W1 + kB) * 4u;
            const uint32_t bLoAdr = smem_base + W1T_LO + (uint32_t)(rB * S_W1 + kB) * 4u;

            #pragma unroll 2
            for (int ks = 0; ks < 5; ++ks) {
                const uint32_t ko = (uint32_t)(ks * 8) * 4u;
                uint32_t bHi[6][2], bLo[6][2], aHi[4], aLo[4];
                #pragma unroll
                for (int p = 0; p < 3; ++p) {      // tile 5 garbage, unused
                    const uint32_t po = (uint32_t)(p * 16 * S_W1) * 4u + ko;
                    LDSM4(bHi[2*p][0], bHi[2*p][1], bHi[2*p+1][0], bHi[2*p+1][1], bHiAdr + po);
                    LDSM4(bLo[2*p][0], bLo[2*p][1], bLo[2*p+1][0], bLo[2*p+1][1], bLoAdr + po);
                }
                LDSM4(aHi[0], aHi[1], aHi[2], aHi[3], aHiAdr + ko);
                LDSM4(aLo[0], aLo[1], aLo[2], aLo[3], aLoAdr + ko);
                #pragma unroll
                for (int n = 0; n < 5; ++n) MMA16816(C1[n], aHi, bHi[n]);
                #pragma unroll
                for (int n = 0; n < 5; ++n) MMA16816(C1[n], aHi, bLo[n]);
                #pragma unroll
                for (int n = 0; n < 5; ++n) MMA16816(C1[n], aLo, bHi[n]);
            }

            const float b2v = b2[0];
            float p0 = 0.f, p1 = 0.f;
            #pragma unroll
            for (int nt = 0; nt < 5; ++nt) {
                const int col = nt * 8 + (lane & 3) * 2;
                p0 += fmaxf(C1[nt][0] + b1s[col],     0.f) * w2s[col]
                    + fmaxf(C1[nt][1] + b1s[col + 1], 0.f) * w2s[col + 1];
                p1 += fmaxf(C1[nt][2] + b1s[col],     0.f) * w2s[col]
                    + fmaxf(C1[nt][3] + b1s[col + 1], 0.f) * w2s[col + 1];
            }
            p0 += __shfl_xor_sync(0xffffffffu, p0, 1);
            p0 += __shfl_xor_sync(0xffffffffu, p0, 2);
            p1 += __shfl_xor_sync(0xffffffffu, p1, 1);
            p1 += __shfl_xor_sync(0xffffffffu, p1, 2);
            if ((lane & 3) == 0) {
                const int row = mb + (lane >> 2);
                scoreS[c * ROWS + row]     = p0 + b2v;
                scoreS[c * ROWS + row + 8] = p1 + b2v;
            }
        }

        if (c == 0) {
            __syncthreads();              // GEMM1 reads of X done
            stage_chunk(smc, hb, 1, tid); // overwrite X with chunk1 hist
            __syncthreads();
        }
    }
    __syncthreads();

    // ---- masked softmax over L (7 warps) ----
    float logit = -3.402823466e38f;
    if (tid < LL) {
        float m = (float)mask[(size_t)b * LL + tid];
        logit = scoreS[tid] + (1.0f - m) * (-1e9f);
    }
    {
        float v = logit;
        #pragma unroll
        for (int o = 16; o; o >>= 1) v = fmaxf(v, __shfl_xor_sync(0xffffffffu, v, o));
        if (lane == 0) redS[wid] = v;
    }
    __syncthreads();
    if (tid < 32) {
        float m = (tid < 7) ? redS[tid] : -3.402823466e38f;
        #pragma unroll
        for (int o = 4; o; o >>= 1) m = fmaxf(m, __shfl_xor_sync(0xffffffffu, m, o));
        if (tid == 0) redS[16] = m;
    }
    __syncthreads();
    const float M = redS[16];
    float e = (tid < LL) ? expf(logit - M) : 0.f;
    {
        float s = e;
        #pragma unroll
        for (int o = 16; o; o >>= 1) s += __shfl_xor_sync(0xffffffffu, s, o);
        if (lane == 0) redS[wid] = s;
    }
    __syncthreads();
    if (tid < 32) {
        float s = (tid < 7) ? redS[tid] : 0.f;
        #pragma unroll
        for (int o = 4; o; o >>= 1) s += __shfl_xor_sync(0xffffffffu, s, o);
        if (tid == 0) redS[17] = s;
    }
    __syncthreads();
    const float S = redS[17];
    if (tid < LL) {
        float a = e / S;
        attnS[tid] = a;
        out[(size_t)BB * DD + (size_t)b * LL + tid] = a;
    }
    __syncthreads();

    // ---- user_interest[b][d] = sum_l attn[l]*hist[l][d]  (gmem fp32, L2-hot) ----
    {
        const float* hbf = hist + (size_t)b * LL * DD;
        for (int i = tid; i < 512; i += NT) {
            const int d = i & 127;
            const int g = i >> 7;
            float s = 0.f;
            #pragma unroll 2
            for (int l = g * 50; l < g * 50 + 50; ++l)
                s = fmaf(attnS[l], hbf[l * DD + d], s);
            partS[g * 128 + d] = s;
        }
    }
    __syncthreads();
    if (tid < DD)
        out[(size_t)b * DD + tid] = partS[tid] + partS[128 + tid] + partS[256 + tid] + partS[384 + tid];
}

extern "C" void kernel_launch(void* const* d_in, const int* in_sizes, int n_in,
                              void* d_out, int out_size)
{
    const float* hist = (const float*)d_in[0];
    const float* tgt  = (const float*)d_in[1];
    const int*   mask = (const int*)  d_in[2];
    const float* W0   = (const float*)d_in[3];
    const float* b0   = (const float*)d_in[4];
    const float* W1   = (const float*)d_in[5];
    const float* b1   = (const float*)d_in[6];
    const float* W2   = (const float*)d_in[7];
    const float* b2   = (const float*)d_in[8];
    float* out = (float*)d_out;

    static int smem_set = 0;
    if (!smem_set) {
        cudaFuncSetAttribute(din_kernel,
                             cudaFuncAttributeMaxDynamicSharedMemorySize,
                             SMEM_BYTES);
        smem_set = 1;
    }
    din_kernel<<<BB, NT, SMEM_BYTES>>>(hist, tgt, mask, W0, b0, W1, b1, W2, b2, out);
}

// round 8
// speedup vs baseline: 2.4719x; 1.2517x over previous
#include <cuda_runtime.h>
#include <cuda_bf16.h>
#include <cstdint>
#include <math.h>

#define BB 2048
#define LL 200
#define DD 128
#define H0N 80
#define H1N 40
#define NT 448            // 14 warps: (m-tile w%7) x (n-half w/7); 2 CTAs/SM
#define ROWS 112          // L-rows per chunk (2 chunks)

// word strides (conflict-free ldmatrix; 16B-aligned rows)
#define S_HIST 68
#define S_H0   44
#define S_W1   44

// ---- smem byte offsets ----
#define HIST_HI 0
#define HIST_LO (ROWS*S_HIST*4)          // 30464
#define H0_HI   0                         // alias (hist dead after GEMM0 mainloop)
#define H0_LO   (ROWS*S_H0*4)             // 19712
#define W1T_HI  (2*ROWS*S_H0*4)           // 39424
#define W1T_LO  (W1T_HI + H1N*S_W1*4)     // 46464
#define A0T_HI  (2*ROWS*S_HIST*4)         // 60928
#define A0T_LO  (A0T_HI + H0N*S_HIST*4)   // 82688
#define MISC    104448
#define OFF_TGT  (MISC + 0)
#define OFF_C0   (MISC + 512)
#define OFF_B1   (MISC + 896)
#define OFF_W2   (MISC + 1088)
#define OFF_SC   (MISC + 1280)
#define OFF_ATTN (MISC + 2176)
#define OFF_RED  (MISC + 3072)
#define OFF_PART (MISC + 3200)
#define SMEM_BYTES (MISC + 5248)          // 109,696 B -> 2 CTAs/SM

#define LDSM4(r0, r1, r2, r3, addr) asm volatile( \
    "ldmatrix.sync.aligned.m8n8.x4.shared.b16 {%0,%1,%2,%3}, [%4];" \
    : "=r"(r0), "=r"(r1), "=r"(r2), "=r"(r3) : "r"(addr))

#define LDSM2(r0, r1, addr) asm volatile( \
    "ldmatrix.sync.aligned.m8n8.x2.shared.b16 {%0,%1}, [%2];" \
    : "=r"(r0), "=r"(r1) : "r"(addr))

#define MMA16816(c, a, bfr) asm volatile( \
    "mma.sync.aligned.m16n8k16.row.col.f32.bf16.bf16.f32 " \
    "{%0,%1,%2,%3}, {%4,%5,%6,%7}, {%8,%9}, {%0,%1,%2,%3};" \
    : "+f"((c)[0]), "+f"((c)[1]), "+f"((c)[2]), "+f"((c)[3]) \
    : "r"((a)[0]), "r"((a)[1]), "r"((a)[2]), "r"((a)[3]), \
      "r"((bfr)[0]), "r"((bfr)[1]))

__device__ __forceinline__ uint32_t smem_u32(const void* p) {
    uint32_t a;
    asm("{ .reg .u64 t; cvta.to.shared.u64 t, %1; cvt.u32.u64 %0, t; }" : "=r"(a) : "l"(p));
    return a;
}

__device__ __forceinline__ void split2(float a, float b, uint32_t& hiw, uint32_t& low) {
    __nv_bfloat16 ah = __float2bfloat16(a);
    __nv_bfloat16 bh = __float2bfloat16(b);
    __nv_bfloat16 al = __float2bfloat16(a - __bfloat162float(ah));
    __nv_bfloat16 bl = __float2bfloat16(b - __bfloat162float(bh));
    hiw = (uint32_t)__bfloat16_as_ushort(ah) | ((uint32_t)__bfloat16_as_ushort(bh) << 16);
    low = (uint32_t)__bfloat16_as_ushort(al) | ((uint32_t)__bfloat16_as_ushort(bl) << 16);
}

// stage one 112-row chunk of hist as bf16 hi/lo (rows past L zeroed)
__device__ __forceinline__ void stage_chunk(char* smc, const float4* hb, int c, int tid) {
    for (int idx = tid; idx < ROWS * 32; idx += NT) {
        int r = idx >> 5;
        int q = idx & 31;
        int gl = c * ROWS + r;
        float4 v = make_float4(0.f, 0.f, 0.f, 0.f);
        if (gl < LL) v = hb[gl * 32 + q];
        uint32_t hw0, lw0, hw1, lw1;
        split2(v.x, v.y, hw0, lw0);
        split2(v.z, v.w, hw1, lw1);
        uint32_t wo = (uint32_t)(r * S_HIST + q * 2) * 4u;
        *(uint32_t*)(smc + HIST_HI + wo)     = hw0;
        *(uint32_t*)(smc + HIST_LO + wo)     = lw0;
        *(uint32_t*)(smc + HIST_HI + wo + 4) = hw1;
        *(uint32_t*)(smc + HIST_LO + wo + 4) = lw1;
    }
}

__global__ __launch_bounds__(NT, 2)
void din_kernel(const float* __restrict__ hist,
                const float* __restrict__ tgt,
                const int*   __restrict__ mask,
                const float* __restrict__ W0,
                const float* __restrict__ b0,
                const float* __restrict__ W1,
                const float* __restrict__ b1,
                const float* __restrict__ W2,
                const float* __restrict__ b2,
                float* __restrict__ out)
{
    extern __shared__ char smc[];
    float* tgtS   = (float*)(smc + OFF_TGT);
    float* c0s    = (float*)(smc + OFF_C0);
    float* b1s    = (float*)(smc + OFF_B1);
    float* w2s    = (float*)(smc + OFF_W2);
    float* scoreS = (float*)(smc + OFF_SC);
    float* attnS  = (float*)(smc + OFF_ATTN);
    float* redS   = (float*)(smc + OFF_RED);
    float* partS  = (float*)(smc + OFF_PART);

    const int b    = blockIdx.x;
    const int tid  = threadIdx.x;
    const int wid  = tid >> 5;
    const int lane = tid & 31;
    const int mwid = (wid < 7) ? wid : wid - 7;   // m-tile index 0..6
    const int nh   = (wid < 7) ? 0 : 1;           // n-half
    const uint32_t smem_base = smem_u32(smc);
    const float4* hb = (const float4*)(hist + (size_t)b * LL * DD);

    if (tid < DD) tgtS[tid] = tgt[(size_t)b * DD + tid];
    __syncthreads();

    // ---- prologue: A0t build + c0 + small vectors + chunk0 staging ----
    for (int w = tid; w < H0N * 64; w += NT) {
        int n  = w % H0N;
        int kp = w / H0N;
        int d  = kp * 2;
        float v0 = W0[d * H0N + n] + W0[(2 * DD + d) * H0N + n] + tgtS[d] * W0[(3 * DD + d) * H0N + n];
        float v1 = W0[(d + 1) * H0N + n] + W0[(2 * DD + d + 1) * H0N + n] + tgtS[d + 1] * W0[(3 * DD + d + 1) * H0N + n];
        uint32_t hw, lw;
        split2(v0, v1, hw, lw);
        uint32_t wo = (uint32_t)(n * S_HIST + kp) * 4u;
        *(uint32_t*)(smc + A0T_HI + wo) = hw;
        *(uint32_t*)(smc + A0T_LO + wo) = lw;
    }
    if (tid < H0N) {
        float s0 = 0.f, s1 = 0.f;
        #pragma unroll 4
        for (int d = 0; d < DD; d += 2) {
            s0 = fmaf(tgtS[d],     W0[(DD + d) * H0N + tid]     - W0[(2 * DD + d) * H0N + tid],     s0);
            s1 = fmaf(tgtS[d + 1], W0[(DD + d + 1) * H0N + tid] - W0[(2 * DD + d + 1) * H0N + tid], s1);
        }
        c0s[tid] = b0[tid] + s0 + s1;
    }
    if (tid < H1N) { b1s[tid] = b1[tid]; w2s[tid] = W2[tid]; }
    stage_chunk(smc, hb, 0, tid);
    __syncthreads();

    // ldmatrix lane geometry
    const int rA = lane & 15;
    const int kA = (lane & 16) ? 4 : 0;
    const int rB = (lane & 7) | ((lane & 16) >> 1);
    const int kB = (lane & 8) ? 4 : 0;
    const int rB2 = lane & 7;                    // x2 geometry (lanes 0-15 used)
    const int kB2 = (lane & 8) ? 4 : 0;
    const int mb = mwid * 16;

    #pragma unroll 1
    for (int c = 0; c < 2; ++c) {
        // ===== GEMM0: h0 = relu(hist @ A0t^T + c0); warp = (m-tile, 40-col n-half) =====
        {
            float C0[5][4];
            #pragma unroll
            for (int n = 0; n < 5; ++n)
                #pragma unroll
                for (int j = 0; j < 4; ++j) C0[n][j] = 0.f;

            const uint32_t aHiAdr = smem_base + HIST_HI + (uint32_t)((mb + rA) * S_HIST + kA) * 4u;
            const uint32_t aLoAdr = smem_base + HIST_LO + (uint32_t)((mb + rA) * S_HIST + kA) * 4u;
            const int nrow0 = nh * 40;
            const uint32_t bHiAdr  = smem_base + A0T_HI + (uint32_t)((nrow0 + rB) * S_HIST + kB) * 4u;
            const uint32_t bLoAdr  = smem_base + A0T_LO + (uint32_t)((nrow0 + rB) * S_HIST + kB) * 4u;
            const uint32_t bHiAdr2 = smem_base + A0T_HI + (uint32_t)((nrow0 + 32 + rB2) * S_HIST + kB2) * 4u;
            const uint32_t bLoAdr2 = smem_base + A0T_LO + (uint32_t)((nrow0 + 32 + rB2) * S_HIST + kB2) * 4u;

            #pragma unroll 2
            for (int ks = 0; ks < 8; ++ks) {
                const uint32_t ko = (uint32_t)(ks * 8) * 4u;
                uint32_t bHi[5][2], bLo[5][2], aHi[4], aLo[4];
                #pragma unroll
                for (int p = 0; p < 2; ++p) {
                    const uint32_t po = (uint32_t)(p * 16 * S_HIST) * 4u + ko;
                    LDSM4(bHi[2*p][0], bHi[2*p][1], bHi[2*p+1][0], bHi[2*p+1][1], bHiAdr + po);
                    LDSM4(bLo[2*p][0], bLo[2*p][1], bLo[2*p+1][0], bLo[2*p+1][1], bLoAdr + po);
                }
                LDSM2(bHi[4][0], bHi[4][1], bHiAdr2 + ko);
                LDSM2(bLo[4][0], bLo[4][1], bLoAdr2 + ko);
                LDSM4(aHi[0], aHi[1], aHi[2], aHi[3], aHiAdr + ko);
                LDSM4(aLo[0], aLo[1], aLo[2], aLo[3], aLoAdr + ko);
                #pragma unroll
                for (int n = 0; n < 5; ++n) MMA16816(C0[n], aHi, bHi[n]);
                #pragma unroll
                for (int n = 0; n < 5; ++n) MMA16816(C0[n], aHi, bLo[n]);
                #pragma unroll
                for (int n = 0; n < 5; ++n) MMA16816(C0[n], aLo, bHi[n]);
            }
            __syncthreads();   // hist reads done; X region can be overwritten

            // epilogue: bias+relu+split -> H0 (alias X); rebuild W1T (X tail)
            const int row = mb + (lane >> 2);
            #pragma unroll
            for (int nt = 0; nt < 5; ++nt) {
                const int g   = nh * 5 + nt;
                const int col = g * 8 + (lane & 3) * 2;
                uint32_t hw, lw;
                float v0 = fmaxf(C0[nt][0] + c0s[col],     0.f);
                float v1 = fmaxf(C0[nt][1] + c0s[col + 1], 0.f);
                split2(v0, v1, hw, lw);
                uint32_t wo = (uint32_t)(row * S_H0 + g * 4 + (lane & 3)) * 4u;
                *(uint32_t*)(smc + H0_HI + wo) = hw;
                *(uint32_t*)(smc + H0_LO + wo) = lw;
                v0 = fmaxf(C0[nt][2] + c0s[col],     0.f);
                v1 = fmaxf(C0[nt][3] + c0s[col + 1], 0.f);
                split2(v0, v1, hw, lw);
                wo = (uint32_t)((row + 8) * S_H0 + g * 4 + (lane & 3)) * 4u;
                *(uint32_t*)(smc + H0_HI + wo) = hw;
                *(uint32_t*)(smc + H0_LO + wo) = lw;
            }
            for (int w = tid; w < H1N * 40; w += NT) {
                int n  = w % H1N;
                int kp = w / H1N;
                int k  = kp * 2;
                uint32_t hw, lw;
                split2(W1[k * H1N + n], W1[(k + 1) * H1N + n], hw, lw);
                uint32_t wo = (uint32_t)(n * S_W1 + kp) * 4u;
                *(uint32_t*)(smc + W1T_HI + wo) = hw;
                *(uint32_t*)(smc + W1T_LO + wo) = lw;
            }
        }
        __syncthreads();

        // ===== GEMM1 + layer2: scores (nh==0 warps only), fused split-bf16, K=80 =====
        if (nh == 0) {
            float C1[5][4];
            #pragma unroll
            for (int n = 0; n < 5; ++n)
                #pragma unroll
                for (int j = 0; j < 4; ++j) C1[n][j] = 0.f;

            const uint32_t aHiAdr = smem_base + H0_HI + (uint32_t)((mb + rA) * S_H0 + kA) * 4u;
            const uint32_t aLoAdr = smem_base + H0_LO + (uint32_t)((mb + rA) * S_H0 + kA) * 4u;
            const uint32_t bHiAdr = smem_base + W1T_HI + (uint32_t)(rB * S_W1 + kB) * 4u;
            const uint32_t bLoAdr = smem_base + W1T_LO + (uint32_t)(rB * S_W1 + kB) * 4u;

            #pragma unroll 2
            for (int ks = 0; ks < 5; ++ks) {
                const uint32_t ko = (uint32_t)(ks * 8) * 4u;
                uint32_t bHi[6][2], bLo[6][2], aHi[4], aLo[4];
                #pragma unroll
                for (int p = 0; p < 3; ++p) {      // tile 5 garbage, unused
                    const uint32_t po = (uint32_t)(p * 16 * S_W1) * 4u + ko;
                    LDSM4(bHi[2*p][0], bHi[2*p][1], bHi[2*p+1][0], bHi[2*p+1][1], bHiAdr + po);
                    LDSM4(bLo[2*p][0], bLo[2*p][1], bLo[2*p+1][0], bLo[2*p+1][1], bLoAdr + po);
                }
                LDSM4(aHi[0], aHi[1], aHi[2], aHi[3], aHiAdr + ko);
                LDSM4(aLo[0], aLo[1], aLo[2], aLo[3], aLoAdr + ko);
                #pragma unroll
                for (int n = 0; n < 5; ++n) MMA16816(C1[n], aHi, bHi[n]);
                #pragma unroll
                for (int n = 0; n < 5; ++n) MMA16816(C1[n], aHi, bLo[n]);
                #pragma unroll
                for (int n = 0; n < 5; ++n) MMA16816(C1[n], aLo, bHi[n]);
            }

            const float b2v = b2[0];
            float p0 = 0.f, p1 = 0.f;
            #pragma unroll
            for (int nt = 0; nt < 5; ++nt) {
                const int col = nt * 8 + (lane & 3) * 2;
                p0 += fmaxf(C1[nt][0] + b1s[col],     0.f) * w2s[col]
                    + fmaxf(C1[nt][1] + b1s[col + 1], 0.f) * w2s[col + 1];
                p1 += fmaxf(C1[nt][2] + b1s[col],     0.f) * w2s[col]
                    + fmaxf(C1[nt][3] + b1s[col + 1], 0.f) * w2s[col + 1];
            }
            p0 += __shfl_xor_sync(0xffffffffu, p0, 1);
            p0 += __shfl_xor_sync(0xffffffffu, p0, 2);
            p1 += __shfl_xor_sync(0xffffffffu, p1, 1);
            p1 += __shfl_xor_sync(0xffffffffu, p1, 2);
            if ((lane & 3) == 0) {
                const int row = mb + (lane >> 2);
                scoreS[c * ROWS + row]     = p0 + b2v;
                scoreS[c * ROWS + row + 8] = p1 + b2v;
            }
        }

        if (c == 0) {
            __syncthreads();              // GEMM1 reads of X done
            stage_chunk(smc, hb, 1, tid); // overwrite X with chunk1 hist
            __syncthreads();
        }
    }
    __syncthreads();

    // ---- masked softmax over L (14 warps) ----
    float logit = -3.402823466e38f;
    if (tid < LL) {
        float m = (float)mask[(size_t)b * LL + tid];
        logit = scoreS[tid] + (1.0f - m) * (-1e9f);
    }
    {
        float v = logit;
        #pragma unroll
        for (int o = 16; o; o >>= 1) v = fmaxf(v, __shfl_xor_sync(0xffffffffu, v, o));
        if (lane == 0) redS[wid] = v;
    }
    __syncthreads();
    if (tid < 32) {
        float m = (tid < 14) ? redS[tid] : -3.402823466e38f;
        #pragma unroll
        for (int o = 8; o; o >>= 1) m = fmaxf(m, __shfl_xor_sync(0xffffffffu, m, o));
        if (tid == 0) redS[16] = m;
    }
    __syncthreads();
    const float M = redS[16];
    float e = (tid < LL) ? expf(logit - M) : 0.f;
    {
        float s = e;
        #pragma unroll
        for (int o = 16; o; o >>= 1) s += __shfl_xor_sync(0xffffffffu, s, o);
        if (lane == 0) redS[wid] = s;
    }
    __syncthreads();
    if (tid < 32) {
        float s = (tid < 14) ? redS[tid] : 0.f;
        #pragma unroll
        for (int o = 8; o; o >>= 1) s += __shfl_xor_sync(0xffffffffu, s, o);
        if (tid == 0) redS[17] = s;
    }
    __syncthreads();
    const float S = redS[17];
    if (tid < LL) {
        float a = e / S;
        attnS[tid] = a;
        out[(size_t)BB * DD + (size_t)b * LL + tid] = a;
    }
    __syncthreads();

    // ---- user_interest[b][d] = sum_l attn[l]*hist[l][d]  (gmem fp32, L2-hot) ----
    {
        const float* hbf = hist + (size_t)b * LL * DD;
        for (int i = tid; i < 512; i += NT) {
            const int d = i & 127;
            const int g = i >> 7;
            float s = 0.f;
            #pragma unroll 2
            for (int l = g * 50; l < g * 50 + 50; ++l)
                s = fmaf(attnS[l], hbf[l * DD + d], s);
            partS[g * 128 + d] = s;
        }
    }
    __syncthreads();
    if (tid < DD)
        out[(size_t)b * DD + tid] = partS[tid] + partS[128 + tid] + partS[256 + tid] + partS[384 + tid];
}

extern "C" void kernel_launch(void* const* d_in, const int* in_sizes, int n_in,
                              void* d_out, int out_size)
{
    const float* hist = (const float*)d_in[0];
    const float* tgt  = (const float*)d_in[1];
    const int*   mask = (const int*)  d_in[2];
    const float* W0   = (const float*)d_in[3];
    const float* b0   = (const float*)d_in[4];
    const float* W1   = (const float*)d_in[5];
    const float* b1   = (const float*)d_in[6];
    const float* W2   = (const float*)d_in[7];
    const float* b2   = (const float*)d_in[8];
    float* out = (float*)d_out;

    static int smem_set = 0;
    if (!smem_set) {
        cudaFuncSetAttribute(din_kernel,
                             cudaFuncAttributeMaxDynamicSharedMemorySize,
                             SMEM_BYTES);
        smem_set = 1;
    }
    din_kernel<<<BB, NT, SMEM_BYTES>>>(hist, tgt, mask, W0, b0, W1, b1, W2, b2, out);
}

// round 10
// speedup vs baseline: 2.5373x; 1.0265x over previous
#include <cuda_runtime.h>
#include <cuda_bf16.h>
#include <cstdint>
#include <math.h>

#define BB 2048
#define LL 200
#define DD 128
#define H0N 80
#define H1N 40
#define NT 448            // 14 warps: (m-tile w%7) x (n-half w/7); 2 CTAs/SM
#define ROWS 112          // L-rows per chunk (2 chunks)

// word strides (conflict-free ldmatrix; stride ≡ 4 mod 32)
#define S_HIST 68
#define S_H0   44
#define S_W1   44

// ---- smem byte offsets ----
#define HIST_HI 0
#define HIST_LO (ROWS*S_HIST*4)          // 30464
#define H0_HI   0                         // alias (hist dead after GEMM0 mainloop)
#define H0_LO   (ROWS*S_H0*4)             // 19712
#define W1T_HI  (2*ROWS*S_H0*4)           // 39424
#define W1T_LO  (W1T_HI + H1N*S_W1*4)     // 46464
#define A0T_HI  (2*ROWS*S_HIST*4)         // 60928
#define A0T_LO  (A0T_HI + H0N*S_HIST*4)   // 82688
#define MISC    104448
#define OFF_TGT  (MISC + 0)       // 128 f
#define OFF_C0   (MISC + 512)     // 80 f
#define OFF_B1   (MISC + 896)     // 40 f
#define OFF_W2   (MISC + 1088)    // 40 f
#define OFF_SC   (MISC + 1280)    // 224 f (nh0 partial)
#define OFF_SC2  (MISC + 2176)    // 224 f (nh1 partial)
#define OFF_ATTN (MISC + 3072)    // 224 f
#define OFF_RED  (MISC + 3968)    // 32 f
#define OFF_PART (MISC + 4096)    // 512 f
#define SMEM_BYTES (MISC + 6144)  // 110,592 B -> 2 CTAs/SM

#define LDSM4(r0, r1, r2, r3, addr) asm volatile( \
    "ldmatrix.sync.aligned.m8n8.x4.shared.b16 {%0,%1,%2,%3}, [%4];" \
    : "=r"(r0), "=r"(r1), "=r"(r2), "=r"(r3) : "r"(addr))

#define LDSM2(r0, r1, addr) asm volatile( \
    "ldmatrix.sync.aligned.m8n8.x2.shared.b16 {%0,%1}, [%2];" \
    : "=r"(r0), "=r"(r1) : "r"(addr))

#define MMA16816(c, a, bfr) asm volatile( \
    "mma.sync.aligned.m16n8k16.row.col.f32.bf16.bf16.f32 " \
    "{%0,%1,%2,%3}, {%4,%5,%6,%7}, {%8,%9}, {%0,%1,%2,%3};" \
    : "+f"((c)[0]), "+f"((c)[1]), "+f"((c)[2]), "+f"((c)[3]) \
    : "r"((a)[0]), "r"((a)[1]), "r"((a)[2]), "r"((a)[3]), \
      "r"((bfr)[0]), "r"((bfr)[1]))

__device__ __forceinline__ uint32_t smem_u32(const void* p) {
    uint32_t a;
    asm("{ .reg .u64 t; cvta.to.shared.u64 t, %1; cvt.u32.u64 %0, t; }" : "=r"(a) : "l"(p));
    return a;
}

__device__ __forceinline__ void split2(float a, float b, uint32_t& hiw, uint32_t& low) {
    __nv_bfloat16 ah = __float2bfloat16(a);
    __nv_bfloat16 bh = __float2bfloat16(b);
    __nv_bfloat16 al = __float2bfloat16(a - __bfloat162float(ah));
    __nv_bfloat16 bl = __float2bfloat16(b - __bfloat162float(bh));
    hiw = (uint32_t)__bfloat16_as_ushort(ah) | ((uint32_t)__bfloat16_as_ushort(bh) << 16);
    low = (uint32_t)__bfloat16_as_ushort(al) | ((uint32_t)__bfloat16_as_ushort(bl) << 16);
}

// stage one 112-row chunk of hist as bf16 hi/lo (rows past L zeroed); STS.64
__device__ __forceinline__ void stage_chunk(char* smc, const float4* hb, int c, int tid) {
    for (int idx = tid; idx < ROWS * 32; idx += NT) {
        int r = idx >> 5;
        int q = idx & 31;
        int gl = c * ROWS + r;
        float4 v = make_float4(0.f, 0.f, 0.f, 0.f);
        if (gl < LL) v = hb[gl * 32 + q];
        uint32_t hw0, lw0, hw1, lw1;
        split2(v.x, v.y, hw0, lw0);
        split2(v.z, v.w, hw1, lw1);
        uint32_t wo = (uint32_t)(r * S_HIST + q * 2) * 4u;
        *(uint2*)(smc + HIST_HI + wo) = make_uint2(hw0, hw1);
        *(uint2*)(smc + HIST_LO + wo) = make_uint2(lw0, lw1);
    }
}

__global__ __launch_bounds__(NT, 2)
void din_kernel(const float* __restrict__ hist,
                const float* __restrict__ tgt,
                const int*   __restrict__ mask,
                const float* __restrict__ W0,
                const float* __restrict__ b0,
                const float* __restrict__ W1,
                const float* __restrict__ b1,
                const float* __restrict__ W2,
                const float* __restrict__ b2,
                float* __restrict__ out)
{
    extern __shared__ char smc[];
    float* tgtS    = (float*)(smc + OFF_TGT);
    float* c0s     = (float*)(smc + OFF_C0);
    float* b1s     = (float*)(smc + OFF_B1);
    float* w2s     = (float*)(smc + OFF_W2);
    float* scoreSA = (float*)(smc + OFF_SC);
    float* scoreSB = (float*)(smc + OFF_SC2);
    float* attnS   = (float*)(smc + OFF_ATTN);
    float* redS    = (float*)(smc + OFF_RED);
    float* partS   = (float*)(smc + OFF_PART);

    const int b    = blockIdx.x;
    const int tid  = threadIdx.x;
    const int wid  = tid >> 5;
    const int lane = tid & 31;
    const int mwid = (wid < 7) ? wid : wid - 7;   // m-tile index 0..6
    const int nh   = (wid < 7) ? 0 : 1;           // n-half
    const uint32_t smem_base = smem_u32(smc);
    const float4* hb = (const float4*)(hist + (size_t)b * LL * DD);

    if (tid < DD) tgtS[tid] = tgt[(size_t)b * DD + tid];
    __syncthreads();

    // ---- prologue: A0t build (uint2 stores) + c0 + small vectors + chunk0 staging ----
    for (int w = tid; w < H0N * 32; w += NT) {
        int n   = w % H0N;
        int kp2 = (w / H0N) * 2;
        int d   = kp2 * 2;
        float v0 = W0[d * H0N + n] + W0[(2 * DD + d) * H0N + n] + tgtS[d] * W0[(3 * DD + d) * H0N + n];
        float v1 = W0[(d + 1) * H0N + n] + W0[(2 * DD + d + 1) * H0N + n] + tgtS[d + 1] * W0[(3 * DD + d + 1) * H0N + n];
        float v2 = W0[(d + 2) * H0N + n] + W0[(2 * DD + d + 2) * H0N + n] + tgtS[d + 2] * W0[(3 * DD + d + 2) * H0N + n];
        float v3 = W0[(d + 3) * H0N + n] + W0[(2 * DD + d + 3) * H0N + n] + tgtS[d + 3] * W0[(3 * DD + d + 3) * H0N + n];
        uint32_t hw0, lw0, hw1, lw1;
        split2(v0, v1, hw0, lw0);
        split2(v2, v3, hw1, lw1);
        uint32_t wo = (uint32_t)(n * S_HIST + kp2) * 4u;
        *(uint2*)(smc + A0T_HI + wo) = make_uint2(hw0, hw1);
        *(uint2*)(smc + A0T_LO + wo) = make_uint2(lw0, lw1);
    }
    if (tid < H0N) {
        float s0 = 0.f, s1 = 0.f;
        #pragma unroll 4
        for (int d = 0; d < DD; d += 2) {
            s0 = fmaf(tgtS[d],     W0[(DD + d) * H0N + tid]     - W0[(2 * DD + d) * H0N + tid],     s0);
            s1 = fmaf(tgtS[d + 1], W0[(DD + d + 1) * H0N + tid] - W0[(2 * DD + d + 1) * H0N + tid], s1);
        }
        c0s[tid] = b0[tid] + s0 + s1;
    }
    if (tid < H1N) { b1s[tid] = b1[tid]; w2s[tid] = W2[tid]; }
    stage_chunk(smc, hb, 0, tid);
    __syncthreads();

    // ldmatrix lane geometry
    const int rA = lane & 15;
    const int kA = (lane & 16) ? 4 : 0;
    const int rB = (lane & 7) | ((lane & 16) >> 1);
    const int kB = (lane & 8) ? 4 : 0;
    const int rB2 = lane & 7;                    // x2 geometry
    const int kB2 = (lane & 8) ? 4 : 0;
    const int mb = mwid * 16;

    #pragma unroll 1
    for (int c = 0; c < 2; ++c) {
        // ===== GEMM0: h0 = relu(hist @ A0t^T + c0); warp = (m-tile, 40-col n-half) =====
        {
            float C0[5][4];
            #pragma unroll
            for (int n = 0; n < 5; ++n)
                #pragma unroll
                for (int j = 0; j < 4; ++j) C0[n][j] = 0.f;

            const uint32_t aHiAdr = smem_base + HIST_HI + (uint32_t)((mb + rA) * S_HIST + kA) * 4u;
            const uint32_t aLoAdr = smem_base + HIST_LO + (uint32_t)((mb + rA) * S_HIST + kA) * 4u;
            const int nrow0 = nh * 40;
            const uint32_t bHiAdr  = smem_base + A0T_HI + (uint32_t)((nrow0 + rB) * S_HIST + kB) * 4u;
            const uint32_t bLoAdr  = smem_base + A0T_LO + (uint32_t)((nrow0 + rB) * S_HIST + kB) * 4u;
            const uint32_t bHiAdr2 = smem_base + A0T_HI + (uint32_t)((nrow0 + 32 + rB2) * S_HIST + kB2) * 4u;
            const uint32_t bLoAdr2 = smem_base + A0T_LO + (uint32_t)((nrow0 + 32 + rB2) * S_HIST + kB2) * 4u;

            #pragma unroll
            for (int ks = 0; ks < 8; ++ks) {
                const uint32_t ko = (uint32_t)(ks * 8) * 4u;
                uint32_t bHi[5][2], bLo[5][2], aHi[4], aLo[4];
                #pragma unroll
                for (int p = 0; p < 2; ++p) {
                    const uint32_t po = (uint32_t)(p * 16 * S_HIST) * 4u + ko;
                    LDSM4(bHi[2*p][0], bHi[2*p][1], bHi[2*p+1][0], bHi[2*p+1][1], bHiAdr + po);
                    LDSM4(bLo[2*p][0], bLo[2*p][1], bLo[2*p+1][0], bLo[2*p+1][1], bLoAdr + po);
                }
                LDSM2(bHi[4][0], bHi[4][1], bHiAdr2 + ko);
                LDSM2(bLo[4][0], bLo[4][1], bLoAdr2 + ko);
                LDSM4(aHi[0], aHi[1], aHi[2], aHi[3], aHiAdr + ko);
                LDSM4(aLo[0], aLo[1], aLo[2], aLo[3], aLoAdr + ko);
                #pragma unroll
                for (int n = 0; n < 5; ++n) MMA16816(C0[n], aHi, bHi[n]);
                #pragma unroll
                for (int n = 0; n < 5; ++n) MMA16816(C0[n], aHi, bLo[n]);
                #pragma unroll
                for (int n = 0; n < 5; ++n) MMA16816(C0[n], aLo, bHi[n]);
            }
            __syncthreads();   // hist reads done; X region can be overwritten

            // epilogue: bias+relu+split -> H0 (alias X); rebuild W1T (uint2, FULL K)
            const int row = mb + (lane >> 2);
            #pragma unroll
            for (int nt = 0; nt < 5; ++nt) {
                const int g   = nh * 5 + nt;
                const int col = g * 8 + (lane & 3) * 2;
                uint32_t hw, lw;
                float v0 = fmaxf(C0[nt][0] + c0s[col],     0.f);
                float v1 = fmaxf(C0[nt][1] + c0s[col + 1], 0.f);
                split2(v0, v1, hw, lw);
                uint32_t wo = (uint32_t)(row * S_H0 + g * 4 + (lane & 3)) * 4u;
                *(uint32_t*)(smc + H0_HI + wo) = hw;
                *(uint32_t*)(smc + H0_LO + wo) = lw;
                v0 = fmaxf(C0[nt][2] + c0s[col],     0.f);
                v1 = fmaxf(C0[nt][3] + c0s[col + 1], 0.f);
                split2(v0, v1, hw, lw);
                wo = (uint32_t)((row + 8) * S_H0 + g * 4 + (lane & 3)) * 4u;
                *(uint32_t*)(smc + H0_HI + wo) = hw;
                *(uint32_t*)(smc + H0_LO + wo) = lw;
            }
            for (int w = tid; w < H1N * 20; w += NT) {   // kp2 0..38: all 40 words (K=80)
                int n   = w % H1N;
                int kp2 = (w / H1N) * 2;
                int k   = kp2 * 2;
                uint32_t hw0, lw0, hw1, lw1;
                split2(W1[k * H1N + n],       W1[(k + 1) * H1N + n], hw0, lw0);
                split2(W1[(k + 2) * H1N + n], W1[(k + 3) * H1N + n], hw1, lw1);
                uint32_t wo = (uint32_t)(n * S_W1 + kp2) * 4u;
                *(uint2*)(smc + W1T_HI + wo) = make_uint2(hw0, hw1);
                *(uint2*)(smc + W1T_LO + wo) = make_uint2(lw0, lw1);
            }
        }
        __syncthreads();

        // ===== GEMM1 + layer2 (ALL 14 warps; n-split: nh0 = tiles 0-2, nh1 = tiles 3-4) =====
        {
            const int NTL = (nh == 0) ? 3 : 2;     // n-tiles this warp
            float C1[3][4];
            #pragma unroll
            for (int n = 0; n < 3; ++n)
                #pragma unroll
                for (int j = 0; j < 4; ++j) C1[n][j] = 0.f;

            const uint32_t aHiAdr = smem_base + H0_HI + (uint32_t)((mb + rA) * S_H0 + kA) * 4u;
            const uint32_t aLoAdr = smem_base + H0_LO + (uint32_t)((mb + rA) * S_H0 + kA) * 4u;
            // nh0: rows 0-15 (LDSM4) + rows 16-23 (LDSM2); nh1: rows 24-39 (LDSM4)
            const int brow = (nh == 0) ? 0 : 24;
            const uint32_t bHiAdr  = smem_base + W1T_HI + (uint32_t)((brow + rB) * S_W1 + kB) * 4u;
            const uint32_t bLoAdr  = smem_base + W1T_LO + (uint32_t)((brow + rB) * S_W1 + kB) * 4u;
            const uint32_t bHiAdr2 = smem_base + W1T_HI + (uint32_t)((16 + rB2) * S_W1 + kB2) * 4u;
            const uint32_t bLoAdr2 = smem_base + W1T_LO + (uint32_t)((16 + rB2) * S_W1 + kB2) * 4u;

            #pragma unroll
            for (int ks = 0; ks < 5; ++ks) {
                const uint32_t ko = (uint32_t)(ks * 8) * 4u;
                uint32_t bHi[3][2], bLo[3][2], aHi[4], aLo[4];
                LDSM4(bHi[0][0], bHi[0][1], bHi[1][0], bHi[1][1], bHiAdr + ko);
                LDSM4(bLo[0][0], bLo[0][1], bLo[1][0], bLo[1][1], bLoAdr + ko);
                if (nh == 0) {
                    LDSM2(bHi[2][0], bHi[2][1], bHiAdr2 + ko);
                    LDSM2(bLo[2][0], bLo[2][1], bLoAdr2 + ko);
                }
                LDSM4(aHi[0], aHi[1], aHi[2], aHi[3], aHiAdr + ko);
                LDSM4(aLo[0], aLo[1], aLo[2], aLo[3], aLoAdr + ko);
                #pragma unroll
                for (int n = 0; n < 3; ++n) if (n < NTL) MMA16816(C1[n], aHi, bHi[n]);
                #pragma unroll
                for (int n = 0; n < 3; ++n) if (n < NTL) MMA16816(C1[n], aHi, bLo[n]);
                #pragma unroll
                for (int n = 0; n < 3; ++n) if (n < NTL) MMA16816(C1[n], aLo, bHi[n]);
            }

            float p0 = (nh == 0) ? b2[0] : 0.f;
            float p1 = (nh == 0) ? b2[0] : 0.f;
            #pragma unroll
            for (int nt = 0; nt < 3; ++nt) {
                if (nt < NTL) {
                    const int col = (nh * 3 + nt) * 8 + (lane & 3) * 2;
                    p0 += fmaxf(C1[nt][0] + b1s[col],     0.f) * w2s[col]
                        + fmaxf(C1[nt][1] + b1s[col + 1], 0.f) * w2s[col + 1];
                    p1 += fmaxf(C1[nt][2] + b1s[col],     0.f) * w2s[col]
                        + fmaxf(C1[nt][3] + b1s[col + 1], 0.f) * w2s[col + 1];
                }
            }
            p0 += __shfl_xor_sync(0xffffffffu, p0, 1);
            p0 += __shfl_xor_sync(0xffffffffu, p0, 2);
            p1 += __shfl_xor_sync(0xffffffffu, p1, 1);
            p1 += __shfl_xor_sync(0xffffffffu, p1, 2);
            if ((lane & 3) == 0) {
                const int row = mb + (lane >> 2);
                float* sc = (nh == 0) ? scoreSA : scoreSB;
                sc[c * ROWS + row]     = p0;
                sc[c * ROWS + row + 8] = p1;
            }
        }

        if (c == 0) {
            __syncthreads();              // GEMM1 reads of X done
            stage_chunk(smc, hb, 1, tid); // overwrite X with chunk1 hist
            __syncthreads();
        }
    }
    __syncthreads();

    // ---- masked softmax over L (14 warps) ----
    float logit = -3.402823466e38f;
    if (tid < LL) {
        float m = (float)mask[(size_t)b * LL + tid];
        logit = scoreSA[tid] + scoreSB[tid] + (1.0f - m) * (-1e9f);
    }
    {
        float v = logit;
        #pragma unroll
        for (int o = 16; o; o >>= 1) v = fmaxf(v, __shfl_xor_sync(0xffffffffu, v, o));
        if (lane == 0) redS[wid] = v;
    }
    __syncthreads();
    if (tid < 32) {
        float m = (tid < 14) ? redS[tid] : -3.402823466e38f;
        #pragma unroll
        for (int o = 8; o; o >>= 1) m = fmaxf(m, __shfl_xor_sync(0xffffffffu, m, o));
        if (tid == 0) redS[16] = m;
    }
    __syncthreads();
    const float M = redS[16];
    float e = (tid < LL) ? expf(logit - M) : 0.f;
    {
        float s = e;
        #pragma unroll
        for (int o = 16; o; o >>= 1) s += __shfl_xor_sync(0xffffffffu, s, o);
        if (lane == 0) redS[wid] = s;
    }
    __syncthreads();
    if (tid < 32) {
        float s = (tid < 14) ? redS[tid] : 0.f;
        #pragma unroll
        for (int o = 8; o; o >>= 1) s += __shfl_xor_sync(0xffffffffu, s, o);
        if (tid == 0) redS[17] = s;
    }
    __syncthreads();
    const float S = redS[17];
    if (tid < LL) {
        float a = e / S;
        attnS[tid] = a;
        out[(size_t)BB * DD + (size_t)b * LL + tid] = a;
    }
    __syncthreads();

    // ---- user_interest[b][d] = sum_l attn[l]*hist[l][d]  (gmem fp32, L2-hot) ----
    {
        const float* hbf = hist + (size_t)b * LL * DD;
        for (int i = tid; i < 512; i += NT) {
            const int d = i & 127;
            const int g = i >> 7;
            float s = 0.f;
            #pragma unroll 2
            for (int l = g * 50; l < g * 50 + 50; ++l)
                s = fmaf(attnS[l], hbf[l * DD + d], s);
            partS[g * 128 + d] = s;
        }
    }
    __syncthreads();
    if (tid < DD)
        out[(size_t)b * DD + tid] = partS[tid] + partS[128 + tid] + partS[256 + tid] + partS[384 + tid];
}

extern "C" void kernel_launch(void* const* d_in, const int* in_sizes, int n_in,
                              void* d_out, int out_size)
{
    const float* hist = (const float*)d_in[0];
    const float* tgt  = (const float*)d_in[1];
    const int*   mask = (const int*)  d_in[2];
    const float* W0   = (const float*)d_in[3];
    const float* b0   = (const float*)d_in[4];
    const float* W1   = (const float*)d_in[5];
    const float* b1   = (const float*)d_in[6];
    const float* W2   = (const float*)d_in[7];
    const float* b2   = (const float*)d_in[8];
    float* out = (float*)d_out;

    static int smem_set = 0;
    if (!smem_set) {
        cudaFuncSetAttribute(din_kernel,
                             cudaFuncAttributeMaxDynamicSharedMemorySize,
                             SMEM_BYTES);
        smem_set = 1;
    }
    din_kernel<<<BB, NT, SMEM_BYTES>>>(hist, tgt, mask, W0, b0, W1, b1, W2, b2, out);
}

// round 11
// speedup vs baseline: 2.8359x; 1.1177x over previous
#include <cuda_runtime.h>
#include <cuda_fp16.h>
#include <cstdint>
#include <math.h>

#define BB 2048
#define LL 200
#define DD 128
#define H0N 80
#define H1N 40
#define NT 448            // 14 warps: (m-tile w%7) x (n-half w/7); 2 CTAs/SM
#define ROWS 112          // L-rows per chunk (2 chunks)

// word strides (conflict-free ldmatrix; stride ≡ 4 mod 32)
#define S_HIST 68
#define S_H0   44
#define S_W1   44

// ---- smem byte offsets ----
#define HIST_HI 0
#define HIST_LO (ROWS*S_HIST*4)          // 30464
#define H0_HI   0                         // alias (hist dead after GEMM0 mainloop)
#define H0_LO   (ROWS*S_H0*4)             // 19712
#define W1T_HI  (2*ROWS*S_H0*4)           // 39424 (ends 46464)
#define A0T_HI  (2*ROWS*S_HIST*4)         // 60928 (ends 82688)
#define MISC    82688
#define OFF_TGT  (MISC + 0)       // 128 f
#define OFF_C0   (MISC + 512)     // 80 f
#define OFF_B1   (MISC + 896)     // 40 f
#define OFF_W2   (MISC + 1088)    // 40 f
#define OFF_SC   (MISC + 1280)    // 224 f (nh0 partial)
#define OFF_SC2  (MISC + 2176)    // 224 f (nh1 partial)
#define OFF_ATTN (MISC + 3072)    // 224 f
#define OFF_RED  (MISC + 3968)    // 32 f
#define OFF_PART (MISC + 4096)    // 512 f
#define SMEM_BYTES (MISC + 6144)  // 88,832 B -> 2 CTAs/SM

#define LDSM4(r0, r1, r2, r3, addr) asm volatile( \
    "ldmatrix.sync.aligned.m8n8.x4.shared.b16 {%0,%1,%2,%3}, [%4];" \
    : "=r"(r0), "=r"(r1), "=r"(r2), "=r"(r3) : "r"(addr))

#define LDSM2(r0, r1, addr) asm volatile( \
    "ldmatrix.sync.aligned.m8n8.x2.shared.b16 {%0,%1}, [%2];" \
    : "=r"(r0), "=r"(r1) : "r"(addr))

#define MMA16816(c, a, bfr) asm volatile( \
    "mma.sync.aligned.m16n8k16.row.col.f32.f16.f16.f32 " \
    "{%0,%1,%2,%3}, {%4,%5,%6,%7}, {%8,%9}, {%0,%1,%2,%3};" \
    : "+f"((c)[0]), "+f"((c)[1]), "+f"((c)[2]), "+f"((c)[3]) \
    : "r"((a)[0]), "r"((a)[1]), "r"((a)[2]), "r"((a)[3]), \
      "r"((bfr)[0]), "r"((bfr)[1]))

__device__ __forceinline__ uint32_t smem_u32(const void* p) {
    uint32_t a;
    asm("{ .reg .u64 t; cvta.to.shared.u64 t, %1; cvt.u32.u64 %0, t; }" : "=r"(a) : "l"(p));
    return a;
}

// split fp32 pair -> packed fp16x2 hi word + lo word
__device__ __forceinline__ void split2h(float a, float b, uint32_t& hiw, uint32_t& low) {
    __half ah = __float2half_rn(a);
    __half bh = __float2half_rn(b);
    __half al = __float2half_rn(a - __half2float(ah));
    __half bl = __float2half_rn(b - __half2float(bh));
    hiw = (uint32_t)__half_as_ushort(ah) | ((uint32_t)__half_as_ushort(bh) << 16);
    low = (uint32_t)__half_as_ushort(al) | ((uint32_t)__half_as_ushort(bl) << 16);
}
// truncate fp32 pair -> packed fp16x2 word
__device__ __forceinline__ uint32_t pack2h(float a, float b) {
    return (uint32_t)__half_as_ushort(__float2half_rn(a)) |
           ((uint32_t)__half_as_ushort(__float2half_rn(b)) << 16);
}

// stage one 112-row chunk of hist as fp16 hi/lo (rows past L zeroed); STS.64
__device__ __forceinline__ void stage_chunk(char* smc, const float4* hb, int c, int tid) {
    for (int idx = tid; idx < ROWS * 32; idx += NT) {
        int r = idx >> 5;
        int q = idx & 31;
        int gl = c * ROWS + r;
        float4 v = make_float4(0.f, 0.f, 0.f, 0.f);
        if (gl < LL) v = hb[gl * 32 + q];
        uint32_t hw0, lw0, hw1, lw1;
        split2h(v.x, v.y, hw0, lw0);
        split2h(v.z, v.w, hw1, lw1);
        uint32_t wo = (uint32_t)(r * S_HIST + q * 2) * 4u;
        *(uint2*)(smc + HIST_HI + wo) = make_uint2(hw0, hw1);
        *(uint2*)(smc + HIST_LO + wo) = make_uint2(lw0, lw1);
    }
}

__global__ __launch_bounds__(NT, 2)
void din_kernel(const float* __restrict__ hist,
                const float* __restrict__ tgt,
                const int*   __restrict__ mask,
                const float* __restrict__ W0,
                const float* __restrict__ b0,
                const float* __restrict__ W1,
                const float* __restrict__ b1,
                const float* __restrict__ W2,
                const float* __restrict__ b2,
                float* __restrict__ out)
{
    extern __shared__ char smc[];
    float* tgtS    = (float*)(smc + OFF_TGT);
    float* c0s     = (float*)(smc + OFF_C0);
    float* b1s     = (float*)(smc + OFF_B1);
    float* w2s     = (float*)(smc + OFF_W2);
    float* scoreSA = (float*)(smc + OFF_SC);
    float* scoreSB = (float*)(smc + OFF_SC2);
    float* attnS   = (float*)(smc + OFF_ATTN);
    float* redS    = (float*)(smc + OFF_RED);
    float* partS   = (float*)(smc + OFF_PART);

    const int b    = blockIdx.x;
    const int tid  = threadIdx.x;
    const int wid  = tid >> 5;
    const int lane = tid & 31;
    const int mwid = (wid < 7) ? wid : wid - 7;   // m-tile index 0..6
    const int nh   = (wid < 7) ? 0 : 1;           // n-half
    const uint32_t smem_base = smem_u32(smc);
    const float4* hb = (const float4*)(hist + (size_t)b * LL * DD);

    if (tid < DD) tgtS[tid] = tgt[(size_t)b * DD + tid];
    __syncthreads();

    // ---- prologue: A0t build (fp16 single, uint2 stores) + c0 + small vectors + chunk0 ----
    for (int w = tid; w < H0N * 32; w += NT) {
        int n   = w % H0N;
        int kp2 = (w / H0N) * 2;
        int d   = kp2 * 2;
        float v0 = W0[d * H0N + n] + W0[(2 * DD + d) * H0N + n] + tgtS[d] * W0[(3 * DD + d) * H0N + n];
        float v1 = W0[(d + 1) * H0N + n] + W0[(2 * DD + d + 1) * H0N + n] + tgtS[d + 1] * W0[(3 * DD + d + 1) * H0N + n];
        float v2 = W0[(d + 2) * H0N + n] + W0[(2 * DD + d + 2) * H0N + n] + tgtS[d + 2] * W0[(3 * DD + d + 2) * H0N + n];
        float v3 = W0[(d + 3) * H0N + n] + W0[(2 * DD + d + 3) * H0N + n] + tgtS[d + 3] * W0[(3 * DD + d + 3) * H0N + n];
        uint32_t wo = (uint32_t)(n * S_HIST + kp2) * 4u;
        *(uint2*)(smc + A0T_HI + wo) = make_uint2(pack2h(v0, v1), pack2h(v2, v3));
    }
    if (tid < H0N) {
        float s0 = 0.f, s1 = 0.f;
        #pragma unroll 4
        for (int d = 0; d < DD; d += 2) {
            s0 = fmaf(tgtS[d],     W0[(DD + d) * H0N + tid]     - W0[(2 * DD + d) * H0N + tid],     s0);
            s1 = fmaf(tgtS[d + 1], W0[(DD + d + 1) * H0N + tid] - W0[(2 * DD + d + 1) * H0N + tid], s1);
        }
        c0s[tid] = b0[tid] + s0 + s1;
    }
    if (tid < H1N) { b1s[tid] = b1[tid]; w2s[tid] = W2[tid]; }
    stage_chunk(smc, hb, 0, tid);
    __syncthreads();

    // ldmatrix lane geometry
    const int rA = lane & 15;
    const int kA = (lane & 16) ? 4 : 0;
    const int rB = (lane & 7) | ((lane & 16) >> 1);
    const int kB = (lane & 8) ? 4 : 0;
    const int rB2 = lane & 7;                    // x2 geometry
    const int kB2 = (lane & 8) ? 4 : 0;
    const int mb = mwid * 16;

    #pragma unroll 1
    for (int c = 0; c < 2; ++c) {
        // ===== GEMM0: h0 = relu(hist @ A0t^T + c0); fp16 2-term (aHi·b + aLo·b) =====
        {
            float C0[5][4];
            #pragma unroll
            for (int n = 0; n < 5; ++n)
                #pragma unroll
                for (int j = 0; j < 4; ++j) C0[n][j] = 0.f;

            const uint32_t aHiAdr = smem_base + HIST_HI + (uint32_t)((mb + rA) * S_HIST + kA) * 4u;
            const uint32_t aLoAdr = smem_base + HIST_LO + (uint32_t)((mb + rA) * S_HIST + kA) * 4u;
            const int nrow0 = nh * 40;
            const uint32_t bAdr  = smem_base + A0T_HI + (uint32_t)((nrow0 + rB) * S_HIST + kB) * 4u;
            const uint32_t bAdr2 = smem_base + A0T_HI + (uint32_t)((nrow0 + 32 + rB2) * S_HIST + kB2) * 4u;

            #pragma unroll
            for (int ks = 0; ks < 8; ++ks) {
                const uint32_t ko = (uint32_t)(ks * 8) * 4u;
                uint32_t bf[5][2], aHi[4], aLo[4];
                #pragma unroll
                for (int p = 0; p < 2; ++p) {
                    const uint32_t po = (uint32_t)(p * 16 * S_HIST) * 4u + ko;
                    LDSM4(bf[2*p][0], bf[2*p][1], bf[2*p+1][0], bf[2*p+1][1], bAdr + po);
                }
                LDSM2(bf[4][0], bf[4][1], bAdr2 + ko);
                LDSM4(aHi[0], aHi[1], aHi[2], aHi[3], aHiAdr + ko);
                LDSM4(aLo[0], aLo[1], aLo[2], aLo[3], aLoAdr + ko);
                #pragma unroll
                for (int n = 0; n < 5; ++n) MMA16816(C0[n], aHi, bf[n]);
                #pragma unroll
                for (int n = 0; n < 5; ++n) MMA16816(C0[n], aLo, bf[n]);
            }
            __syncthreads();   // hist reads done; X region can be overwritten

            // epilogue: bias+relu+split(fp16) -> H0 (alias X); rebuild W1T (fp16 single)
            const int row = mb + (lane >> 2);
            #pragma unroll
            for (int nt = 0; nt < 5; ++nt) {
                const int g   = nh * 5 + nt;
                const int col = g * 8 + (lane & 3) * 2;
                uint32_t hw, lw;
                float v0 = fmaxf(C0[nt][0] + c0s[col],     0.f);
                float v1 = fmaxf(C0[nt][1] + c0s[col + 1], 0.f);
                split2h(v0, v1, hw, lw);
                uint32_t wo = (uint32_t)(row * S_H0 + g * 4 + (lane & 3)) * 4u;
                *(uint32_t*)(smc + H0_HI + wo) = hw;
                *(uint32_t*)(smc + H0_LO + wo) = lw;
                v0 = fmaxf(C0[nt][2] + c0s[col],     0.f);
                v1 = fmaxf(C0[nt][3] + c0s[col + 1], 0.f);
                split2h(v0, v1, hw, lw);
                wo = (uint32_t)((row + 8) * S_H0 + g * 4 + (lane & 3)) * 4u;
                *(uint32_t*)(smc + H0_HI + wo) = hw;
                *(uint32_t*)(smc + H0_LO + wo) = lw;
            }
            for (int w = tid; w < H1N * 20; w += NT) {   // kp2 0..38: all 40 words (K=80)
                int n   = w % H1N;
                int kp2 = (w / H1N) * 2;
                int k   = kp2 * 2;
                uint32_t wo = (uint32_t)(n * S_W1 + kp2) * 4u;
                *(uint2*)(smc + W1T_HI + wo) =
                    make_uint2(pack2h(W1[k * H1N + n],       W1[(k + 1) * H1N + n]),
                               pack2h(W1[(k + 2) * H1N + n], W1[(k + 3) * H1N + n]));
            }
        }
        __syncthreads();

        // ===== GEMM1 + layer2 (14 warps; n-split: nh0 = tiles 0-2, nh1 = tiles 3-4) =====
        {
            const int NTL = (nh == 0) ? 3 : 2;     // n-tiles this warp
            float C1[3][4];
            #pragma unroll
            for (int n = 0; n < 3; ++n)
                #pragma unroll
                for (int j = 0; j < 4; ++j) C1[n][j] = 0.f;

            const uint32_t aHiAdr = smem_base + H0_HI + (uint32_t)((mb + rA) * S_H0 + kA) * 4u;
            const uint32_t aLoAdr = smem_base + H0_LO + (uint32_t)((mb + rA) * S_H0 + kA) * 4u;
            const int brow = (nh == 0) ? 0 : 24;
            const uint32_t bAdr  = smem_base + W1T_HI + (uint32_t)((brow + rB) * S_W1 + kB) * 4u;
            const uint32_t bAdr2 = smem_base + W1T_HI + (uint32_t)((16 + rB2) * S_W1 + kB2) * 4u;

            #pragma unroll
            for (int ks = 0; ks < 5; ++ks) {
                const uint32_t ko = (uint32_t)(ks * 8) * 4u;
                uint32_t bf[3][2], aHi[4], aLo[4];
                LDSM4(bf[0][0], bf[0][1], bf[1][0], bf[1][1], bAdr + ko);
                if (nh == 0) LDSM2(bf[2][0], bf[2][1], bAdr2 + ko);
                LDSM4(aHi[0], aHi[1], aHi[2], aHi[3], aHiAdr + ko);
                LDSM4(aLo[0], aLo[1], aLo[2], aLo[3], aLoAdr + ko);
                #pragma unroll
                for (int n = 0; n < 3; ++n) if (n < NTL) MMA16816(C1[n], aHi, bf[n]);
                #pragma unroll
                for (int n = 0; n < 3; ++n) if (n < NTL) MMA16816(C1[n], aLo, bf[n]);
            }

            float p0 = (nh == 0) ? b2[0] : 0.f;
            float p1 = (nh == 0) ? b2[0] : 0.f;
            #pragma unroll
            for (int nt = 0; nt < 3; ++nt) {
                if (nt < NTL) {
                    const int col = (nh * 3 + nt) * 8 + (lane & 3) * 2;
                    p0 += fmaxf(C1[nt][0] + b1s[col],     0.f) * w2s[col]
                        + fmaxf(C1[nt][1] + b1s[col + 1], 0.f) * w2s[col + 1];
                    p1 += fmaxf(C1[nt][2] + b1s[col],     0.f) * w2s[col]
                        + fmaxf(C1[nt][3] + b1s[col + 1], 0.f) * w2s[col + 1];
                }
            }
            p0 += __shfl_xor_sync(0xffffffffu, p0, 1);
            p0 += __shfl_xor_sync(0xffffffffu, p0, 2);
            p1 += __shfl_xor_sync(0xffffffffu, p1, 1);
            p1 += __shfl_xor_sync(0xffffffffu, p1, 2);
            if ((lane & 3) == 0) {
                const int row = mb + (lane >> 2);
                float* sc = (nh == 0) ? scoreSA : scoreSB;
                sc[c * ROWS + row]     = p0;
                sc[c * ROWS + row + 8] = p1;
            }
        }

        if (c == 0) {
            __syncthreads();              // GEMM1 reads of X done
            stage_chunk(smc, hb, 1, tid); // overwrite X with chunk1 hist
            __syncthreads();
        }
    }
    __syncthreads();

    // ---- masked softmax over L (14 warps) ----
    float logit = -3.402823466e38f;
    if (tid < LL) {
        float m = (float)mask[(size_t)b * LL + tid];
        logit = scoreSA[tid] + scoreSB[tid] + (1.0f - m) * (-1e9f);
    }
    {
        float v = logit;
        #pragma unroll
        for (int o = 16; o; o >>= 1) v = fmaxf(v, __shfl_xor_sync(0xffffffffu, v, o));
        if (lane == 0) redS[wid] = v;
    }
    __syncthreads();
    if (tid < 32) {
        float m = (tid < 14) ? redS[tid] : -3.402823466e38f;
        #pragma unroll
        for (int o = 8; o; o >>= 1) m = fmaxf(m, __shfl_xor_sync(0xffffffffu, m, o));
        if (tid == 0) redS[16] = m;
    }
    __syncthreads();
    const float M = redS[16];
    float e = (tid < LL) ? expf(logit - M) : 0.f;
    {
        float s = e;
        #pragma unroll
        for (int o = 16; o; o >>= 1) s += __shfl_xor_sync(0xffffffffu, s, o);
        if (lane == 0) redS[wid] = s;
    }
    __syncthreads();
    if (tid < 32) {
        float s = (tid < 14) ? redS[tid] : 0.f;
        #pragma unroll
        for (int o = 8; o; o >>= 1) s += __shfl_xor_sync(0xffffffffu, s, o);
        if (tid == 0) redS[17] = s;
    }
    __syncthreads();
    const float S = redS[17];
    if (tid < LL) {
        float a = e / S;
        attnS[tid] = a;
        out[(size_t)BB * DD + (size_t)b * LL + tid] = a;
    }
    __syncthreads();

    // ---- user_interest[b][d] = sum_l attn[l]*hist[l][d]  (gmem fp32, L2-hot) ----
    {
        const float* hbf = hist + (size_t)b * LL * DD;
        for (int i = tid; i < 512; i += NT) {
            const int d = i & 127;
            const int g = i >> 7;
            float s = 0.f;
            #pragma unroll 2
            for (int l = g * 50; l < g * 50 + 50; ++l)
                s = fmaf(attnS[l], hbf[l * DD + d], s);
            partS[g * 128 + d] = s;
        }
    }
    __syncthreads();
    if (tid < DD)
        out[(size_t)b * DD + tid] = partS[tid] + partS[128 + tid] + partS[256 + tid] + partS[384 + tid];
}

extern "C" void kernel_launch(void* const* d_in, const int* in_sizes, int n_in,
                              void* d_out, int out_size)
{
    const float* hist = (const float*)d_in[0];
    const float* tgt  = (const float*)d_in[1];
    const int*   mask = (const int*)  d_in[2];
    const float* W0   = (const float*)d_in[3];
    const float* b0   = (const float*)d_in[4];
    const float* W1   = (const float*)d_in[5];
    const float* b1   = (const float*)d_in[6];
    const float* W2   = (const float*)d_in[7];
    const float* b2   = (const float*)d_in[8];
    float* out = (float*)d_out;

    static int smem_set = 0;
    if (!smem_set) {
        cudaFuncSetAttribute(din_kernel,
                             cudaFuncAttributeMaxDynamicSharedMemorySize,
                             SMEM_BYTES);
        smem_set = 1;
    }
    din_kernel<<<BB, NT, SMEM_BYTES>>>(hist, tgt, mask, W0, b0, W1, b1, W2, b2, out);
}

// round 12
// speedup vs baseline: 3.4144x; 1.2040x over previous
#include <cuda_runtime.h>
#include <cuda_fp16.h>
#include <cstdint>
#include <math.h>

#define BB 2048
#define LL 200
#define DD 128
#define H0N 80
#define H1N 40
#define NT 320            // 10 warps: (m-tile w%5) x (n-half w/5); 3 CTAs/SM
#define ROWS 80           // L-rows per chunk (3 chunks; last has 40 real rows)

// word strides (conflict-free ldmatrix; stride ≡ 4 mod 32)
#define S_HIST 68
#define S_H0   44
#define S_W1   44

// ---- smem byte offsets ----
#define HIST_HI 0
#define HIST_LO (ROWS*S_HIST*4)          // 21760
#define H0_HI   0                         // alias (hist dead after GEMM0 mainloop)
#define H0_LO   (ROWS*S_H0*4)             // 14080
#define W1T_HI  (2*ROWS*S_H0*4)           // 28160 (ends 35200 < 43520)
#define A0T_HI  (2*ROWS*S_HIST*4)         // 43520 (ends 65280)
#define MISC    65280
#define OFF_TGT  (MISC + 0)       // 128 f
#define OFF_C0   (MISC + 512)     // 80 f
#define OFF_B1   (MISC + 896)     // 40 f
#define OFF_W2   (MISC + 1088)    // 40 f
#define OFF_SC   (MISC + 1280)    // 240 f (nh0 partial)
#define OFF_SC2  (MISC + 2240)    // 240 f (nh1 partial)
#define OFF_ATTN (MISC + 3200)    // 240 f (200 used)
#define OFF_RED  (MISC + 4160)    // 32 f
#define OFF_PART (MISC + 4288)    // 512 f
#define SMEM_BYTES (MISC + 6336)  // 71,616 B -> 3 CTAs/SM

#define LDSM4(r0, r1, r2, r3, addr) asm volatile( \
    "ldmatrix.sync.aligned.m8n8.x4.shared.b16 {%0,%1,%2,%3}, [%4];" \
    : "=r"(r0), "=r"(r1), "=r"(r2), "=r"(r3) : "r"(addr))

#define LDSM2(r0, r1, addr) asm volatile( \
    "ldmatrix.sync.aligned.m8n8.x2.shared.b16 {%0,%1}, [%2];" \
    : "=r"(r0), "=r"(r1) : "r"(addr))

#define MMA16816(c, a, bfr) asm volatile( \
    "mma.sync.aligned.m16n8k16.row.col.f32.f16.f16.f32 " \
    "{%0,%1,%2,%3}, {%4,%5,%6,%7}, {%8,%9}, {%0,%1,%2,%3};" \
    : "+f"((c)[0]), "+f"((c)[1]), "+f"((c)[2]), "+f"((c)[3]) \
    : "r"((a)[0]), "r"((a)[1]), "r"((a)[2]), "r"((a)[3]), \
      "r"((bfr)[0]), "r"((bfr)[1]))

__device__ __forceinline__ uint32_t smem_u32(const void* p) {
    uint32_t a;
    asm("{ .reg .u64 t; cvta.to.shared.u64 t, %1; cvt.u32.u64 %0, t; }" : "=r"(a) : "l"(p));
    return a;
}

// split fp32 pair -> packed fp16x2 hi word + lo word
__device__ __forceinline__ void split2h(float a, float b, uint32_t& hiw, uint32_t& low) {
    __half ah = __float2half_rn(a);
    __half bh = __float2half_rn(b);
    __half al = __float2half_rn(a - __half2float(ah));
    __half bl = __float2half_rn(b - __half2float(bh));
    hiw = (uint32_t)__half_as_ushort(ah) | ((uint32_t)__half_as_ushort(bh) << 16);
    low = (uint32_t)__half_as_ushort(al) | ((uint32_t)__half_as_ushort(bl) << 16);
}
// truncate fp32 pair -> packed fp16x2 word
__device__ __forceinline__ uint32_t pack2h(float a, float b) {
    return (uint32_t)__half_as_ushort(__float2half_rn(a)) |
           ((uint32_t)__half_as_ushort(__float2half_rn(b)) << 16);
}

// stage one 80-row chunk of hist as fp16 hi/lo (rows past L zeroed); STS.64
__device__ __forceinline__ void stage_chunk(char* smc, const float4* hb, int c, int tid) {
    for (int idx = tid; idx < ROWS * 32; idx += NT) {
        int r = idx >> 5;
        int q = idx & 31;
        int gl = c * ROWS + r;
        float4 v = make_float4(0.f, 0.f, 0.f, 0.f);
        if (gl < LL) v = hb[gl * 32 + q];
        uint32_t hw0, lw0, hw1, lw1;
        split2h(v.x, v.y, hw0, lw0);
        split2h(v.z, v.w, hw1, lw1);
        uint32_t wo = (uint32_t)(r * S_HIST + q * 2) * 4u;
        *(uint2*)(smc + HIST_HI + wo) = make_uint2(hw0, hw1);
        *(uint2*)(smc + HIST_LO + wo) = make_uint2(lw0, lw1);
    }
}

__global__ __launch_bounds__(NT, 3)
void din_kernel(const float* __restrict__ hist,
                const float* __restrict__ tgt,
                const int*   __restrict__ mask,
                const float* __restrict__ W0,
                const float* __restrict__ b0,
                const float* __restrict__ W1,
                const float* __restrict__ b1,
                const float* __restrict__ W2,
                const float* __restrict__ b2,
                float* __restrict__ out)
{
    extern __shared__ char smc[];
    float* tgtS    = (float*)(smc + OFF_TGT);
    float* c0s     = (float*)(smc + OFF_C0);
    float* b1s     = (float*)(smc + OFF_B1);
    float* w2s     = (float*)(smc + OFF_W2);
    float* scoreSA = (float*)(smc + OFF_SC);
    float* scoreSB = (float*)(smc + OFF_SC2);
    float* attnS   = (float*)(smc + OFF_ATTN);
    float* redS    = (float*)(smc + OFF_RED);
    float* partS   = (float*)(smc + OFF_PART);

    const int b    = blockIdx.x;
    const int tid  = threadIdx.x;
    const int wid  = tid >> 5;
    const int lane = tid & 31;
    const int mwid = (wid < 5) ? wid : wid - 5;   // m-tile index 0..4
    const int nh   = (wid < 5) ? 0 : 1;           // n-half
    const uint32_t smem_base = smem_u32(smc);
    const float4* hb = (const float4*)(hist + (size_t)b * LL * DD);

    if (tid < DD) tgtS[tid] = tgt[(size_t)b * DD + tid];
    __syncthreads();

    // ---- prologue: A0t build (fp16 single, uint2 stores) + c0 + small vectors + chunk0 ----
    for (int w = tid; w < H0N * 32; w += NT) {
        int n   = w % H0N;
        int kp2 = (w / H0N) * 2;
        int d   = kp2 * 2;
        float v0 = W0[d * H0N + n] + W0[(2 * DD + d) * H0N + n] + tgtS[d] * W0[(3 * DD + d) * H0N + n];
        float v1 = W0[(d + 1) * H0N + n] + W0[(2 * DD + d + 1) * H0N + n] + tgtS[d + 1] * W0[(3 * DD + d + 1) * H0N + n];
        float v2 = W0[(d + 2) * H0N + n] + W0[(2 * DD + d + 2) * H0N + n] + tgtS[d + 2] * W0[(3 * DD + d + 2) * H0N + n];
        float v3 = W0[(d + 3) * H0N + n] + W0[(2 * DD + d + 3) * H0N + n] + tgtS[d + 3] * W0[(3 * DD + d + 3) * H0N + n];
        uint32_t wo = (uint32_t)(n * S_HIST + kp2) * 4u;
        *(uint2*)(smc + A0T_HI + wo) = make_uint2(pack2h(v0, v1), pack2h(v2, v3));
    }
    if (tid < H0N) {
        float s0 = 0.f, s1 = 0.f;
        #pragma unroll 4
        for (int d = 0; d < DD; d += 2) {
            s0 = fmaf(tgtS[d],     W0[(DD + d) * H0N + tid]     - W0[(2 * DD + d) * H0N + tid],     s0);
            s1 = fmaf(tgtS[d + 1], W0[(DD + d + 1) * H0N + tid] - W0[(2 * DD + d + 1) * H0N + tid], s1);
        }
        c0s[tid] = b0[tid] + s0 + s1;
    }
    if (tid < H1N) { b1s[tid] = b1[tid]; w2s[tid] = W2[tid]; }
    stage_chunk(smc, hb, 0, tid);
    __syncthreads();

    // ldmatrix lane geometry
    const int rA = lane & 15;
    const int kA = (lane & 16) ? 4 : 0;
    const int rB = (lane & 7) | ((lane & 16) >> 1);
    const int kB = (lane & 8) ? 4 : 0;
    const int rB2 = lane & 7;                    // x2 geometry
    const int kB2 = (lane & 8) ? 4 : 0;
    const int mb = mwid * 16;

    #pragma unroll 1
    for (int c = 0; c < 3; ++c) {
        const int MT = (c < 2) ? 5 : 3;   // active m-tiles this chunk

        // ===== GEMM0: h0 = relu(hist @ A0t^T + c0); fp16 2-term (aHi·b + aLo·b) =====
        {
            float C0[5][4];
            #pragma unroll
            for (int n = 0; n < 5; ++n)
                #pragma unroll
                for (int j = 0; j < 4; ++j) C0[n][j] = 0.f;

            const uint32_t aHiAdr = smem_base + HIST_HI + (uint32_t)((mb + rA) * S_HIST + kA) * 4u;
            const uint32_t aLoAdr = smem_base + HIST_LO + (uint32_t)((mb + rA) * S_HIST + kA) * 4u;
            const int nrow0 = nh * 40;
            const uint32_t bAdr  = smem_base + A0T_HI + (uint32_t)((nrow0 + rB) * S_HIST + kB) * 4u;
            const uint32_t bAdr2 = smem_base + A0T_HI + (uint32_t)((nrow0 + 32 + rB2) * S_HIST + kB2) * 4u;

            if (mwid < MT) {
                #pragma unroll
                for (int ks = 0; ks < 8; ++ks) {
                    const uint32_t ko = (uint32_t)(ks * 8) * 4u;
                    uint32_t bf[5][2], aHi[4], aLo[4];
                    #pragma unroll
                    for (int p = 0; p < 2; ++p) {
                        const uint32_t po = (uint32_t)(p * 16 * S_HIST) * 4u + ko;
                        LDSM4(bf[2*p][0], bf[2*p][1], bf[2*p+1][0], bf[2*p+1][1], bAdr + po);
                    }
                    LDSM2(bf[4][0], bf[4][1], bAdr2 + ko);
                    LDSM4(aHi[0], aHi[1], aHi[2], aHi[3], aHiAdr + ko);
                    LDSM4(aLo[0], aLo[1], aLo[2], aLo[3], aLoAdr + ko);
                    #pragma unroll
                    for (int n = 0; n < 5; ++n) MMA16816(C0[n], aHi, bf[n]);
                    #pragma unroll
                    for (int n = 0; n < 5; ++n) MMA16816(C0[n], aLo, bf[n]);
                }
            }
            __syncthreads();   // hist reads done; X region can be overwritten

            // epilogue: bias+relu+split(fp16) -> H0 (alias X); rebuild W1T (fp16 single)
            if (mwid < MT) {
                const int row = mb + (lane >> 2);
                #pragma unroll
                for (int nt = 0; nt < 5; ++nt) {
                    const int g   = nh * 5 + nt;
                    const int col = g * 8 + (lane & 3) * 2;
                    uint32_t hw, lw;
                    float v0 = fmaxf(C0[nt][0] + c0s[col],     0.f);
                    float v1 = fmaxf(C0[nt][1] + c0s[col + 1], 0.f);
                    split2h(v0, v1, hw, lw);
                    uint32_t wo = (uint32_t)(row * S_H0 + g * 4 + (lane & 3)) * 4u;
                    *(uint32_t*)(smc + H0_HI + wo) = hw;
                    *(uint32_t*)(smc + H0_LO + wo) = lw;
                    v0 = fmaxf(C0[nt][2] + c0s[col],     0.f);
                    v1 = fmaxf(C0[nt][3] + c0s[col + 1], 0.f);
                    split2h(v0, v1, hw, lw);
                    wo = (uint32_t)((row + 8) * S_H0 + g * 4 + (lane & 3)) * 4u;
                    *(uint32_t*)(smc + H0_HI + wo) = hw;
                    *(uint32_t*)(smc + H0_LO + wo) = lw;
                }
            }
            for (int w = tid; w < H1N * 20; w += NT) {   // kp2 0..38: all 40 words (K=80)
                int n   = w % H1N;
                int kp2 = (w / H1N) * 2;
                int k   = kp2 * 2;
                uint32_t wo = (uint32_t)(n * S_W1 + kp2) * 4u;
                *(uint2*)(smc + W1T_HI + wo) =
                    make_uint2(pack2h(W1[k * H1N + n],       W1[(k + 1) * H1N + n]),
                               pack2h(W1[(k + 2) * H1N + n], W1[(k + 3) * H1N + n]));
            }
        }
        __syncthreads();

        // ===== GEMM1 + layer2 (n-split: nh0 = tiles 0-2, nh1 = tiles 3-4) =====
        if (mwid < MT) {
            const int NTL = (nh == 0) ? 3 : 2;     // n-tiles this warp
            float C1[3][4];
            #pragma unroll
            for (int n = 0; n < 3; ++n)
                #pragma unroll
                for (int j = 0; j < 4; ++j) C1[n][j] = 0.f;

            const uint32_t aHiAdr = smem_base + H0_HI + (uint32_t)((mb + rA) * S_H0 + kA) * 4u;
            const uint32_t aLoAdr = smem_base + H0_LO + (uint32_t)((mb + rA) * S_H0 + kA) * 4u;
            const int brow = (nh == 0) ? 0 : 24;
            const uint32_t bAdr  = smem_base + W1T_HI + (uint32_t)((brow + rB) * S_W1 + kB) * 4u;
            const uint32_t bAdr2 = smem_base + W1T_HI + (uint32_t)((16 + rB2) * S_W1 + kB2) * 4u;

            #pragma unroll
            for (int ks = 0; ks < 5; ++ks) {
                const uint32_t ko = (uint32_t)(ks * 8) * 4u;
                uint32_t bf[3][2], aHi[4], aLo[4];
                LDSM4(bf[0][0], bf[0][1], bf[1][0], bf[1][1], bAdr + ko);
                if (nh == 0) LDSM2(bf[2][0], bf[2][1], bAdr2 + ko);
                LDSM4(aHi[0], aHi[1], aHi[2], aHi[3], aHiAdr + ko);
                LDSM4(aLo[0], aLo[1], aLo[2], aLo[3], aLoAdr + ko);
                #pragma unroll
                for (int n = 0; n < 3; ++n) if (n < NTL) MMA16816(C1[n], aHi, bf[n]);
                #pragma unroll
                for (int n = 0; n < 3; ++n) if (n < NTL) MMA16816(C1[n], aLo, bf[n]);
            }

            float p0 = (nh == 0) ? b2[0] : 0.f;
            float p1 = (nh == 0) ? b2[0] : 0.f;
            #pragma unroll
            for (int nt = 0; nt < 3; ++nt) {
                if (nt < NTL) {
                    const int col = (nh * 3 + nt) * 8 + (lane & 3) * 2;
                    p0 += fmaxf(C1[nt][0] + b1s[col],     0.f) * w2s[col]
                        + fmaxf(C1[nt][1] + b1s[col + 1], 0.f) * w2s[col + 1];
                    p1 += fmaxf(C1[nt][2] + b1s[col],     0.f) * w2s[col]
                        + fmaxf(C1[nt][3] + b1s[col + 1], 0.f) * w2s[col + 1];
                }
            }
            p0 += __shfl_xor_sync(0xffffffffu, p0, 1);
            p0 += __shfl_xor_sync(0xffffffffu, p0, 2);
            p1 += __shfl_xor_sync(0xffffffffu, p1, 1);
            p1 += __shfl_xor_sync(0xffffffffu, p1, 2);
            if ((lane & 3) == 0) {
                const int row = mb + (lane >> 2);
                float* sc = (nh == 0) ? scoreSA : scoreSB;
                sc[c * ROWS + row]     = p0;
                sc[c * ROWS + row + 8] = p1;
            }
        }

        if (c < 2) {
            __syncthreads();                  // GEMM1 reads of X done
            stage_chunk(smc, hb, c + 1, tid); // overwrite X with next chunk's hist
            __syncthreads();
        }
    }
    __syncthreads();

    // ---- masked softmax over L (10 warps) ----
    float logit = -3.402823466e38f;
    if (tid < LL) {
        float m = (float)mask[(size_t)b * LL + tid];
        logit = scoreSA[tid] + scoreSB[tid] + (1.0f - m) * (-1e9f);
    }
    {
        float v = logit;
        #pragma unroll
        for (int o = 16; o; o >>= 1) v = fmaxf(v, __shfl_xor_sync(0xffffffffu, v, o));
        if (lane == 0) redS[wid] = v;
    }
    __syncthreads();
    if (tid < 32) {
        float m = (tid < 10) ? redS[tid] : -3.402823466e38f;
        #pragma unroll
        for (int o = 8; o; o >>= 1) m = fmaxf(m, __shfl_xor_sync(0xffffffffu, m, o));
        if (tid == 0) redS[16] = m;
    }
    __syncthreads();
    const float M = redS[16];
    float e = (tid < LL) ? expf(logit - M) : 0.f;
    {
        float s = e;
        #pragma unroll
        for (int o = 16; o; o >>= 1) s += __shfl_xor_sync(0xffffffffu, s, o);
        if (lane == 0) redS[wid] = s;
    }
    __syncthreads();
    if (tid < 32) {
        float s = (tid < 10) ? redS[tid] : 0.f;
        #pragma unroll
        for (int o = 8; o; o >>= 1) s += __shfl_xor_sync(0xffffffffu, s, o);
        if (tid == 0) redS[17] = s;
    }
    __syncthreads();
    const float S = redS[17];
    if (tid < LL) {
        float a = e / S;
        attnS[tid] = a;
        out[(size_t)BB * DD + (size_t)b * LL + tid] = a;
    }
    __syncthreads();

    // ---- user_interest[b][d] = sum_l attn[l]*hist[l][d]  (gmem fp32, L2-hot) ----
    {
        const float* hbf = hist + (size_t)b * LL * DD;
        for (int i = tid; i < 512; i += NT) {
            const int d = i & 127;
            const int g = i >> 7;
            float s = 0.f;
            #pragma unroll 2
            for (int l = g * 50; l < g * 50 + 50; ++l)
                s = fmaf(attnS[l], hbf[l * DD + d], s);
            partS[g * 128 + d] = s;
        }
    }
    __syncthreads();
    if (tid < DD)
        out[(size_t)b * DD + tid] = partS[tid] + partS[128 + tid] + partS[256 + tid] + partS[384 + tid];
}

extern "C" void kernel_launch(void* const* d_in, const int* in_sizes, int n_in,
                              void* d_out, int out_size)
{
    const float* hist = (const float*)d_in[0];
    const float* tgt  = (const float*)d_in[1];
    const int*   mask = (const int*)  d_in[2];
    const float* W0   = (const float*)d_in[3];
    const float* b0   = (const float*)d_in[4];
    const float* W1   = (const float*)d_in[5];
    const float* b1   = (const float*)d_in[6];
    const float* W2   = (const float*)d_in[7];
    const float* b2   = (const float*)d_in[8];
    float* out = (float*)d_out;

    static int smem_set = 0;
    if (!smem_set) {
        cudaFuncSetAttribute(din_kernel,
                             cudaFuncAttributeMaxDynamicSharedMemorySize,
                             SMEM_BYTES);
        smem_set = 1;
    }
    din_kernel<<<BB, NT, SMEM_BYTES>>>(hist, tgt, mask, W0, b0, W1, b1, W2, b2, out);
}

// round 13
// speedup vs baseline: 3.5588x; 1.0423x over previous
#include <cuda_runtime.h>
#include <cuda_fp16.h>
#include <cstdint>
#include <math.h>

#define BB 2048
#define LL 200
#define DD 128
#define H0N 80
#define H1N 40
#define NT 320            // 10 warps: (m-tile w%5) x (n-half w/5); 3 CTAs/SM
#define ROWS 80           // L-rows per chunk (3 chunks; last has 40 real rows)

// word strides (conflict-free ldmatrix; stride ≡ 4 mod 8)
#define S_HIST 68
#define S_H0   68         // == S_HIST: h0 row r aliases hist row r's own footprint
#define S_W1   44

// ---- smem byte offsets ----
// X region (chunk-lived): hist hi/lo; h0 hi/lo aliased row-aligned inside it
#define HIST_HI 0
#define HIST_LO (ROWS*S_HIST*4)           // 21760
#define H0_HI   0
#define H0_LO   HIST_LO
// Y region (batch-lived): A0T + W1T
#define A0T_HI  (2*ROWS*S_HIST*4)         // 43520 (ends 65280)
#define W1T_HI  65280                     // 40*44*4 = 7040 (ends 72320)
#define MISC    72320
#define OFF_TGT  (MISC + 0)       // 128 f
#define OFF_C0   (MISC + 512)     // 80 f
#define OFF_B1   (MISC + 832)     // 40 f
#define OFF_W2   (MISC + 992)     // 40 f
#define OFF_SC   (MISC + 1152)    // 240 f (nh0 partial; partS aliases after softmax)
#define OFF_SC2  (MISC + 2112)    // 240 f (nh1 partial)
#define OFF_ATTN (MISC + 3072)    // 200 f
#define OFF_RED  (MISC + 3872)    // 32 f
#define SMEM_BYTES (MISC + 4000)  // 76,320 B -> 3 CTAs/SM
#define OFF_PART OFF_SC           // alias: scores dead after logit read

#define LDSM4(r0, r1, r2, r3, addr) asm volatile( \
    "ldmatrix.sync.aligned.m8n8.x4.shared.b16 {%0,%1,%2,%3}, [%4];" \
    : "=r"(r0), "=r"(r1), "=r"(r2), "=r"(r3) : "r"(addr))

#define LDSM2(r0, r1, addr) asm volatile( \
    "ldmatrix.sync.aligned.m8n8.x2.shared.b16 {%0,%1}, [%2];" \
    : "=r"(r0), "=r"(r1) : "r"(addr))

#define MMA16816(c, a, bfr) asm volatile( \
    "mma.sync.aligned.m16n8k16.row.col.f32.f16.f16.f32 " \
    "{%0,%1,%2,%3}, {%4,%5,%6,%7}, {%8,%9}, {%0,%1,%2,%3};" \
    : "+f"((c)[0]), "+f"((c)[1]), "+f"((c)[2]), "+f"((c)[3]) \
    : "r"((a)[0]), "r"((a)[1]), "r"((a)[2]), "r"((a)[3]), \
      "r"((bfr)[0]), "r"((bfr)[1]))

// pairwise named barrier: the 2 warps sharing m-tile `mwid` (64 threads)
#define BARPAIR(id) asm volatile("bar.sync %0, 64;" :: "r"(id) : "memory")

__device__ __forceinline__ uint32_t smem_u32(const void* p) {
    uint32_t a;
    asm("{ .reg .u64 t; cvta.to.shared.u64 t, %1; cvt.u32.u64 %0, t; }" : "=r"(a) : "l"(p));
    return a;
}

// split fp32 pair -> packed fp16x2 hi word + lo word
__device__ __forceinline__ void split2h(float a, float b, uint32_t& hiw, uint32_t& low) {
    __half ah = __float2half_rn(a);
    __half bh = __float2half_rn(b);
    __half al = __float2half_rn(a - __half2float(ah));
    __half bl = __float2half_rn(b - __half2float(bh));
    hiw = (uint32_t)__half_as_ushort(ah) | ((uint32_t)__half_as_ushort(bh) << 16);
    low = (uint32_t)__half_as_ushort(al) | ((uint32_t)__half_as_ushort(bl) << 16);
}
// truncate fp32 pair -> packed fp16x2 word
__device__ __forceinline__ uint32_t pack2h(float a, float b) {
    return (uint32_t)__half_as_ushort(__float2half_rn(a)) |
           ((uint32_t)__half_as_ushort(__float2half_rn(b)) << 16);
}

// stage one 80-row chunk of hist as fp16 hi/lo (rows past L zeroed); STS.64
__device__ __forceinline__ void stage_chunk(char* smc, const float4* hb, int c, int tid) {
    for (int idx = tid; idx < ROWS * 32; idx += NT) {
        int r = idx >> 5;
        int q = idx & 31;
        int gl = c * ROWS + r;
        float4 v = make_float4(0.f, 0.f, 0.f, 0.f);
        if (gl < LL) v = hb[gl * 32 + q];
        uint32_t hw0, lw0, hw1, lw1;
        split2h(v.x, v.y, hw0, lw0);
        split2h(v.z, v.w, hw1, lw1);
        uint32_t wo = (uint32_t)(r * S_HIST + q * 2) * 4u;
        *(uint2*)(smc + HIST_HI + wo) = make_uint2(hw0, hw1);
        *(uint2*)(smc + HIST_LO + wo) = make_uint2(lw0, lw1);
    }
}

__global__ __launch_bounds__(NT, 3)
void din_kernel(const float* __restrict__ hist,
                const float* __restrict__ tgt,
                const int*   __restrict__ mask,
                const float* __restrict__ W0,
                const float* __restrict__ b0,
                const float* __restrict__ W1,
                const float* __restrict__ b1,
                const float* __restrict__ W2,
                const float* __restrict__ b2,
                float* __restrict__ out)
{
    extern __shared__ char smc[];
    float* tgtS    = (float*)(smc + OFF_TGT);
    float* c0s     = (float*)(smc + OFF_C0);
    float* b1s     = (float*)(smc + OFF_B1);
    float* w2s     = (float*)(smc + OFF_W2);
    float* scoreSA = (float*)(smc + OFF_SC);
    float* scoreSB = (float*)(smc + OFF_SC2);
    float* attnS   = (float*)(smc + OFF_ATTN);
    float* redS    = (float*)(smc + OFF_RED);
    float* partS   = (float*)(smc + OFF_PART);

    const int b    = blockIdx.x;
    const int tid  = threadIdx.x;
    const int wid  = tid >> 5;
    const int lane = tid & 31;
    const int mwid = (wid < 5) ? wid : wid - 5;   // m-tile index 0..4
    const int nh   = (wid < 5) ? 0 : 1;           // n-half
    const uint32_t smem_base = smem_u32(smc);
    const float4* hb = (const float4*)(hist + (size_t)b * LL * DD);

    if (tid < DD) tgtS[tid] = tgt[(size_t)b * DD + tid];
    __syncthreads();

    // ---- prologue: A0t build + W1t build (once) + c0 + small vectors + chunk0 ----
    for (int w = tid; w < H0N * 32; w += NT) {
        int n   = w % H0N;
        int kp2 = (w / H0N) * 2;
        int d   = kp2 * 2;
        float v0 = W0[d * H0N + n] + W0[(2 * DD + d) * H0N + n] + tgtS[d] * W0[(3 * DD + d) * H0N + n];
        float v1 = W0[(d + 1) * H0N + n] + W0[(2 * DD + d + 1) * H0N + n] + tgtS[d + 1] * W0[(3 * DD + d + 1) * H0N + n];
        float v2 = W0[(d + 2) * H0N + n] + W0[(2 * DD + d + 2) * H0N + n] + tgtS[d + 2] * W0[(3 * DD + d + 2) * H0N + n];
        float v3 = W0[(d + 3) * H0N + n] + W0[(2 * DD + d + 3) * H0N + n] + tgtS[d + 3] * W0[(3 * DD + d + 3) * H0N + n];
        uint32_t wo = (uint32_t)(n * S_HIST + kp2) * 4u;
        *(uint2*)(smc + A0T_HI + wo) = make_uint2(pack2h(v0, v1), pack2h(v2, v3));
    }
    for (int w = tid; w < H1N * 20; w += NT) {    // W1t [n][k] fp16, built ONCE
        int n   = w % H1N;
        int kp2 = (w / H1N) * 2;
        int k   = kp2 * 2;
        uint32_t wo = (uint32_t)(n * S_W1 + kp2) * 4u;
        *(uint2*)(smc + W1T_HI + wo) =
            make_uint2(pack2h(W1[k * H1N + n],       W1[(k + 1) * H1N + n]),
                       pack2h(W1[(k + 2) * H1N + n], W1[(k + 3) * H1N + n]));
    }
    if (tid < H0N) {
        float s0 = 0.f, s1 = 0.f;
        #pragma unroll 4
        for (int d = 0; d < DD; d += 2) {
            s0 = fmaf(tgtS[d],     W0[(DD + d) * H0N + tid]     - W0[(2 * DD + d) * H0N + tid],     s0);
            s1 = fmaf(tgtS[d + 1], W0[(DD + d + 1) * H0N + tid] - W0[(2 * DD + d + 1) * H0N + tid], s1);
        }
        c0s[tid] = b0[tid] + s0 + s1;
    }
    if (tid < H1N) { b1s[tid] = b1[tid]; w2s[tid] = W2[tid]; }
    stage_chunk(smc, hb, 0, tid);
    __syncthreads();

    // ldmatrix lane geometry
    const int rA = lane & 15;
    const int kA = (lane & 16) ? 4 : 0;
    const int rB = (lane & 7) | ((lane & 16) >> 1);
    const int kB = (lane & 8) ? 4 : 0;
    const int rB2 = lane & 7;                    // x2 geometry
    const int kB2 = (lane & 8) ? 4 : 0;
    const int mb = mwid * 16;
    const int barid = 1 + mwid;

    #pragma unroll 1
    for (int c = 0; c < 3; ++c) {
        const int MT = (c < 2) ? 5 : 3;   // active m-tiles this chunk

        if (mwid < MT) {
            // ===== GEMM0: h0 = relu(hist @ A0t^T + c0); fp16 2-term =====
            float C0[5][4];
            #pragma unroll
            for (int n = 0; n < 5; ++n)
                #pragma unroll
                for (int j = 0; j < 4; ++j) C0[n][j] = 0.f;

            const uint32_t aHiAdr = smem_base + HIST_HI + (uint32_t)((mb + rA) * S_HIST + kA) * 4u;
            const uint32_t aLoAdr = smem_base + HIST_LO + (uint32_t)((mb + rA) * S_HIST + kA) * 4u;
            const int nrow0 = nh * 40;
            const uint32_t bAdr  = smem_base + A0T_HI + (uint32_t)((nrow0 + rB) * S_HIST + kB) * 4u;
            const uint32_t bAdr2 = smem_base + A0T_HI + (uint32_t)((nrow0 + 32 + rB2) * S_HIST + kB2) * 4u;

            #pragma unroll
            for (int ks = 0; ks < 8; ++ks) {
                const uint32_t ko = (uint32_t)(ks * 8) * 4u;
                uint32_t bf[5][2], aHi[4], aLo[4];
                #pragma unroll
                for (int p = 0; p < 2; ++p) {
                    const uint32_t po = (uint32_t)(p * 16 * S_HIST) * 4u + ko;
                    LDSM4(bf[2*p][0], bf[2*p][1], bf[2*p+1][0], bf[2*p+1][1], bAdr + po);
                }
                LDSM2(bf[4][0], bf[4][1], bAdr2 + ko);
                LDSM4(aHi[0], aHi[1], aHi[2], aHi[3], aHiAdr + ko);
                LDSM4(aLo[0], aLo[1], aLo[2], aLo[3], aLoAdr + ko);
                #pragma unroll
                for (int n = 0; n < 5; ++n) MMA16816(C0[n], aHi, bf[n]);
                #pragma unroll
                for (int n = 0; n < 5; ++n) MMA16816(C0[n], aLo, bf[n]);
            }
            BARPAIR(barid);   // pair's hist reads done; pair's rows can be overwritten

            // epilogue: bias+relu+split(fp16) -> h0 (row-aligned alias of hist rows)
            {
                const int row = mb + (lane >> 2);
                #pragma unroll
                for (int nt = 0; nt < 5; ++nt) {
                    const int g   = nh * 5 + nt;
                    const int col = g * 8 + (lane & 3) * 2;
                    uint32_t hw, lw;
                    float v0 = fmaxf(C0[nt][0] + c0s[col],     0.f);
                    float v1 = fmaxf(C0[nt][1] + c0s[col + 1], 0.f);
                    split2h(v0, v1, hw, lw);
                    uint32_t wo = (uint32_t)(row * S_H0 + g * 4 + (lane & 3)) * 4u;
                    *(uint32_t*)(smc + H0_HI + wo) = hw;
                    *(uint32_t*)(smc + H0_LO + wo) = lw;
                    v0 = fmaxf(C0[nt][2] + c0s[col],     0.f);
                    v1 = fmaxf(C0[nt][3] + c0s[col + 1], 0.f);
                    split2h(v0, v1, hw, lw);
                    wo = (uint32_t)((row + 8) * S_H0 + g * 4 + (lane & 3)) * 4u;
                    *(uint32_t*)(smc + H0_HI + wo) = hw;
                    *(uint32_t*)(smc + H0_LO + wo) = lw;
                }
            }
            BARPAIR(barid);   // pair's h0 rows complete

            // ===== GEMM1 + layer2 (n-split: nh0 = tiles 0-2, nh1 = tiles 3-4) =====
            {
                const int NTL = (nh == 0) ? 3 : 2;
                float C1[3][4];
                #pragma unroll
                for (int n = 0; n < 3; ++n)
                    #pragma unroll
                    for (int j = 0; j < 4; ++j) C1[n][j] = 0.f;

                const uint32_t aHiAdr1 = smem_base + H0_HI + (uint32_t)((mb + rA) * S_H0 + kA) * 4u;
                const uint32_t aLoAdr1 = smem_base + H0_LO + (uint32_t)((mb + rA) * S_H0 + kA) * 4u;
                const int brow = (nh == 0) ? 0 : 24;
                const uint32_t bAdr1  = smem_base + W1T_HI + (uint32_t)((brow + rB) * S_W1 + kB) * 4u;
                const uint32_t bAdr21 = smem_base + W1T_HI + (uint32_t)((16 + rB2) * S_W1 + kB2) * 4u;

                #pragma unroll
                for (int ks = 0; ks < 5; ++ks) {
                    const uint32_t ko = (uint32_t)(ks * 8) * 4u;
                    uint32_t bf[3][2], aHi[4], aLo[4];
                    LDSM4(bf[0][0], bf[0][1], bf[1][0], bf[1][1], bAdr1 + ko);
                    if (nh == 0) LDSM2(bf[2][0], bf[2][1], bAdr21 + ko);
                    LDSM4(aHi[0], aHi[1], aHi[2], aHi[3], aHiAdr1 + ko);
                    LDSM4(aLo[0], aLo[1], aLo[2], aLo[3], aLoAdr1 + ko);
                    #pragma unroll
                    for (int n = 0; n < 3; ++n) if (n < NTL) MMA16816(C1[n], aHi, bf[n]);
                    #pragma unroll
                    for (int n = 0; n < 3; ++n) if (n < NTL) MMA16816(C1[n], aLo, bf[n]);
                }

                float p0 = (nh == 0) ? b2[0] : 0.f;
                float p1 = (nh == 0) ? b2[0] : 0.f;
                #pragma unroll
                for (int nt = 0; nt < 3; ++nt) {
                    if (nt < NTL) {
                        const int col = (nh * 3 + nt) * 8 + (lane & 3) * 2;
                        p0 += fmaxf(C1[nt][0] + b1s[col],     0.f) * w2s[col]
                            + fmaxf(C1[nt][1] + b1s[col + 1], 0.f) * w2s[col + 1];
                        p1 += fmaxf(C1[nt][2] + b1s[col],     0.f) * w2s[col]
                            + fmaxf(C1[nt][3] + b1s[col + 1], 0.f) * w2s[col + 1];
                    }
                }
                p0 += __shfl_xor_sync(0xffffffffu, p0, 1);
                p0 += __shfl_xor_sync(0xffffffffu, p0, 2);
                p1 += __shfl_xor_sync(0xffffffffu, p1, 1);
                p1 += __shfl_xor_sync(0xffffffffu, p1, 2);
                if ((lane & 3) == 0) {
                    const int row = mb + (lane >> 2);
                    float* sc = (nh == 0) ? scoreSA : scoreSB;
                    sc[c * ROWS + row]     = p0;
                    sc[c * ROWS + row + 8] = p1;
                }
            }
        }

        if (c < 2) {
            __syncthreads();                  // all reads of X done
            stage_chunk(smc, hb, c + 1, tid); // overwrite X with next chunk's hist
            __syncthreads();
        }
    }
    __syncthreads();

    // ---- masked softmax over L (10 warps) ----
    float logit = -3.402823466e38f;
    if (tid < LL) {
        float m = (float)mask[(size_t)b * LL + tid];
        logit = scoreSA[tid] + scoreSB[tid] + (1.0f - m) * (-1e9f);
    }
    {
        float v = logit;
        #pragma unroll
        for (int o = 16; o; o >>= 1) v = fmaxf(v, __shfl_xor_sync(0xffffffffu, v, o));
        if (lane == 0) redS[wid] = v;
    }
    __syncthreads();
    if (tid < 32) {
        float m = (tid < 10) ? redS[tid] : -3.402823466e38f;
        #pragma unroll
        for (int o = 8; o; o >>= 1) m = fmaxf(m, __shfl_xor_sync(0xffffffffu, m, o));
        if (tid == 0) redS[16] = m;
    }
    __syncthreads();
    const float M = redS[16];
    float e = (tid < LL) ? expf(logit - M) : 0.f;
    {
        float s = e;
        #pragma unroll
        for (int o = 16; o; o >>= 1) s += __shfl_xor_sync(0xffffffffu, s, o);
        if (lane == 0) redS[wid] = s;
    }
    __syncthreads();
    if (tid < 32) {
        float s = (tid < 10) ? redS[tid] : 0.f;
        #pragma unroll
        for (int o = 8; o; o >>= 1) s += __shfl_xor_sync(0xffffffffu, s, o);
        if (tid == 0) redS[17] = s;
    }
    __syncthreads();
    const float S = redS[17];
    if (tid < LL) {
        float a = e / S;
        attnS[tid] = a;
        out[(size_t)BB * DD + (size_t)b * LL + tid] = a;
    }
    __syncthreads();   // attn ready; scoreS regions now dead -> partS alias safe

    // ---- user_interest[b][d] = sum_l attn[l]*hist[l][d]  (gmem fp32, L2-hot) ----
    if (tid < 256) {
        const int d = tid & 127;
        const int g = tid >> 7;               // 0..1, 100 l's each
        const float* hbf = hist + (size_t)b * LL * DD;
        float s = 0.f;
        #pragma unroll 2
        for (int l = g * 100; l < g * 100 + 100; ++l)
            s = fmaf(attnS[l], hbf[l * DD + d], s);
        partS[g * 128 + d] = s;
    }
    __syncthreads();
    if (tid < DD)
        out[(size_t)b * DD + tid] = partS[tid] + partS[128 + tid];
}

extern "C" void kernel_launch(void* const* d_in, const int* in_sizes, int n_in,
                              void* d_out, int out_size)
{
    const float* hist = (const float*)d_in[0];
    const float* tgt  = (const float*)d_in[1];
    const int*   mask = (const int*)  d_in[2];
    const float* W0   = (const float*)d_in[3];
    const float* b0   = (const float*)d_in[4];
    const float* W1   = (const float*)d_in[5];
    const float* b1   = (const float*)d_in[6];
    const float* W2   = (const float*)d_in[7];
    const float* b2   = (const float*)d_in[8];
    float* out = (float*)d_out;

    static int smem_set = 0;
    if (!smem_set) {
        cudaFuncSetAttribute(din_kernel,
                             cudaFuncAttributeMaxDynamicSharedMemorySize,
                             SMEM_BYTES);
        smem_set = 1;
    }
    din_kernel<<<BB, NT, SMEM_BYTES>>>(hist, tgt, mask, W0, b0, W1, b1, W2, b2, out);
}

// round 14
// speedup vs baseline: 4.1832x; 1.1755x over previous
#include <cuda_runtime.h>
#include <cuda_fp16.h>
#include <cstdint>
#include <math.h>

#define BB 2048
#define LL 200
#define DD 128
#define H0N 80
#define H1N 40
#define NT 256            // 8 warps: (m-tile w%4) x (n-half w/4); 4 CTAs/SM
#define ROWS 64           // L-rows per chunk (4 chunks; last has 8 real rows)

// word strides (conflict-free ldmatrix; stride ≡ 4 mod 8)
#define S_HIST 68
#define S_H0   68         // == S_HIST: h0 row r aliases hist row r's own footprint
#define S_W1   44

// ---- smem byte offsets ----
#define HIST_HI 0                         // [64][68w] fp16-single (17408 B); h0 aliases
#define H0_HI   0
#define A0T_HI  (ROWS*S_HIST*4)           // 17408, 80*68*4=21760 (ends 39168)
#define W1T_HI  39168                     // 40*44*4 = 7040 (ends 46208)
#define MISC    46208
#define OFF_TGT  (MISC + 0)       // 128 f
#define OFF_C0   (MISC + 512)     // 80 f
#define OFF_B1   (MISC + 832)     // 40 f
#define OFF_W2   (MISC + 992)     // 40 f
#define OFF_SC   (MISC + 1152)    // 256 f (nh0 partial; partS aliases after softmax)
#define OFF_SC2  (MISC + 2176)    // 256 f (nh1 partial)
#define OFF_ATTN (MISC + 3200)    // 200 f
#define OFF_RED  (MISC + 4000)    // 32 f
#define SMEM_BYTES (MISC + 4128)  // 50,336 B -> 4 CTAs/SM
#define OFF_PART OFF_SC           // alias: scores dead after logit read

#define LDSM4(r0, r1, r2, r3, addr) asm volatile( \
    "ldmatrix.sync.aligned.m8n8.x4.shared.b16 {%0,%1,%2,%3}, [%4];" \
    : "=r"(r0), "=r"(r1), "=r"(r2), "=r"(r3) : "r"(addr))

#define LDSM2(r0, r1, addr) asm volatile( \
    "ldmatrix.sync.aligned.m8n8.x2.shared.b16 {%0,%1}, [%2];" \
    : "=r"(r0), "=r"(r1) : "r"(addr))

#define MMA16816(c, a, bfr) asm volatile( \
    "mma.sync.aligned.m16n8k16.row.col.f32.f16.f16.f32 " \
    "{%0,%1,%2,%3}, {%4,%5,%6,%7}, {%8,%9}, {%0,%1,%2,%3};" \
    : "+f"((c)[0]), "+f"((c)[1]), "+f"((c)[2]), "+f"((c)[3]) \
    : "r"((a)[0]), "r"((a)[1]), "r"((a)[2]), "r"((a)[3]), \
      "r"((bfr)[0]), "r"((bfr)[1]))

// pairwise named barrier: the 2 warps sharing m-tile `mwid` (64 threads)
#define BARPAIR(id) asm volatile("bar.sync %0, 64;" :: "r"(id) : "memory")

__device__ __forceinline__ uint32_t smem_u32(const void* p) {
    uint32_t a;
    asm("{ .reg .u64 t; cvta.to.shared.u64 t, %1; cvt.u32.u64 %0, t; }" : "=r"(a) : "l"(p));
    return a;
}

// truncate fp32 pair -> packed fp16x2 word
__device__ __forceinline__ uint32_t pack2h(float a, float b) {
    return (uint32_t)__half_as_ushort(__float2half_rn(a)) |
           ((uint32_t)__half_as_ushort(__float2half_rn(b)) << 16);
}

// stage one 64-row chunk of hist as fp16 single (rows past L zeroed); STS.64
__device__ __forceinline__ void stage_chunk(char* smc, const float4* hb, int c, int tid) {
    for (int idx = tid; idx < ROWS * 32; idx += NT) {
        int r = idx >> 5;
        int q = idx & 31;
        int gl = c * ROWS + r;
        float4 v = make_float4(0.f, 0.f, 0.f, 0.f);
        if (gl < LL) v = hb[gl * 32 + q];
        uint32_t wo = (uint32_t)(r * S_HIST + q * 2) * 4u;
        *(uint2*)(smc + HIST_HI + wo) = make_uint2(pack2h(v.x, v.y), pack2h(v.z, v.w));
    }
}

__global__ __launch_bounds__(NT, 4)
void din_kernel(const float* __restrict__ hist,
                const float* __restrict__ tgt,
                const int*   __restrict__ mask,
                const float* __restrict__ W0,
                const float* __restrict__ b0,
                const float* __restrict__ W1,
                const float* __restrict__ b1,
                const float* __restrict__ W2,
                const float* __restrict__ b2,
                float* __restrict__ out)
{
    extern __shared__ char smc[];
    float* tgtS    = (float*)(smc + OFF_TGT);
    float* c0s     = (float*)(smc + OFF_C0);
    float* b1s     = (float*)(smc + OFF_B1);
    float* w2s     = (float*)(smc + OFF_W2);
    float* scoreSA = (float*)(smc + OFF_SC);
    float* scoreSB = (float*)(smc + OFF_SC2);
    float* attnS   = (float*)(smc + OFF_ATTN);
    float* redS    = (float*)(smc + OFF_RED);
    float* partS   = (float*)(smc + OFF_PART);

    const int b    = blockIdx.x;
    const int tid  = threadIdx.x;
    const int wid  = tid >> 5;
    const int lane = tid & 31;
    const int mwid = (wid < 4) ? wid : wid - 4;   // m-tile index 0..3
    const int nh   = (wid < 4) ? 0 : 1;           // n-half
    const uint32_t smem_base = smem_u32(smc);
    const float4* hb = (const float4*)(hist + (size_t)b * LL * DD);

    if (tid < DD) tgtS[tid] = tgt[(size_t)b * DD + tid];
    __syncthreads();

    // ---- prologue: A0t + W1t build (fp16 single, once) + c0 + small vectors + chunk0 ----
    for (int w = tid; w < H0N * 32; w += NT) {
        int n   = w % H0N;
        int kp2 = (w / H0N) * 2;
        int d   = kp2 * 2;
        float v0 = W0[d * H0N + n] + W0[(2 * DD + d) * H0N + n] + tgtS[d] * W0[(3 * DD + d) * H0N + n];
        float v1 = W0[(d + 1) * H0N + n] + W0[(2 * DD + d + 1) * H0N + n] + tgtS[d + 1] * W0[(3 * DD + d + 1) * H0N + n];
        float v2 = W0[(d + 2) * H0N + n] + W0[(2 * DD + d + 2) * H0N + n] + tgtS[d + 2] * W0[(3 * DD + d + 2) * H0N + n];
        float v3 = W0[(d + 3) * H0N + n] + W0[(2 * DD + d + 3) * H0N + n] + tgtS[d + 3] * W0[(3 * DD + d + 3) * H0N + n];
        uint32_t wo = (uint32_t)(n * S_HIST + kp2) * 4u;
        *(uint2*)(smc + A0T_HI + wo) = make_uint2(pack2h(v0, v1), pack2h(v2, v3));
    }
    for (int w = tid; w < H1N * 20; w += NT) {
        int n   = w % H1N;
        int kp2 = (w / H1N) * 2;
        int k   = kp2 * 2;
        uint32_t wo = (uint32_t)(n * S_W1 + kp2) * 4u;
        *(uint2*)(smc + W1T_HI + wo) =
            make_uint2(pack2h(W1[k * H1N + n],       W1[(k + 1) * H1N + n]),
                       pack2h(W1[(k + 2) * H1N + n], W1[(k + 3) * H1N + n]));
    }
    if (tid < H0N) {
        float s0 = 0.f, s1 = 0.f;
        #pragma unroll 4
        for (int d = 0; d < DD; d += 2) {
            s0 = fmaf(tgtS[d],     W0[(DD + d) * H0N + tid]     - W0[(2 * DD + d) * H0N + tid],     s0);
            s1 = fmaf(tgtS[d + 1], W0[(DD + d + 1) * H0N + tid] - W0[(2 * DD + d + 1) * H0N + tid], s1);
        }
        c0s[tid] = b0[tid] + s0 + s1;
    }
    if (tid < H1N) { b1s[tid] = b1[tid]; w2s[tid] = W2[tid]; }
    stage_chunk(smc, hb, 0, tid);
    __syncthreads();

    // ldmatrix lane geometry
    const int rA = lane & 15;
    const int kA = (lane & 16) ? 4 : 0;
    const int rB = (lane & 7) | ((lane & 16) >> 1);
    const int kB = (lane & 8) ? 4 : 0;
    const int rB2 = lane & 7;                    // x2 geometry
    const int kB2 = (lane & 8) ? 4 : 0;
    const int mb = mwid * 16;
    const int barid = 1 + mwid;

    #pragma unroll 1
    for (int c = 0; c < 4; ++c) {
        const int MT = (c < 3) ? 4 : 1;   // active m-tiles this chunk

        if (mwid < MT) {
            // ===== GEMM0: h0 = relu(hist @ A0t^T + c0); fp16 single =====
            float C0[5][4];
            #pragma unroll
            for (int n = 0; n < 5; ++n)
                #pragma unroll
                for (int j = 0; j < 4; ++j) C0[n][j] = 0.f;

            const uint32_t aAdr = smem_base + HIST_HI + (uint32_t)((mb + rA) * S_HIST + kA) * 4u;
            const int nrow0 = nh * 40;
            const uint32_t bAdr  = smem_base + A0T_HI + (uint32_t)((nrow0 + rB) * S_HIST + kB) * 4u;
            const uint32_t bAdr2 = smem_base + A0T_HI + (uint32_t)((nrow0 + 32 + rB2) * S_HIST + kB2) * 4u;

            #pragma unroll
            for (int ks = 0; ks < 8; ++ks) {
                const uint32_t ko = (uint32_t)(ks * 8) * 4u;
                uint32_t bf[5][2], a[4];
                #pragma unroll
                for (int p = 0; p < 2; ++p) {
                    const uint32_t po = (uint32_t)(p * 16 * S_HIST) * 4u + ko;
                    LDSM4(bf[2*p][0], bf[2*p][1], bf[2*p+1][0], bf[2*p+1][1], bAdr + po);
                }
                LDSM2(bf[4][0], bf[4][1], bAdr2 + ko);
                LDSM4(a[0], a[1], a[2], a[3], aAdr + ko);
                #pragma unroll
                for (int n = 0; n < 5; ++n) MMA16816(C0[n], a, bf[n]);
            }
            BARPAIR(barid);   // pair's hist reads done; pair's rows can be overwritten

            // epilogue: bias+relu+pack(fp16) -> h0 (row-aligned alias of hist rows)
            {
                const int row = mb + (lane >> 2);
                #pragma unroll
                for (int nt = 0; nt < 5; ++nt) {
                    const int g   = nh * 5 + nt;
                    const int col = g * 8 + (lane & 3) * 2;
                    float v0 = fmaxf(C0[nt][0] + c0s[col],     0.f);
                    float v1 = fmaxf(C0[nt][1] + c0s[col + 1], 0.f);
                    uint32_t wo = (uint32_t)(row * S_H0 + g * 4 + (lane & 3)) * 4u;
                    *(uint32_t*)(smc + H0_HI + wo) = pack2h(v0, v1);
                    v0 = fmaxf(C0[nt][2] + c0s[col],     0.f);
                    v1 = fmaxf(C0[nt][3] + c0s[col + 1], 0.f);
                    wo = (uint32_t)((row + 8) * S_H0 + g * 4 + (lane & 3)) * 4u;
                    *(uint32_t*)(smc + H0_HI + wo) = pack2h(v0, v1);
                }
            }
            BARPAIR(barid);   // pair's h0 rows complete

            // ===== GEMM1 + layer2 (n-split: nh0 = tiles 0-2, nh1 = tiles 3-4) =====
            {
                const int NTL = (nh == 0) ? 3 : 2;
                float C1[3][4];
                #pragma unroll
                for (int n = 0; n < 3; ++n)
                    #pragma unroll
                    for (int j = 0; j < 4; ++j) C1[n][j] = 0.f;

                const uint32_t aAdr1 = smem_base + H0_HI + (uint32_t)((mb + rA) * S_H0 + kA) * 4u;
                const int brow = (nh == 0) ? 0 : 24;
                const uint32_t bAdr1  = smem_base + W1T_HI + (uint32_t)((brow + rB) * S_W1 + kB) * 4u;
                const uint32_t bAdr21 = smem_base + W1T_HI + (uint32_t)((16 + rB2) * S_W1 + kB2) * 4u;

                #pragma unroll
                for (int ks = 0; ks < 5; ++ks) {
                    const uint32_t ko = (uint32_t)(ks * 8) * 4u;
                    uint32_t bf[3][2], a[4];
                    LDSM4(bf[0][0], bf[0][1], bf[1][0], bf[1][1], bAdr1 + ko);
                    if (nh == 0) LDSM2(bf[2][0], bf[2][1], bAdr21 + ko);
                    LDSM4(a[0], a[1], a[2], a[3], aAdr1 + ko);
                    #pragma unroll
                    for (int n = 0; n < 3; ++n) if (n < NTL) MMA16816(C1[n], a, bf[n]);
                }

                float p0 = (nh == 0) ? b2[0] : 0.f;
                float p1 = (nh == 0) ? b2[0] : 0.f;
                #pragma unroll
                for (int nt = 0; nt < 3; ++nt) {
                    if (nt < NTL) {
                        const int col = (nh * 3 + nt) * 8 + (lane & 3) * 2;
                        p0 += fmaxf(C1[nt][0] + b1s[col],     0.f) * w2s[col]
                            + fmaxf(C1[nt][1] + b1s[col + 1], 0.f) * w2s[col + 1];
                        p1 += fmaxf(C1[nt][2] + b1s[col],     0.f) * w2s[col]
                            + fmaxf(C1[nt][3] + b1s[col + 1], 0.f) * w2s[col + 1];
                    }
                }
                p0 += __shfl_xor_sync(0xffffffffu, p0, 1);
                p0 += __shfl_xor_sync(0xffffffffu, p0, 2);
                p1 += __shfl_xor_sync(0xffffffffu, p1, 1);
                p1 += __shfl_xor_sync(0xffffffffu, p1, 2);
                if ((lane & 3) == 0) {
                    const int row = mb + (lane >> 2);
                    float* sc = (nh == 0) ? scoreSA : scoreSB;
                    sc[c * ROWS + row]     = p0;
                    sc[c * ROWS + row + 8] = p1;
                }
            }
        }

        if (c < 3) {
            __syncthreads();                  // all reads of X done
            stage_chunk(smc, hb, c + 1, tid); // overwrite X with next chunk's hist
            __syncthreads();
        }
    }
    __syncthreads();

    // ---- masked softmax over L (8 warps) ----
    float logit = -3.402823466e38f;
    if (tid < LL) {
        float m = (float)mask[(size_t)b * LL + tid];
        logit = scoreSA[tid] + scoreSB[tid] + (1.0f - m) * (-1e9f);
    }
    {
        float v = logit;
        #pragma unroll
        for (int o = 16; o; o >>= 1) v = fmaxf(v, __shfl_xor_sync(0xffffffffu, v, o));
        if (lane == 0) redS[wid] = v;
    }
    __syncthreads();
    if (tid < 32) {
        float m = (tid < 8) ? redS[tid] : -3.402823466e38f;
        #pragma unroll
        for (int o = 4; o; o >>= 1) m = fmaxf(m, __shfl_xor_sync(0xffffffffu, m, o));
        if (tid == 0) redS[16] = m;
    }
    __syncthreads();
    const float M = redS[16];
    float e = (tid < LL) ? expf(logit - M) : 0.f;
    {
        float s = e;
        #pragma unroll
        for (int o = 16; o; o >>= 1) s += __shfl_xor_sync(0xffffffffu, s, o);
        if (lane == 0) redS[wid] = s;
    }
    __syncthreads();
    if (tid < 32) {
        float s = (tid < 8) ? redS[tid] : 0.f;
        #pragma unroll
        for (int o = 4; o; o >>= 1) s += __shfl_xor_sync(0xffffffffu, s, o);
        if (tid == 0) redS[17] = s;
    }
    __syncthreads();
    const float S = redS[17];
    if (tid < LL) {
        float a = e / S;
        attnS[tid] = a;
        out[(size_t)BB * DD + (size_t)b * LL + tid] = a;
    }
    __syncthreads();   // attn ready; scoreS regions now dead -> partS alias safe

    // ---- user_interest[b][d] = sum_l attn[l]*hist[l][d]  (gmem fp32, L2-hot) ----
    {
        const int d = tid & 127;
        const int g = tid >> 7;               // 0..1, 100 l's each
        const float* hbf = hist + (size_t)b * LL * DD;
        float s = 0.f;
        #pragma unroll 2
        for (int l = g * 100; l < g * 100 + 100; ++l)
            s = fmaf(attnS[l], hbf[l * DD + d], s);
        partS[g * 128 + d] = s;
    }
    __syncthreads();
    if (tid < DD)
        out[(size_t)b * DD + tid] = partS[tid] + partS[128 + tid];
}

extern "C" void kernel_launch(void* const* d_in, const int* in_sizes, int n_in,
                              void* d_out, int out_size)
{
    const float* hist = (const float*)d_in[0];
    const float* tgt  = (const float*)d_in[1];
    const int*   mask = (const int*)  d_in[2];
    const float* W0   = (const float*)d_in[3];
    const float* b0   = (const float*)d_in[4];
    const float* W1   = (const float*)d_in[5];
    const float* b1   = (const float*)d_in[6];
    const float* W2   = (const float*)d_in[7];
    const float* b2   = (const float*)d_in[8];
    float* out = (float*)d_out;

    static int smem_set = 0;
    if (!smem_set) {
        cudaFuncSetAttribute(din_kernel,
                             cudaFuncAttributeMaxDynamicSharedMemorySize,
                             SMEM_BYTES);
        smem_set = 1;
    }
    din_kernel<<<BB, NT, SMEM_BYTES>>>(hist, tgt, mask, W0, b0, W1, b1, W2, b2, out);
}

// round 15
// speedup vs baseline: 5.1622x; 1.2340x over previous
#include <cuda_runtime.h>
#include <cuda_fp16.h>
#include <cstdint>
#include <math.h>

#define BB 2048
#define LL 200
#define DD 128
#define H0N 80
#define H1N 40
#define NT 256            // 8 warps: (m-tile w%4) x (n-half w/4); 4 CTAs/SM
#define ROWS 64           // L-rows per chunk (4 chunks; last has 8 real rows)

// word strides (conflict-free ldmatrix; stride ≡ 4 mod 8)
#define S_HIST 68
#define S_H0   68         // == S_HIST: h0 row r aliases hist row r's own footprint
#define S_W1   44

// ---- smem byte offsets ----
#define HIST_HI 0                         // [64][68w] fp16-single (17408 B); h0 aliases
#define H0_HI   0
#define A0T_HI  (ROWS*S_HIST*4)           // 17408, 80*68*4=21760 (ends 39168)
#define W1T_HI  39168                     // 40*44*4 = 7040 (ends 46208)
#define MISC    46208
#define OFF_TGT  (MISC + 0)       // 128 f
#define OFF_C0   (MISC + 512)     // 80 f
#define OFF_B1   (MISC + 832)     // 40 f
#define OFF_W2   (MISC + 992)     // 40 f
#define OFF_SC   (MISC + 1152)    // 256 f (nh0 partial)
#define OFF_SC2  (MISC + 2176)    // 256 f (nh1 partial)
#define OFF_ATTN (MISC + 3200)    // 200 f
#define OFF_RED  (MISC + 4000)    // 32 f
#define OFF_CP   (MISC + 4128)    // 240 f (c0 partials)
#define OFF_PART (MISC + 5088)    // 1024 f = [8][32] float4
#define SMEM_BYTES (MISC + 9184)  // 55,392 B -> 4 CTAs/SM

#define LDSM4(r0, r1, r2, r3, addr) asm volatile( \
    "ldmatrix.sync.aligned.m8n8.x4.shared.b16 {%0,%1,%2,%3}, [%4];" \
    : "=r"(r0), "=r"(r1), "=r"(r2), "=r"(r3) : "r"(addr))

#define LDSM2(r0, r1, addr) asm volatile( \
    "ldmatrix.sync.aligned.m8n8.x2.shared.b16 {%0,%1}, [%2];" \
    : "=r"(r0), "=r"(r1) : "r"(addr))

#define MMA16816(c, a, bfr) asm volatile( \
    "mma.sync.aligned.m16n8k16.row.col.f32.f16.f16.f32 " \
    "{%0,%1,%2,%3}, {%4,%5,%6,%7}, {%8,%9}, {%0,%1,%2,%3};" \
    : "+f"((c)[0]), "+f"((c)[1]), "+f"((c)[2]), "+f"((c)[3]) \
    : "r"((a)[0]), "r"((a)[1]), "r"((a)[2]), "r"((a)[3]), \
      "r"((bfr)[0]), "r"((bfr)[1]))

// pairwise named barrier: the 2 warps sharing m-tile `mwid` (64 threads)
#define BARPAIR(id) asm volatile("bar.sync %0, 64;" :: "r"(id) : "memory")

__device__ __forceinline__ uint32_t smem_u32(const void* p) {
    uint32_t a;
    asm("{ .reg .u64 t; cvta.to.shared.u64 t, %1; cvt.u32.u64 %0, t; }" : "=r"(a) : "l"(p));
    return a;
}

// truncate fp32 pair -> packed fp16x2 word
__device__ __forceinline__ uint32_t pack2h(float a, float b) {
    return (uint32_t)__half_as_ushort(__float2half_rn(a)) |
           ((uint32_t)__half_as_ushort(__float2half_rn(b)) << 16);
}

// stage `nrows` rows of one chunk of hist as fp16 single (rows past L zeroed); STS.64
__device__ __forceinline__ void stage_chunk(char* smc, const float4* hb, int c, int tid, int nrows) {
    for (int idx = tid; idx < nrows * 32; idx += NT) {
        int r = idx >> 5;
        int q = idx & 31;
        int gl = c * ROWS + r;
        float4 v = make_float4(0.f, 0.f, 0.f, 0.f);
        if (gl < LL) v = hb[gl * 32 + q];
        uint32_t wo = (uint32_t)(r * S_HIST + q * 2) * 4u;
        *(uint2*)(smc + HIST_HI + wo) = make_uint2(pack2h(v.x, v.y), pack2h(v.z, v.w));
    }
}

__global__ __launch_bounds__(NT, 4)
void din_kernel(const float* __restrict__ hist,
                const float* __restrict__ tgt,
                const int*   __restrict__ mask,
                const float* __restrict__ W0,
                const float* __restrict__ b0,
                const float* __restrict__ W1,
                const float* __restrict__ b1,
                const float* __restrict__ W2,
                const float* __restrict__ b2,
                float* __restrict__ out)
{
    extern __shared__ char smc[];
    float* tgtS    = (float*)(smc + OFF_TGT);
    float* c0s     = (float*)(smc + OFF_C0);
    float* b1s     = (float*)(smc + OFF_B1);
    float* w2s     = (float*)(smc + OFF_W2);
    float* scoreSA = (float*)(smc + OFF_SC);
    float* scoreSB = (float*)(smc + OFF_SC2);
    float* attnS   = (float*)(smc + OFF_ATTN);
    float* redS    = (float*)(smc + OFF_RED);
    float* cpS     = (float*)(smc + OFF_CP);
    float4* partS4 = (float4*)(smc + OFF_PART);

    const int b    = blockIdx.x;
    const int tid  = threadIdx.x;
    const int wid  = tid >> 5;
    const int lane = tid & 31;
    const int mwid = (wid < 4) ? wid : wid - 4;   // m-tile index 0..3
    const int nh   = (wid < 4) ? 0 : 1;           // n-half
    const uint32_t smem_base = smem_u32(smc);
    const float4* hb = (const float4*)(hist + (size_t)b * LL * DD);

    if (tid < DD) tgtS[tid] = tgt[(size_t)b * DD + tid];
    __syncthreads();

    // ---- prologue: A0t + W1t build (fp16 single, once) + c0 partials + chunk0 ----
    for (int w = tid; w < H0N * 32; w += NT) {
        int n   = w % H0N;
        int kp2 = (w / H0N) * 2;
        int d   = kp2 * 2;
        float v0 = W0[d * H0N + n] + W0[(2 * DD + d) * H0N + n] + tgtS[d] * W0[(3 * DD + d) * H0N + n];
        float v1 = W0[(d + 1) * H0N + n] + W0[(2 * DD + d + 1) * H0N + n] + tgtS[d + 1] * W0[(3 * DD + d + 1) * H0N + n];
        float v2 = W0[(d + 2) * H0N + n] + W0[(2 * DD + d + 2) * H0N + n] + tgtS[d + 2] * W0[(3 * DD + d + 2) * H0N + n];
        float v3 = W0[(d + 3) * H0N + n] + W0[(2 * DD + d + 3) * H0N + n] + tgtS[d + 3] * W0[(3 * DD + d + 3) * H0N + n];
        uint32_t wo = (uint32_t)(n * S_HIST + kp2) * 4u;
        *(uint2*)(smc + A0T_HI + wo) = make_uint2(pack2h(v0, v1), pack2h(v2, v3));
    }
    for (int w = tid; w < H1N * 20; w += NT) {
        int n   = w % H1N;
        int kp2 = (w / H1N) * 2;
        int k   = kp2 * 2;
        uint32_t wo = (uint32_t)(n * S_W1 + kp2) * 4u;
        *(uint2*)(smc + W1T_HI + wo) =
            make_uint2(pack2h(W1[k * H1N + n],       W1[(k + 1) * H1N + n]),
                       pack2h(W1[(k + 2) * H1N + n], W1[(k + 3) * H1N + n]));
    }
    // c0 partials: 240 threads = 80 h x 3 d-slices
    if (tid < 240) {
        const int h  = tid % 80;
        const int sl = tid / 80;
        const int d0 = sl * 43;
        const int d1 = (sl == 2) ? DD : d0 + 43;
        float s = 0.f;
        #pragma unroll 4
        for (int d = d0; d < d1; ++d)
            s = fmaf(tgtS[d], W0[(DD + d) * H0N + h] - W0[(2 * DD + d) * H0N + h], s);
        cpS[tid] = s;
    }
    if (tid < H1N) { b1s[tid] = b1[tid]; w2s[tid] = W2[tid]; }
    stage_chunk(smc, hb, 0, tid, ROWS);
    __syncthreads();
    if (tid < H0N) c0s[tid] = b0[tid] + cpS[tid] + cpS[80 + tid] + cpS[160 + tid];
    __syncthreads();

    // ldmatrix lane geometry
    const int rA = lane & 15;
    const int kA = (lane & 16) ? 4 : 0;
    const int rB = (lane & 7) | ((lane & 16) >> 1);
    const int kB = (lane & 8) ? 4 : 0;
    const int rB2 = lane & 7;                    // x2 geometry
    const int kB2 = (lane & 8) ? 4 : 0;
    const int mb = mwid * 16;
    const int barid = 1 + mwid;

    #pragma unroll 1
    for (int c = 0; c < 4; ++c) {
        const int MT = (c < 3) ? 4 : 1;   // active m-tiles this chunk

        if (mwid < MT) {
            // ===== GEMM0: h0 = relu(hist @ A0t^T + c0); fp16 single =====
            float C0[5][4];
            #pragma unroll
            for (int n = 0; n < 5; ++n)
                #pragma unroll
                for (int j = 0; j < 4; ++j) C0[n][j] = 0.f;

            const uint32_t aAdr = smem_base + HIST_HI + (uint32_t)((mb + rA) * S_HIST + kA) * 4u;
            const int nrow0 = nh * 40;
            const uint32_t bAdr  = smem_base + A0T_HI + (uint32_t)((nrow0 + rB) * S_HIST + kB) * 4u;
            const uint32_t bAdr2 = smem_base + A0T_HI + (uint32_t)((nrow0 + 32 + rB2) * S_HIST + kB2) * 4u;

            #pragma unroll
            for (int ks = 0; ks < 8; ++ks) {
                const uint32_t ko = (uint32_t)(ks * 8) * 4u;
                uint32_t bf[5][2], a[4];
                #pragma unroll
                for (int p = 0; p < 2; ++p) {
                    const uint32_t po = (uint32_t)(p * 16 * S_HIST) * 4u + ko;
                    LDSM4(bf[2*p][0], bf[2*p][1], bf[2*p+1][0], bf[2*p+1][1], bAdr + po);
                }
                LDSM2(bf[4][0], bf[4][1], bAdr2 + ko);
                LDSM4(a[0], a[1], a[2], a[3], aAdr + ko);
                #pragma unroll
                for (int n = 0; n < 5; ++n) MMA16816(C0[n], a, bf[n]);
            }
            BARPAIR(barid);   // pair's hist reads done; pair's rows can be overwritten

            // epilogue: bias+relu+pack(fp16) -> h0 (row-aligned alias of hist rows)
            {
                const int row = mb + (lane >> 2);
                #pragma unroll
                for (int nt = 0; nt < 5; ++nt) {
                    const int g   = nh * 5 + nt;
                    const int col = g * 8 + (lane & 3) * 2;
                    float v0 = fmaxf(C0[nt][0] + c0s[col],     0.f);
                    float v1 = fmaxf(C0[nt][1] + c0s[col + 1], 0.f);
                    uint32_t wo = (uint32_t)(row * S_H0 + g * 4 + (lane & 3)) * 4u;
                    *(uint32_t*)(smc + H0_HI + wo) = pack2h(v0, v1);
                    v0 = fmaxf(C0[nt][2] + c0s[col],     0.f);
                    v1 = fmaxf(C0[nt][3] + c0s[col + 1], 0.f);
                    wo = (uint32_t)((row + 8) * S_H0 + g * 4 + (lane & 3)) * 4u;
                    *(uint32_t*)(smc + H0_HI + wo) = pack2h(v0, v1);
                }
            }
            BARPAIR(barid);   // pair's h0 rows complete

            // ===== GEMM1 + layer2 (n-split: nh0 = tiles 0-2, nh1 = tiles 3-4) =====
            {
                const int NTL = (nh == 0) ? 3 : 2;
                float C1[3][4];
                #pragma unroll
                for (int n = 0; n < 3; ++n)
                    #pragma unroll
                    for (int j = 0; j < 4; ++j) C1[n][j] = 0.f;

                const uint32_t aAdr1 = smem_base + H0_HI + (uint32_t)((mb + rA) * S_H0 + kA) * 4u;
                const int brow = (nh == 0) ? 0 : 24;
                const uint32_t bAdr1  = smem_base + W1T_HI + (uint32_t)((brow + rB) * S_W1 + kB) * 4u;
                const uint32_t bAdr21 = smem_base + W1T_HI + (uint32_t)((16 + rB2) * S_W1 + kB2) * 4u;

                #pragma unroll
                for (int ks = 0; ks < 5; ++ks) {
                    const uint32_t ko = (uint32_t)(ks * 8) * 4u;
                    uint32_t bf[3][2], a[4];
                    LDSM4(bf[0][0], bf[0][1], bf[1][0], bf[1][1], bAdr1 + ko);
                    if (nh == 0) LDSM2(bf[2][0], bf[2][1], bAdr21 + ko);
                    LDSM4(a[0], a[1], a[2], a[3], aAdr1 + ko);
                    #pragma unroll
                    for (int n = 0; n < 3; ++n) if (n < NTL) MMA16816(C1[n], a, bf[n]);
                }

                float p0 = (nh == 0) ? b2[0] : 0.f;
                float p1 = (nh == 0) ? b2[0] : 0.f;
                #pragma unroll
                for (int nt = 0; nt < 3; ++nt) {
                    if (nt < NTL) {
                        const int col = (nh * 3 + nt) * 8 + (lane & 3) * 2;
                        p0 += fmaxf(C1[nt][0] + b1s[col],     0.f) * w2s[col]
                            + fmaxf(C1[nt][1] + b1s[col + 1], 0.f) * w2s[col + 1];
                        p1 += fmaxf(C1[nt][2] + b1s[col],     0.f) * w2s[col]
                            + fmaxf(C1[nt][3] + b1s[col + 1], 0.f) * w2s[col + 1];
                    }
                }
                p0 += __shfl_xor_sync(0xffffffffu, p0, 1);
                p0 += __shfl_xor_sync(0xffffffffu, p0, 2);
                p1 += __shfl_xor_sync(0xffffffffu, p1, 1);
                p1 += __shfl_xor_sync(0xffffffffu, p1, 2);
                if ((lane & 3) == 0) {
                    const int row = mb + (lane >> 2);
                    float* sc = (nh == 0) ? scoreSA : scoreSB;
                    sc[c * ROWS + row]     = p0;
                    sc[c * ROWS + row + 8] = p1;
                }
            }
        }

        if (c < 3) {
            __syncthreads();                  // all reads of X done
            stage_chunk(smc, hb, c + 1, tid, (c == 2) ? 16 : ROWS);
            __syncthreads();
        }
    }
    __syncthreads();

    // ---- masked softmax over L (8 warps) ----
    float logit = -3.402823466e38f;
    if (tid < LL) {
        float m = (float)mask[(size_t)b * LL + tid];
        logit = scoreSA[tid] + scoreSB[tid] + (1.0f - m) * (-1e9f);
    }
    {
        float v = logit;
        #pragma unroll
        for (int o = 16; o; o >>= 1) v = fmaxf(v, __shfl_xor_sync(0xffffffffu, v, o));
        if (lane == 0) redS[wid] = v;
    }
    __syncthreads();
    if (tid < 32) {
        float m = (tid < 8) ? redS[tid] : -3.402823466e38f;
        #pragma unroll
        for (int o = 4; o; o >>= 1) m = fmaxf(m, __shfl_xor_sync(0xffffffffu, m, o));
        if (tid == 0) redS[16] = m;
    }
    __syncthreads();
    const float M = redS[16];
    float e = (tid < LL) ? expf(logit - M) : 0.f;
    {
        float s = e;
        #pragma unroll
        for (int o = 16; o; o >>= 1) s += __shfl_xor_sync(0xffffffffu, s, o);
        if (lane == 0) redS[wid] = s;
    }
    __syncthreads();
    if (tid < 32) {
        float s = (tid < 8) ? redS[tid] : 0.f;
        #pragma unroll
        for (int o = 4; o; o >>= 1) s += __shfl_xor_sync(0xffffffffu, s, o);
        if (tid == 0) redS[17] = s;
    }
    __syncthreads();
    const float S = redS[17];
    if (tid < LL) {
        float a = e / S;
        attnS[tid] = a;
        out[(size_t)BB * DD + (size_t)b * LL + tid] = a;
    }
    __syncthreads();

    // ---- user_interest[b][d] = sum_l attn[l]*hist[l][d]  (float4, 8 l-groups) ----
    {
        const int q = tid & 31;               // float4 column (32 per row)
        const int g = tid >> 5;               // 0..7, 25 l's each
        float4 acc = make_float4(0.f, 0.f, 0.f, 0.f);
        #pragma unroll 5
        for (int l = g * 25; l < g * 25 + 25; ++l) {
            float a = attnS[l];
            float4 v = hb[l * 32 + q];
            acc.x = fmaf(a, v.x, acc.x);
            acc.y = fmaf(a, v.y, acc.y);
            acc.z = fmaf(a, v.z, acc.z);
            acc.w = fmaf(a, v.w, acc.w);
        }
        partS4[g * 32 + q] = acc;
    }
    __syncthreads();
    if (tid < 32) {
        float4 s = partS4[tid];
        #pragma unroll
        for (int g = 1; g < 8; ++g) {
            float4 v = partS4[g * 32 + tid];
            s.x += v.x; s.y += v.y; s.z += v.z; s.w += v.w;
        }
        ((float4*)(out + (size_t)b * DD))[tid] = s;
    }
}

extern "C" void kernel_launch(void* const* d_in, const int* in_sizes, int n_in,
                              void* d_out, int out_size)
{
    const float* hist = (const float*)d_in[0];
    const float* tgt  = (const float*)d_in[1];
    const int*   mask = (const int*)  d_in[2];
    const float* W0   = (const float*)d_in[3];
    const float* b0   = (const float*)d_in[4];
    const float* W1   = (const float*)d_in[5];
    const float* b1   = (const float*)d_in[6];
    const float* W2   = (const float*)d_in[7];
    const float* b2   = (const float*)d_in[8];
    float* out = (float*)d_out;

    static int smem_set = 0;
    if (!smem_set) {
        cudaFuncSetAttribute(din_kernel,
                             cudaFuncAttributeMaxDynamicSharedMemorySize,
                             SMEM_BYTES);
        smem_set = 1;
    }
    din_kernel<<<BB, NT, SMEM_BYTES>>>(hist, tgt, mask, W0, b0, W1, b1, W2, b2, out);
}

// round 16
// speedup vs baseline: 5.3262x; 1.0318x over previous
#include <cuda_runtime.h>
#include <cuda_fp16.h>
#include <cstdint>
#include <math.h>

#define BB 2048
#define LL 200
#define DD 128
#define H0N 80
#define H1N 40
#define NT 256            // 8 warps: (m-tile w%4) x (n-half w/4); 4 CTAs/SM
#define ROWS 64           // L-rows per chunk (4 chunks; last has 8 real rows)

// word strides (conflict-free ldmatrix; stride ≡ 4 mod 8)
#define S_HIST 68
#define S_H0   68         // == S_HIST: h0 row r aliases hist row r's own footprint
#define S_W1   44

// ---- smem byte offsets ----
#define HIST_HI 0                         // [64][68w] fp16-single (17408 B); h0 aliases
#define H0_HI   0
#define A0T_HI  (ROWS*S_HIST*4)           // 17408, 80*68*4=21760 (ends 39168)
#define W1T_HI  39168                     // 40*44*4 = 7040 (ends 46208)
#define MISC    46208
#define OFF_TGT  (MISC + 0)       // 128 f
#define OFF_C0   (MISC + 512)     // 80 f
#define OFF_B1   (MISC + 832)     // 40 f
#define OFF_W2   (MISC + 992)     // 40 f
#define OFF_SC   (MISC + 1152)    // 256 f (nh0 partial)
#define OFF_SC2  (MISC + 2176)    // 256 f (nh1 partial)
#define OFF_ATTN (MISC + 3200)    // 200 f
#define OFF_RED  (MISC + 4000)    // 32 f
#define OFF_CP   (MISC + 4128)    // 640 f (c0 partials [8][80])
#define OFF_PART (MISC + 6688)    // 1024 f = [8][32] float4
#define SMEM_BYTES (MISC + 10784) // 56,992 B -> 4 CTAs/SM

#define LDSM4(r0, r1, r2, r3, addr) asm volatile( \
    "ldmatrix.sync.aligned.m8n8.x4.shared.b16 {%0,%1,%2,%3}, [%4];" \
    : "=r"(r0), "=r"(r1), "=r"(r2), "=r"(r3) : "r"(addr))

#define LDSM2(r0, r1, addr) asm volatile( \
    "ldmatrix.sync.aligned.m8n8.x2.shared.b16 {%0,%1}, [%2];" \
    : "=r"(r0), "=r"(r1) : "r"(addr))

#define MMA16816(c, a, bfr) asm volatile( \
    "mma.sync.aligned.m16n8k16.row.col.f32.f16.f16.f32 " \
    "{%0,%1,%2,%3}, {%4,%5,%6,%7}, {%8,%9}, {%0,%1,%2,%3};" \
    : "+f"((c)[0]), "+f"((c)[1]), "+f"((c)[2]), "+f"((c)[3]) \
    : "r"((a)[0]), "r"((a)[1]), "r"((a)[2]), "r"((a)[3]), \
      "r"((bfr)[0]), "r"((bfr)[1]))

// pairwise named barrier: the 2 warps sharing m-tile `mwid` (64 threads)
#define BARPAIR(id) asm volatile("bar.sync %0, 64;" :: "r"(id) : "memory")

__device__ __forceinline__ uint32_t smem_u32(const void* p) {
    uint32_t a;
    asm("{ .reg .u64 t; cvta.to.shared.u64 t, %1; cvt.u32.u64 %0, t; }" : "=r"(a) : "l"(p));
    return a;
}

// truncate fp32 pair -> packed fp16x2 word
__device__ __forceinline__ uint32_t pack2h(float a, float b) {
    return (uint32_t)__half_as_ushort(__float2half_rn(a)) |
           ((uint32_t)__half_as_ushort(__float2half_rn(b)) << 16);
}

// stage `nrows` rows of one chunk of hist as fp16 single; STS.128 (8 halves)
__device__ __forceinline__ void stage_chunk(char* smc, const float4* hb, int c, int tid, int nrows) {
    for (int idx = tid; idx < nrows * 16; idx += NT) {
        int r  = idx >> 4;
        int q2 = (idx & 15) * 2;              // float4 pair index
        int gl = c * ROWS + r;
        float4 v0 = make_float4(0.f, 0.f, 0.f, 0.f);
        float4 v1 = v0;
        if (gl < LL) { v0 = hb[gl * 32 + q2]; v1 = hb[gl * 32 + q2 + 1]; }
        uint32_t wo = (uint32_t)(r * S_HIST + q2 * 2) * 4u;
        uint4 pk;
        pk.x = pack2h(v0.x, v0.y); pk.y = pack2h(v0.z, v0.w);
        pk.z = pack2h(v1.x, v1.y); pk.w = pack2h(v1.z, v1.w);
        *(uint4*)(smc + HIST_HI + wo) = pk;
    }
}

__global__ __launch_bounds__(NT, 4)
void din_kernel(const float* __restrict__ hist,
                const float* __restrict__ tgt,
                const int*   __restrict__ mask,
                const float* __restrict__ W0,
                const float* __restrict__ b0,
                const float* __restrict__ W1,
                const float* __restrict__ b1,
                const float* __restrict__ W2,
                const float* __restrict__ b2,
                float* __restrict__ out)
{
    extern __shared__ char smc[];
    float* tgtS    = (float*)(smc + OFF_TGT);
    float* c0s     = (float*)(smc + OFF_C0);
    float* b1s     = (float*)(smc + OFF_B1);
    float* w2s     = (float*)(smc + OFF_W2);
    float* scoreSA = (float*)(smc + OFF_SC);
    float* scoreSB = (float*)(smc + OFF_SC2);
    float* attnS   = (float*)(smc + OFF_ATTN);
    float* redS    = (float*)(smc + OFF_RED);
    float* cpS     = (float*)(smc + OFF_CP);
    float4* partS4 = (float4*)(smc + OFF_PART);

    const int b    = blockIdx.x;
    const int tid  = threadIdx.x;
    const int wid  = tid >> 5;
    const int lane = tid & 31;
    const int mwid = (wid < 4) ? wid : wid - 4;   // m-tile index 0..3
    const int nh   = (wid < 4) ? 0 : 1;           // n-half
    const uint32_t smem_base = smem_u32(smc);
    const float4* hb = (const float4*)(hist + (size_t)b * LL * DD);

    if (tid < DD) tgtS[tid] = tgt[(size_t)b * DD + tid];
    __syncthreads();

    // ---- prologue: vectorized A0t / W1t / c0 builds + chunk0 staging ----
    // A0t: 640 units = 20 n-quads x 32 k-word-pairs; 12 LDG.128 + 4 STS.64 each
    for (int u = tid; u < 640; u += NT) {
        const int n4  = (u % 20) * 4;
        const int kp2 = (u / 20) * 2;
        const int d   = kp2 * 2;
        uint32_t w0[4], w1[4];
        {
            float4 h0v = *(const float4*)&W0[d * H0N + n4];
            float4 h1v = *(const float4*)&W0[(d + 1) * H0N + n4];
            float4 f0v = *(const float4*)&W0[(2 * DD + d) * H0N + n4];
            float4 f1v = *(const float4*)&W0[(2 * DD + d + 1) * H0N + n4];
            float4 p0v = *(const float4*)&W0[(3 * DD + d) * H0N + n4];
            float4 p1v = *(const float4*)&W0[(3 * DD + d + 1) * H0N + n4];
            float t0 = tgtS[d], t1 = tgtS[d + 1];
            w0[0] = pack2h(h0v.x + f0v.x + t0 * p0v.x, h1v.x + f1v.x + t1 * p1v.x);
            w0[1] = pack2h(h0v.y + f0v.y + t0 * p0v.y, h1v.y + f1v.y + t1 * p1v.y);
            w0[2] = pack2h(h0v.z + f0v.z + t0 * p0v.z, h1v.z + f1v.z + t1 * p1v.z);
            w0[3] = pack2h(h0v.w + f0v.w + t0 * p0v.w, h1v.w + f1v.w + t1 * p1v.w);
        }
        {
            float4 h0v = *(const float4*)&W0[(d + 2) * H0N + n4];
            float4 h1v = *(const float4*)&W0[(d + 3) * H0N + n4];
            float4 f0v = *(const float4*)&W0[(2 * DD + d + 2) * H0N + n4];
            float4 f1v = *(const float4*)&W0[(2 * DD + d + 3) * H0N + n4];
            float4 p0v = *(const float4*)&W0[(3 * DD + d + 2) * H0N + n4];
            float4 p1v = *(const float4*)&W0[(3 * DD + d + 3) * H0N + n4];
            float t2 = tgtS[d + 2], t3 = tgtS[d + 3];
            w1[0] = pack2h(h0v.x + f0v.x + t2 * p0v.x, h1v.x + f1v.x + t3 * p1v.x);
            w1[1] = pack2h(h0v.y + f0v.y + t2 * p0v.y, h1v.y + f1v.y + t3 * p1v.y);
            w1[2] = pack2h(h0v.z + f0v.z + t2 * p0v.z, h1v.z + f1v.z + t3 * p1v.z);
            w1[3] = pack2h(h0v.w + f0v.w + t2 * p0v.w, h1v.w + f1v.w + t3 * p1v.w);
        }
        #pragma unroll
        for (int j = 0; j < 4; ++j) {
            uint32_t wo = (uint32_t)((n4 + j) * S_HIST + kp2) * 4u;
            *(uint2*)(smc + A0T_HI + wo) = make_uint2(w0[j], w1[j]);
        }
    }
    // W1t: 200 units = 10 n-quads x 20 k-word-pairs; 4 LDG.128 + 4 STS.64 each
    for (int u = tid; u < 200; u += NT) {
        const int n4  = (u % 10) * 4;
        const int kp2 = (u / 10) * 2;
        const int k   = kp2 * 2;
        float4 k0 = *(const float4*)&W1[k * H1N + n4];
        float4 k1 = *(const float4*)&W1[(k + 1) * H1N + n4];
        float4 k2 = *(const float4*)&W1[(k + 2) * H1N + n4];
        float4 k3 = *(const float4*)&W1[(k + 3) * H1N + n4];
        uint2 e0 = make_uint2(pack2h(k0.x, k1.x), pack2h(k2.x, k3.x));
        uint2 e1 = make_uint2(pack2h(k0.y, k1.y), pack2h(k2.y, k3.y));
        uint2 e2 = make_uint2(pack2h(k0.z, k1.z), pack2h(k2.z, k3.z));
        uint2 e3 = make_uint2(pack2h(k0.w, k1.w), pack2h(k2.w, k3.w));
        uint32_t wo = (uint32_t)(n4 * S_W1 + kp2) * 4u;
        *(uint2*)(smc + W1T_HI + wo)                 = e0;
        *(uint2*)(smc + W1T_HI + wo + S_W1 * 4)      = e1;
        *(uint2*)(smc + W1T_HI + wo + 2 * S_W1 * 4)  = e2;
        *(uint2*)(smc + W1T_HI + wo + 3 * S_W1 * 4)  = e3;
    }
    // c0 partials: 160 threads = 20 h-quads x 8 d-slices of 16; float4 math
    if (tid < 160) {
        const int h4 = (tid % 20) * 4;
        const int sl = tid / 20;
        const int d0 = sl * 16;
        float4 acc = make_float4(0.f, 0.f, 0.f, 0.f);
        #pragma unroll 4
        for (int d = d0; d < d0 + 16; ++d) {
            float t = tgtS[d];
            float4 tv = *(const float4*)&W0[(DD + d) * H0N + h4];
            float4 dv = *(const float4*)&W0[(2 * DD + d) * H0N + h4];
            acc.x = fmaf(t, tv.x - dv.x, acc.x);
            acc.y = fmaf(t, tv.y - dv.y, acc.y);
            acc.z = fmaf(t, tv.z - dv.z, acc.z);
            acc.w = fmaf(t, tv.w - dv.w, acc.w);
        }
        *(float4*)&cpS[sl * 80 + h4] = acc;
    }
    if (tid < H1N) { b1s[tid] = b1[tid]; w2s[tid] = W2[tid]; }
    stage_chunk(smc, hb, 0, tid, ROWS);
    __syncthreads();
    if (tid < H0N) {
        float s = b0[tid];
        #pragma unroll
        for (int sl = 0; sl < 8; ++sl) s += cpS[sl * 80 + tid];
        c0s[tid] = s;
    }
    __syncthreads();

    // ldmatrix lane geometry
    const int rA = lane & 15;
    const int kA = (lane & 16) ? 4 : 0;
    const int rB = (lane & 7) | ((lane & 16) >> 1);
    const int kB = (lane & 8) ? 4 : 0;
    const int rB2 = lane & 7;                    // x2 geometry
    const int kB2 = (lane & 8) ? 4 : 0;
    const int mb = mwid * 16;
    const int barid = 1 + mwid;

    #pragma unroll 1
    for (int c = 0; c < 4; ++c) {
        const int MT = (c < 3) ? 4 : 1;   // active m-tiles this chunk

        if (mwid < MT) {
            // ===== GEMM0: h0 = relu(hist @ A0t^T + c0); fp16 single =====
            float C0[5][4];
            #pragma unroll
            for (int n = 0; n < 5; ++n)
                #pragma unroll
                for (int j = 0; j < 4; ++j) C0[n][j] = 0.f;

            const uint32_t aAdr = smem_base + HIST_HI + (uint32_t)((mb + rA) * S_HIST + kA) * 4u;
            const int nrow0 = nh * 40;
            const uint32_t bAdr  = smem_base + A0T_HI + (uint32_t)((nrow0 + rB) * S_HIST + kB) * 4u;
            const uint32_t bAdr2 = smem_base + A0T_HI + (uint32_t)((nrow0 + 32 + rB2) * S_HIST + kB2) * 4u;

            #pragma unroll
            for (int ks = 0; ks < 8; ++ks) {
                const uint32_t ko = (uint32_t)(ks * 8) * 4u;
                uint32_t bf[5][2], a[4];
                #pragma unroll
                for (int p = 0; p < 2; ++p) {
                    const uint32_t po = (uint32_t)(p * 16 * S_HIST) * 4u + ko;
                    LDSM4(bf[2*p][0], bf[2*p][1], bf[2*p+1][0], bf[2*p+1][1], bAdr + po);
                }
                LDSM2(bf[4][0], bf[4][1], bAdr2 + ko);
                LDSM4(a[0], a[1], a[2], a[3], aAdr + ko);
                #pragma unroll
                for (int n = 0; n < 5; ++n) MMA16816(C0[n], a, bf[n]);
            }
            BARPAIR(barid);   // pair's hist reads done; pair's rows can be overwritten

            // epilogue: bias+relu+pack(fp16) -> h0 (row-aligned alias of hist rows)
            {
                const int row = mb + (lane >> 2);
                #pragma unroll
                for (int nt = 0; nt < 5; ++nt) {
                    const int g   = nh * 5 + nt;
                    const int col = g * 8 + (lane & 3) * 2;
                    float v0 = fmaxf(C0[nt][0] + c0s[col],     0.f);
                    float v1 = fmaxf(C0[nt][1] + c0s[col + 1], 0.f);
                    uint32_t wo = (uint32_t)(row * S_H0 + g * 4 + (lane & 3)) * 4u;
                    *(uint32_t*)(smc + H0_HI + wo) = pack2h(v0, v1);
                    v0 = fmaxf(C0[nt][2] + c0s[col],     0.f);
                    v1 = fmaxf(C0[nt][3] + c0s[col + 1], 0.f);
                    wo = (uint32_t)((row + 8) * S_H0 + g * 4 + (lane & 3)) * 4u;
                    *(uint32_t*)(smc + H0_HI + wo) = pack2h(v0, v1);
                }
            }
            BARPAIR(barid);   // pair's h0 rows complete

            // ===== GEMM1 + layer2 (n-split: nh0 = tiles 0-2, nh1 = tiles 3-4) =====
            {
                const int NTL = (nh == 0) ? 3 : 2;
                float C1[3][4];
                #pragma unroll
                for (int n = 0; n < 3; ++n)
                    #pragma unroll
                    for (int j = 0; j < 4; ++j) C1[n][j] = 0.f;

                const uint32_t aAdr1 = smem_base + H0_HI + (uint32_t)((mb + rA) * S_H0 + kA) * 4u;
                const int brow = (nh == 0) ? 0 : 24;
                const uint32_t bAdr1  = smem_base + W1T_HI + (uint32_t)((brow + rB) * S_W1 + kB) * 4u;
                const uint32_t bAdr21 = smem_base + W1T_HI + (uint32_t)((16 + rB2) * S_W1 + kB2) * 4u;

                #pragma unroll
                for (int ks = 0; ks < 5; ++ks) {
                    const uint32_t ko = (uint32_t)(ks * 8) * 4u;
                    uint32_t bf[3][2], a[4];
                    LDSM4(bf[0][0], bf[0][1], bf[1][0], bf[1][1], bAdr1 + ko);
                    if (nh == 0) LDSM2(bf[2][0], bf[2][1], bAdr21 + ko);
                    LDSM4(a[0], a[1], a[2], a[3], aAdr1 + ko);
                    #pragma unroll
                    for (int n = 0; n < 3; ++n) if (n < NTL) MMA16816(C1[n], a, bf[n]);
                }

                float p0 = (nh == 0) ? b2[0] : 0.f;
                float p1 = (nh == 0) ? b2[0] : 0.f;
                #pragma unroll
                for (int nt = 0; nt < 3; ++nt) {
                    if (nt < NTL) {
                        const int col = (nh * 3 + nt) * 8 + (lane & 3) * 2;
                        p0 += fmaxf(C1[nt][0] + b1s[col],     0.f) * w2s[col]
                            + fmaxf(C1[nt][1] + b1s[col + 1], 0.f) * w2s[col + 1];
                        p1 += fmaxf(C1[nt][2] + b1s[col],     0.f) * w2s[col]
                            + fmaxf(C1[nt][3] + b1s[col + 1], 0.f) * w2s[col + 1];
                    }
                }
                p0 += __shfl_xor_sync(0xffffffffu, p0, 1);
                p0 += __shfl_xor_sync(0xffffffffu, p0, 2);
                p1 += __shfl_xor_sync(0xffffffffu, p1, 1);
                p1 += __shfl_xor_sync(0xffffffffu, p1, 2);
                if ((lane & 3) == 0) {
                    const int row = mb + (lane >> 2);
                    float* sc = (nh == 0) ? scoreSA : scoreSB;
                    sc[c * ROWS + row]     = p0;
                    sc[c * ROWS + row + 8] = p1;
                }
            }
        }

        if (c < 3) {
            __syncthreads();                  // all reads of X done
            stage_chunk(smc, hb, c + 1, tid, (c == 2) ? 16 : ROWS);
            __syncthreads();
        }
    }
    __syncthreads();

    // ---- masked softmax over L (8 warps) ----
    float logit = -3.402823466e38f;
    if (tid < LL) {
        float m = (float)mask[(size_t)b * LL + tid];
        logit = scoreSA[tid] + scoreSB[tid] + (1.0f - m) * (-1e9f);
    }
    {
        float v = logit;
        #pragma unroll
        for (int o = 16; o; o >>= 1) v = fmaxf(v, __shfl_xor_sync(0xffffffffu, v, o));
        if (lane == 0) redS[wid] = v;
    }
    __syncthreads();
    if (tid < 32) {
        float m = (tid < 8) ? redS[tid] : -3.402823466e38f;
        #pragma unroll
        for (int o = 4; o; o >>= 1) m = fmaxf(m, __shfl_xor_sync(0xffffffffu, m, o));
        if (tid == 0) redS[16] = m;
    }
    __syncthreads();
    const float M = redS[16];
    float e = (tid < LL) ? expf(logit - M) : 0.f;
    {
        float s = e;
        #pragma unroll
        for (int o = 16; o; o >>= 1) s += __shfl_xor_sync(0xffffffffu, s, o);
        if (lane == 0) redS[wid] = s;
    }
    __syncthreads();
    if (tid < 32) {
        float s = (tid < 8) ? redS[tid] : 0.f;
        #pragma unroll
        for (int o = 4; o; o >>= 1) s += __shfl_xor_sync(0xffffffffu, s, o);
        if (tid == 0) redS[17] = s;
    }
    __syncthreads();
    const float S = redS[17];
    if (tid < LL) {
        float a = e / S;
        attnS[tid] = a;
        out[(size_t)BB * DD + (size_t)b * LL + tid] = a;
    }
    __syncthreads();

    // ---- user_interest[b][d] = sum_l attn[l]*hist[l][d]  (float4, 8 l-groups) ----
    {
        const int q = tid & 31;               // float4 column (32 per row)
        const int g = tid >> 5;               // 0..7, 25 l's each
        float4 acc = make_float4(0.f, 0.f, 0.f, 0.f);
        #pragma unroll 5
        for (int l = g * 25; l < g * 25 + 25; ++l) {
            float a = attnS[l];
            float4 v = hb[l * 32 + q];
            acc.x = fmaf(a, v.x, acc.x);
            acc.y = fmaf(a, v.y, acc.y);
            acc.z = fmaf(a, v.z, acc.z);
            acc.w = fmaf(a, v.w, acc.w);
        }
        partS4[g * 32 + q] = acc;
    }
    __syncthreads();
    if (tid < 32) {
        float4 s = partS4[tid];
        #pragma unroll
        for (int g = 1; g < 8; ++g) {
            float4 v = partS4[g * 32 + tid];
            s.x += v.x; s.y += v.y; s.z += v.z; s.w += v.w;
        }
        ((float4*)(out + (size_t)b * DD))[tid] = s;
    }
}

extern "C" void kernel_launch(void* const* d_in, const int* in_sizes, int n_in,
                              void* d_out, int out_size)
{
    const float* hist = (const float*)d_in[0];
    const float* tgt  = (const float*)d_in[1];
    const int*   mask = (const int*)  d_in[2];
    const float* W0   = (const float*)d_in[3];
    const float* b0   = (const float*)d_in[4];
    const float* W1   = (const float*)d_in[5];
    const float* b1   = (const float*)d_in[6];
    const float* W2   = (const float*)d_in[7];
    const float* b2   = (const float*)d_in[8];
    float* out = (float*)d_out;

    static int smem_set = 0;
    if (!smem_set) {
        cudaFuncSetAttribute(din_kernel,
                             cudaFuncAttributeMaxDynamicSharedMemorySize,
                             SMEM_BYTES);
        smem_set = 1;
    }
    din_kernel<<<BB, NT, SMEM_BYTES>>>(hist, tgt, mask, W0, b0, W1, b1, W2, b2, out);
}

// round 17
// speedup vs baseline: 5.4936x; 1.0314x over previous
#include <cuda_runtime.h>
#include <cuda_fp16.h>
#include <cstdint>
#include <math.h>

#define BB 2048
#define LL 200
#define DD 128
#define H0N 80
#define H1N 40
#define NT 256            // 8 warps: (m-tile w%4) x (n-half w/4); 4 CTAs/SM
#define ROWS 64           // L-rows per chunk (4 chunks; last: only pair 0 active)

// word strides (conflict-free ldmatrix; stride ≡ 4 mod 8)
#define S_HIST 68
#define S_H0   68         // == S_HIST: h0 row r aliases hist row r's own footprint
#define S_W1   44

// ---- smem byte offsets ----
#define HIST_HI 0                         // [64][68w] fp16-single (17408 B); h0 aliases
#define H0_HI   0
#define A0T_HI  (ROWS*S_HIST*4)           // 17408, 80*68*4=21760 (ends 39168)
#define W1T_HI  39168                     // 40*44*4 = 7040 (ends 46208)
#define MISC    46208
#define OFF_TGT  (MISC + 0)       // 128 f
#define OFF_C0   (MISC + 512)     // 80 f
#define OFF_B1   (MISC + 832)     // 40 f
#define OFF_W2   (MISC + 992)     // 40 f
#define OFF_SC   (MISC + 1152)    // 256 f (nh0 partial)
#define OFF_SC2  (MISC + 2176)    // 256 f (nh1 partial)
#define OFF_ATTN (MISC + 3200)    // 200 f
#define OFF_RED  (MISC + 4000)    // 32 f
#define OFF_CP   (MISC + 4128)    // 640 f (c0 partials [8][80])
#define OFF_PART (MISC + 6688)    // 1024 f = [8][32] float4
#define SMEM_BYTES (MISC + 10784) // 56,992 B -> 4 CTAs/SM

#define LDSM4(r0, r1, r2, r3, addr) asm volatile( \
    "ldmatrix.sync.aligned.m8n8.x4.shared.b16 {%0,%1,%2,%3}, [%4];" \
    : "=r"(r0), "=r"(r1), "=r"(r2), "=r"(r3) : "r"(addr))

#define LDSM2(r0, r1, addr) asm volatile( \
    "ldmatrix.sync.aligned.m8n8.x2.shared.b16 {%0,%1}, [%2];" \
    : "=r"(r0), "=r"(r1) : "r"(addr))

#define MMA16816(c, a, bfr) asm volatile( \
    "mma.sync.aligned.m16n8k16.row.col.f32.f16.f16.f32 " \
    "{%0,%1,%2,%3}, {%4,%5,%6,%7}, {%8,%9}, {%0,%1,%2,%3};" \
    : "+f"((c)[0]), "+f"((c)[1]), "+f"((c)[2]), "+f"((c)[3]) \
    : "r"((a)[0]), "r"((a)[1]), "r"((a)[2]), "r"((a)[3]), \
      "r"((bfr)[0]), "r"((bfr)[1]))

// pairwise named barrier: the 2 warps sharing m-tile `mwid` (64 threads)
#define BARPAIR(id) asm volatile("bar.sync %0, 64;" :: "r"(id) : "memory")

__device__ __forceinline__ uint32_t smem_u32(const void* p) {
    uint32_t a;
    asm("{ .reg .u64 t; cvta.to.shared.u64 t, %1; cvt.u32.u64 %0, t; }" : "=r"(a) : "l"(p));
    return a;
}

// truncate fp32 pair -> packed fp16x2 word
__device__ __forceinline__ uint32_t pack2h(float a, float b) {
    return (uint32_t)__half_as_ushort(__float2half_rn(a)) |
           ((uint32_t)__half_as_ushort(__float2half_rn(b)) << 16);
}

// pair-local staging: 64 threads stage the pair's 16 rows of chunk c; STS.128
__device__ __forceinline__ void stage_tile(char* smc, const float4* hb, int c,
                                           int mb, int pt) {
    #pragma unroll
    for (int u = pt; u < 256; u += 64) {        // 16 rows x 16 uint4-units
        int r  = u >> 4;
        int q2 = (u & 15) * 2;
        int lr = mb + r;                        // row within chunk buffer
        int gl = c * ROWS + lr;                 // global L row
        float4 v0 = make_float4(0.f, 0.f, 0.f, 0.f);
        float4 v1 = v0;
        if (gl < LL) { v0 = hb[gl * 32 + q2]; v1 = hb[gl * 32 + q2 + 1]; }
        uint32_t wo = (uint32_t)(lr * S_HIST + q2 * 2) * 4u;
        uint4 pk;
        pk.x = pack2h(v0.x, v0.y); pk.y = pack2h(v0.z, v0.w);
        pk.z = pack2h(v1.x, v1.y); pk.w = pack2h(v1.z, v1.w);
        *(uint4*)(smc + HIST_HI + wo) = pk;
    }
}

__global__ __launch_bounds__(NT, 4)
void din_kernel(const float* __restrict__ hist,
                const float* __restrict__ tgt,
                const int*   __restrict__ mask,
                const float* __restrict__ W0,
                const float* __restrict__ b0,
                const float* __restrict__ W1,
                const float* __restrict__ b1,
                const float* __restrict__ W2,
                const float* __restrict__ b2,
                float* __restrict__ out)
{
    extern __shared__ char smc[];
    float* tgtS    = (float*)(smc + OFF_TGT);
    float* c0s     = (float*)(smc + OFF_C0);
    float* b1s     = (float*)(smc + OFF_B1);
    float* w2s     = (float*)(smc + OFF_W2);
    float* scoreSA = (float*)(smc + OFF_SC);
    float* scoreSB = (float*)(smc + OFF_SC2);
    float* attnS   = (float*)(smc + OFF_ATTN);
    float* redS    = (float*)(smc + OFF_RED);
    float* cpS     = (float*)(smc + OFF_CP);
    float4* partS4 = (float4*)(smc + OFF_PART);

    const int b    = blockIdx.x;
    const int tid  = threadIdx.x;
    const int wid  = tid >> 5;
    const int lane = tid & 31;
    const int mwid = (wid < 4) ? wid : wid - 4;   // m-tile index 0..3
    const int nh   = (wid < 4) ? 0 : 1;           // n-half
    const int pt   = nh * 32 + lane;              // thread id within pair 0..63
    const uint32_t smem_base = smem_u32(smc);
    const float4* hb = (const float4*)(hist + (size_t)b * LL * DD);

    if (tid < DD) tgtS[tid] = tgt[(size_t)b * DD + tid];
    __syncthreads();

    // ---- prologue: vectorized A0t / W1t / c0 builds + chunk0 staging (CTA-wide) ----
    for (int u = tid; u < 640; u += NT) {
        const int n4  = (u % 20) * 4;
        const int kp2 = (u / 20) * 2;
        const int d   = kp2 * 2;
        uint32_t w0[4], w1[4];
        {
            float4 h0v = *(const float4*)&W0[d * H0N + n4];
            float4 h1v = *(const float4*)&W0[(d + 1) * H0N + n4];
            float4 f0v = *(const float4*)&W0[(2 * DD + d) * H0N + n4];
            float4 f1v = *(const float4*)&W0[(2 * DD + d + 1) * H0N + n4];
            float4 p0v = *(const float4*)&W0[(3 * DD + d) * H0N + n4];
            float4 p1v = *(const float4*)&W0[(3 * DD + d + 1) * H0N + n4];
            float t0 = tgtS[d], t1 = tgtS[d + 1];
            w0[0] = pack2h(h0v.x + f0v.x + t0 * p0v.x, h1v.x + f1v.x + t1 * p1v.x);
            w0[1] = pack2h(h0v.y + f0v.y + t0 * p0v.y, h1v.y + f1v.y + t1 * p1v.y);
            w0[2] = pack2h(h0v.z + f0v.z + t0 * p0v.z, h1v.z + f1v.z + t1 * p1v.z);
            w0[3] = pack2h(h0v.w + f0v.w + t0 * p0v.w, h1v.w + f1v.w + t1 * p1v.w);
        }
        {
            float4 h0v = *(const float4*)&W0[(d + 2) * H0N + n4];
            float4 h1v = *(const float4*)&W0[(d + 3) * H0N + n4];
            float4 f0v = *(const float4*)&W0[(2 * DD + d + 2) * H0N + n4];
            float4 f1v = *(const float4*)&W0[(2 * DD + d + 3) * H0N + n4];
            float4 p0v = *(const float4*)&W0[(3 * DD + d + 2) * H0N + n4];
            float4 p1v = *(const float4*)&W0[(3 * DD + d + 3) * H0N + n4];
            float t2 = tgtS[d + 2], t3 = tgtS[d + 3];
            w1[0] = pack2h(h0v.x + f0v.x + t2 * p0v.x, h1v.x + f1v.x + t3 * p1v.x);
            w1[1] = pack2h(h0v.y + f0v.y + t2 * p0v.y, h1v.y + f1v.y + t3 * p1v.y);
            w1[2] = pack2h(h0v.z + f0v.z + t2 * p0v.z, h1v.z + f1v.z + t3 * p1v.z);
            w1[3] = pack2h(h0v.w + f0v.w + t2 * p0v.w, h1v.w + f1v.w + t3 * p1v.w);
        }
        #pragma unroll
        for (int j = 0; j < 4; ++j) {
            uint32_t wo = (uint32_t)((n4 + j) * S_HIST + kp2) * 4u;
            *(uint2*)(smc + A0T_HI + wo) = make_uint2(w0[j], w1[j]);
        }
    }
    for (int u = tid; u < 200; u += NT) {
        const int n4  = (u % 10) * 4;
        const int kp2 = (u / 10) * 2;
        const int k   = kp2 * 2;
        float4 k0 = *(const float4*)&W1[k * H1N + n4];
        float4 k1 = *(const float4*)&W1[(k + 1) * H1N + n4];
        float4 k2 = *(const float4*)&W1[(k + 2) * H1N + n4];
        float4 k3 = *(const float4*)&W1[(k + 3) * H1N + n4];
        uint2 e0 = make_uint2(pack2h(k0.x, k1.x), pack2h(k2.x, k3.x));
        uint2 e1 = make_uint2(pack2h(k0.y, k1.y), pack2h(k2.y, k3.y));
        uint2 e2 = make_uint2(pack2h(k0.z, k1.z), pack2h(k2.z, k3.z));
        uint2 e3 = make_uint2(pack2h(k0.w, k1.w), pack2h(k2.w, k3.w));
        uint32_t wo = (uint32_t)(n4 * S_W1 + kp2) * 4u;
        *(uint2*)(smc + W1T_HI + wo)                 = e0;
        *(uint2*)(smc + W1T_HI + wo + S_W1 * 4)      = e1;
        *(uint2*)(smc + W1T_HI + wo + 2 * S_W1 * 4)  = e2;
        *(uint2*)(smc + W1T_HI + wo + 3 * S_W1 * 4)  = e3;
    }
    if (tid < 160) {
        const int h4 = (tid % 20) * 4;
        const int sl = tid / 20;
        const int d0 = sl * 16;
        float4 acc = make_float4(0.f, 0.f, 0.f, 0.f);
        #pragma unroll 4
        for (int d = d0; d < d0 + 16; ++d) {
            float t = tgtS[d];
            float4 tv = *(const float4*)&W0[(DD + d) * H0N + h4];
            float4 dv = *(const float4*)&W0[(2 * DD + d) * H0N + h4];
            acc.x = fmaf(t, tv.x - dv.x, acc.x);
            acc.y = fmaf(t, tv.y - dv.y, acc.y);
            acc.z = fmaf(t, tv.z - dv.z, acc.z);
            acc.w = fmaf(t, tv.w - dv.w, acc.w);
        }
        *(float4*)&cpS[sl * 80 + h4] = acc;
    }
    if (tid < H1N) { b1s[tid] = b1[tid]; w2s[tid] = W2[tid]; }
    // chunk-0 staging (CTA-wide, all 64 rows)
    for (int u = tid; u < ROWS * 16; u += NT) {
        int r  = u >> 4;
        int q2 = (u & 15) * 2;
        float4 v0 = hb[r * 32 + q2];
        float4 v1 = hb[r * 32 + q2 + 1];
        uint32_t wo = (uint32_t)(r * S_HIST + q2 * 2) * 4u;
        uint4 pk;
        pk.x = pack2h(v0.x, v0.y); pk.y = pack2h(v0.z, v0.w);
        pk.z = pack2h(v1.x, v1.y); pk.w = pack2h(v1.z, v1.w);
        *(uint4*)(smc + HIST_HI + wo) = pk;
    }
    __syncthreads();
    if (tid < H0N) {
        float s = b0[tid];
        #pragma unroll
        for (int sl = 0; sl < 8; ++sl) s += cpS[sl * 80 + tid];
        c0s[tid] = s;
    }
    __syncthreads();

    // ldmatrix lane geometry
    const int rA = lane & 15;
    const int kA = (lane & 16) ? 4 : 0;
    const int rB = (lane & 7) | ((lane & 16) >> 1);
    const int kB = (lane & 8) ? 4 : 0;
    const int rB2 = lane & 7;                    // x2 geometry
    const int kB2 = (lane & 8) ? 4 : 0;
    const int mb = mwid * 16;
    const int barid = 1 + mwid;

    // ===== chunk loop: fully pair-asynchronous (no CTA-wide barriers) =====
    #pragma unroll 1
    for (int c = 0; c < 4; ++c) {
        const bool active = (c < 3) || (mwid == 0);   // chunk 3: only pair 0
        if (active) {
            // --- GEMM0: h0 = relu(hist @ A0t^T + c0); fp16 single ---
            float C0[5][4];
            #pragma unroll
            for (int n = 0; n < 5; ++n)
                #pragma unroll
                for (int j = 0; j < 4; ++j) C0[n][j] = 0.f;

            const uint32_t aAdr = smem_base + HIST_HI + (uint32_t)((mb + rA) * S_HIST + kA) * 4u;
            const int nrow0 = nh * 40;
            const uint32_t bAdr  = smem_base + A0T_HI + (uint32_t)((nrow0 + rB) * S_HIST + kB) * 4u;
            const uint32_t bAdr2 = smem_base + A0T_HI + (uint32_t)((nrow0 + 32 + rB2) * S_HIST + kB2) * 4u;

            #pragma unroll
            for (int ks = 0; ks < 8; ++ks) {
                const uint32_t ko = (uint32_t)(ks * 8) * 4u;
                uint32_t bf[5][2], a[4];
                #pragma unroll
                for (int p = 0; p < 2; ++p) {
                    const uint32_t po = (uint32_t)(p * 16 * S_HIST) * 4u + ko;
                    LDSM4(bf[2*p][0], bf[2*p][1], bf[2*p+1][0], bf[2*p+1][1], bAdr + po);
                }
                LDSM2(bf[4][0], bf[4][1], bAdr2 + ko);
                LDSM4(a[0], a[1], a[2], a[3], aAdr + ko);
                #pragma unroll
                for (int n = 0; n < 5; ++n) MMA16816(C0[n], a, bf[n]);
            }
            BARPAIR(barid);   // pair's hist reads done

            // --- epilogue: bias+relu+pack -> h0 (row-aligned alias) ---
            {
                const int row = mb + (lane >> 2);
                #pragma unroll
                for (int nt = 0; nt < 5; ++nt) {
                    const int g   = nh * 5 + nt;
                    const int col = g * 8 + (lane & 3) * 2;
                    float v0 = fmaxf(C0[nt][0] + c0s[col],     0.f);
                    float v1 = fmaxf(C0[nt][1] + c0s[col + 1], 0.f);
                    uint32_t wo = (uint32_t)(row * S_H0 + g * 4 + (lane & 3)) * 4u;
                    *(uint32_t*)(smc + H0_HI + wo) = pack2h(v0, v1);
                    v0 = fmaxf(C0[nt][2] + c0s[col],     0.f);
                    v1 = fmaxf(C0[nt][3] + c0s[col + 1], 0.f);
                    wo = (uint32_t)((row + 8) * S_H0 + g * 4 + (lane & 3)) * 4u;
                    *(uint32_t*)(smc + H0_HI + wo) = pack2h(v0, v1);
                }
            }
            BARPAIR(barid);   // pair's h0 rows complete

            // --- GEMM1 + layer2 (n-split: nh0 = tiles 0-2, nh1 = tiles 3-4) ---
            {
                const int NTL = (nh == 0) ? 3 : 2;
                float C1[3][4];
                #pragma unroll
                for (int n = 0; n < 3; ++n)
                    #pragma unroll
                    for (int j = 0; j < 4; ++j) C1[n][j] = 0.f;

                const uint32_t aAdr1 = smem_base + H0_HI + (uint32_t)((mb + rA) * S_H0 + kA) * 4u;
                const int brow = (nh == 0) ? 0 : 24;
                const uint32_t bAdr1  = smem_base + W1T_HI + (uint32_t)((brow + rB) * S_W1 + kB) * 4u;
                const uint32_t bAdr21 = smem_base + W1T_HI + (uint32_t)((16 + rB2) * S_W1 + kB2) * 4u;

                #pragma unroll
                for (int ks = 0; ks < 5; ++ks) {
                    const uint32_t ko = (uint32_t)(ks * 8) * 4u;
                    uint32_t bf[3][2], a[4];
                    LDSM4(bf[0][0], bf[0][1], bf[1][0], bf[1][1], bAdr1 + ko);
                    if (nh == 0) LDSM2(bf[2][0], bf[2][1], bAdr21 + ko);
                    LDSM4(a[0], a[1], a[2], a[3], aAdr1 + ko);
                    #pragma unroll
                    for (int n = 0; n < 3; ++n) if (n < NTL) MMA16816(C1[n], a, bf[n]);
                }

                float p0 = (nh == 0) ? b2[0] : 0.f;
                float p1 = (nh == 0) ? b2[0] : 0.f;
                #pragma unroll
                for (int nt = 0; nt < 3; ++nt) {
                    if (nt < NTL) {
                        const int col = (nh * 3 + nt) * 8 + (lane & 3) * 2;
                        p0 += fmaxf(C1[nt][0] + b1s[col],     0.f) * w2s[col]
                            + fmaxf(C1[nt][1] + b1s[col + 1], 0.f) * w2s[col + 1];
                        p1 += fmaxf(C1[nt][2] + b1s[col],     0.f) * w2s[col]
                            + fmaxf(C1[nt][3] + b1s[col + 1], 0.f) * w2s[col + 1];
                    }
                }
                p0 += __shfl_xor_sync(0xffffffffu, p0, 1);
                p0 += __shfl_xor_sync(0xffffffffu, p0, 2);
                p1 += __shfl_xor_sync(0xffffffffu, p1, 1);
                p1 += __shfl_xor_sync(0xffffffffu, p1, 2);
                if ((lane & 3) == 0) {
                    const int row = mb + (lane >> 2);
                    float* sc = (nh == 0) ? scoreSA : scoreSB;
                    sc[c * ROWS + row]     = p0;
                    sc[c * ROWS + row + 8] = p1;
                }
            }
        }

        // --- pair-local staging of next chunk's 16 rows ---
        if (c < 3 && (c < 2 || mwid == 0)) {
            BARPAIR(barid);               // pair's h0 reads (GEMM1) done
            stage_tile(smc, hb, c + 1, mb, pt);
            BARPAIR(barid);               // pair's new hist rows visible
        }
    }
    __syncthreads();   // all pairs' scores visible

    // ---- masked softmax over L (8 warps) ----
    float logit = -3.402823466e38f;
    if (tid < LL) {
        float m = (float)mask[(size_t)b * LL + tid];
        logit = scoreSA[tid] + scoreSB[tid] + (1.0f - m) * (-1e9f);
    }
    {
        float v = logit;
        #pragma unroll
        for (int o = 16; o; o >>= 1) v = fmaxf(v, __shfl_xor_sync(0xffffffffu, v, o));
        if (lane == 0) redS[wid] = v;
    }
    __syncthreads();
    if (tid < 32) {
        float m = (tid < 8) ? redS[tid] : -3.402823466e38f;
        #pragma unroll
        for (int o = 4; o; o >>= 1) m = fmaxf(m, __shfl_xor_sync(0xffffffffu, m, o));
        if (tid == 0) redS[16] = m;
    }
    __syncthreads();
    const float M = redS[16];
    float e = (tid < LL) ? expf(logit - M) : 0.f;
    {
        float s = e;
        #pragma unroll
        for (int o = 16; o; o >>= 1) s += __shfl_xor_sync(0xffffffffu, s, o);
        if (lane == 0) redS[wid] = s;
    }
    __syncthreads();
    if (tid < 32) {
        float s = (tid < 8) ? redS[tid] : 0.f;
        #pragma unroll
        for (int o = 4; o; o >>= 1) s += __shfl_xor_sync(0xffffffffu, s, o);
        if (tid == 0) redS[17] = s;
    }
    __syncthreads();
    const float S = redS[17];
    if (tid < LL) {
        float a = e / S;
        attnS[tid] = a;
        out[(size_t)BB * DD + (size_t)b * LL + tid] = a;
    }
    __syncthreads();

    // ---- user_interest[b][d] = sum_l attn[l]*hist[l][d]  (float4, 8 l-groups) ----
    {
        const int q = tid & 31;
        const int g = tid >> 5;               // 0..7, 25 l's each
        float4 acc = make_float4(0.f, 0.f, 0.f, 0.f);
        #pragma unroll 5
        for (int l = g * 25; l < g * 25 + 25; ++l) {
            float a = attnS[l];
            float4 v = hb[l * 32 + q];
            acc.x = fmaf(a, v.x, acc.x);
            acc.y = fmaf(a, v.y, acc.y);
            acc.z = fmaf(a, v.z, acc.z);
            acc.w = fmaf(a, v.w, acc.w);
        }
        partS4[g * 32 + q] = acc;
    }
    __syncthreads();
    if (tid < 32) {
        float4 s = partS4[tid];
        #pragma unroll
        for (int g = 1; g < 8; ++g) {
            float4 v = partS4[g * 32 + tid];
            s.x += v.x; s.y += v.y; s.z += v.z; s.w += v.w;
        }
        ((float4*)(out + (size_t)b * DD))[tid] = s;
    }
}

extern "C" void kernel_launch(void* const* d_in, const int* in_sizes, int n_in,
                              void* d_out, int out_size)
{
    const float* hist = (const float*)d_in[0];
    const float* tgt  = (const float*)d_in[1];
    const int*   mask = (const int*)  d_in[2];
    const float* W0   = (const float*)d_in[3];
    const float* b0   = (const float*)d_in[4];
    const float* W1   = (const float*)d_in[5];
    const float* b1   = (const float*)d_in[6];
    const float* W2   = (const float*)d_in[7];
    const float* b2   = (const float*)d_in[8];
    float* out = (float*)d_out;

    static int smem_set = 0;
    if (!smem_set) {
        cudaFuncSetAttribute(din_kernel,
                             cudaFuncAttributeMaxDynamicSharedMemorySize,
                             SMEM_BYTES);
        smem_set = 1;
    }
    din_kernel<<<BB, NT, SMEM_BYTES>>>(hist, tgt, mask, W0, b0, W1, b1, W2, b2, out);
}